// round 1
// baseline (speedup 1.0000x reference)
#include <cuda_runtime.h>
#include <math.h>

// ---------------- problem constants ----------------
static const int B_  = 8;
static const int S_  = 256;
static const int G_  = 2048;      // B*S graphs / tokens
static const int L_  = 68;        // landmarks
static const int DM  = 512;       // d_model
static const int NH  = 8;
static const int DH  = 64;
static const int DFF = 2048;
static const int NL  = 6;
static const int MAXE = 512;

// ---------------- scratch (static device memory; no allocation) -------------
__device__ float g_h   [G_ * L_ * 64];   // GAT output  [G, 68*64] = [G,4352]
__device__ float g_x   [G_ * DM];        // running activations [G,512]
__device__ float g_qkv [G_ * 3 * DM];    // [G,1536]
__device__ float g_attn[G_ * DM];
__device__ float g_proj[G_ * DM];
__device__ float g_ff  [G_ * DFF];

// =====================================================================
// GAT: both layers fused, one block per graph
// =====================================================================
__global__ __launch_bounds__(128) void gat_kernel(
    const float* __restrict__ lm, const int* __restrict__ ei, int E,
    const float* __restrict__ w1, const float* __restrict__ as1,
    const float* __restrict__ ad1, const float* __restrict__ b1,
    const float* __restrict__ w2, const float* __restrict__ as2,
    const float* __restrict__ ad2, const float* __restrict__ b2,
    float* __restrict__ out)
{
    __shared__ float h1[L_ * 16];
    __shared__ float x2[L_ * 16];
    __shared__ float h2[L_ * 64];
    __shared__ float sa[L_], sd[L_];
    __shared__ float ee[MAXE];
    __shared__ int   ssrc[MAXE], sdst[MAXE];

    const int g   = blockIdx.x;
    const int tid = threadIdx.x;
    const float* x = lm + (size_t)g * L_ * 2;

    for (int j = tid; j < E; j += blockDim.x) { ssrc[j] = ei[j]; sdst[j] = ei[E + j]; }

    // ---- layer 1: h1 = x @ W1^T  (W1 [16,2]) ----
    for (int i = tid; i < L_ * 16; i += blockDim.x) {
        int l = i >> 4, f = i & 15;
        h1[i] = w1[f * 2 + 0] * x[l * 2 + 0] + w1[f * 2 + 1] * x[l * 2 + 1];
    }
    __syncthreads();
    if (tid < L_) {
        float a = 0.f, d = 0.f;
        #pragma unroll
        for (int f = 0; f < 16; f++) { a += h1[tid * 16 + f] * as1[f]; d += h1[tid * 16 + f] * ad1[f]; }
        sa[tid] = a; sd[tid] = d;
    }
    __syncthreads();
    for (int j = tid; j < E; j += blockDim.x) {
        float v = sa[ssrc[j]] + sd[sdst[j]];
        ee[j] = v > 0.f ? v : 0.2f * v;
    }
    __syncthreads();
    if (tid < L_) {
        float m = -1e30f;
        for (int j = 0; j < E; j++) if (sdst[j] == tid) m = fmaxf(m, ee[j]);
        float s = 0.f;
        float acc[16];
        #pragma unroll
        for (int f = 0; f < 16; f++) acc[f] = 0.f;
        for (int j = 0; j < E; j++) if (sdst[j] == tid) {
            float w = expf(ee[j] - m); s += w;
            const float* hs = &h1[ssrc[j] * 16];
            #pragma unroll
            for (int f = 0; f < 16; f++) acc[f] += w * hs[f];
        }
        float inv = 1.f / s;
        #pragma unroll
        for (int f = 0; f < 16; f++) {
            float v = acc[f] * inv + b1[f];
            x2[tid * 16 + f] = v > 0.f ? v : 0.f;        // relu
        }
    }
    __syncthreads();

    // ---- layer 2: h2 = x2 @ W2^T  (W2 [64,16]) ----
    for (int i = tid; i < L_ * 64; i += blockDim.x) {
        int l = i >> 6, f = i & 63;
        float a = 0.f;
        const float* xr = &x2[l * 16];
        const float* wr = &w2[f * 16];
        #pragma unroll
        for (int c = 0; c < 16; c++) a += xr[c] * wr[c];
        h2[i] = a;
    }
    __syncthreads();
    if (tid < L_) {
        float a = 0.f, d = 0.f;
        const float* hr = &h2[tid * 64];
        #pragma unroll
        for (int f = 0; f < 64; f++) { a += hr[f] * as2[f]; d += hr[f] * ad2[f]; }
        sa[tid] = a; sd[tid] = d;
    }
    __syncthreads();
    for (int j = tid; j < E; j += blockDim.x) {
        float v = sa[ssrc[j]] + sd[sdst[j]];
        ee[j] = v > 0.f ? v : 0.2f * v;
    }
    __syncthreads();
    if (tid < L_) {
        float m = -1e30f;
        for (int j = 0; j < E; j++) if (sdst[j] == tid) m = fmaxf(m, ee[j]);
        float s = 0.f;
        float acc[64];
        #pragma unroll
        for (int f = 0; f < 64; f++) acc[f] = 0.f;
        for (int j = 0; j < E; j++) if (sdst[j] == tid) {
            float w = expf(ee[j] - m); s += w;
            const float* hs = &h2[ssrc[j] * 64];
            #pragma unroll
            for (int f = 0; f < 64; f++) acc[f] += w * hs[f];
        }
        float inv = 1.f / s;
        float* orow = out + (size_t)g * (L_ * 64) + tid * 64;
        #pragma unroll
        for (int f = 0; f < 64; f++) {
            float v = acc[f] * inv + b2[f];
            orow[f] = v > 0.f ? v : 0.f;                  // relu
        }
    }
}

// =====================================================================
// SGEMM: C[M,N] = A[M,K] @ W[N,K]^T + bias   (128x128x8, 8x8/thread)
// flags: 1 = relu, 2 = add positional encoding (pe[(m%256)*512 + n])
// =====================================================================
__global__ __launch_bounds__(256) void gemm_nt(
    const float* __restrict__ A, const float* __restrict__ W,
    const float* __restrict__ bias, float* __restrict__ C,
    int M, int N, int K, int flags, const float* __restrict__ pe)
{
    __shared__ __align__(16) float As[8][132];
    __shared__ __align__(16) float Bs[8][132];

    const int tid = threadIdx.x;
    const int lr  = tid >> 1;
    const int kq  = (tid & 1) * 4;
    const int tx  = tid & 15, ty = tid >> 4;

    const int rowA = blockIdx.y * 128 + lr;
    const int rowB = blockIdx.x * 128 + lr;
    const float* aptr = A + (size_t)rowA * K + kq;
    const float* bptr = W + (size_t)rowB * K + kq;

    float acc[8][8];
    #pragma unroll
    for (int i = 0; i < 8; i++)
        #pragma unroll
        for (int j = 0; j < 8; j++) acc[i][j] = 0.f;

    for (int k0 = 0; k0 < K; k0 += 8) {
        float4 av = *(const float4*)(aptr + k0);
        float4 bv = *(const float4*)(bptr + k0);
        As[kq + 0][lr] = av.x; As[kq + 1][lr] = av.y;
        As[kq + 2][lr] = av.z; As[kq + 3][lr] = av.w;
        Bs[kq + 0][lr] = bv.x; Bs[kq + 1][lr] = bv.y;
        Bs[kq + 2][lr] = bv.z; Bs[kq + 3][lr] = bv.w;
        __syncthreads();
        #pragma unroll
        for (int k = 0; k < 8; k++) {
            float a[8], b[8];
            *(float4*)(a)     = *(const float4*)&As[k][ty * 8];
            *(float4*)(a + 4) = *(const float4*)&As[k][ty * 8 + 4];
            *(float4*)(b)     = *(const float4*)&Bs[k][tx * 8];
            *(float4*)(b + 4) = *(const float4*)&Bs[k][tx * 8 + 4];
            #pragma unroll
            for (int i = 0; i < 8; i++)
                #pragma unroll
                for (int j = 0; j < 8; j++)
                    acc[i][j] = fmaf(a[i], b[j], acc[i][j]);
        }
        __syncthreads();
    }

    const int m0 = blockIdx.y * 128 + ty * 8;
    const int n0 = blockIdx.x * 128 + tx * 8;
    #pragma unroll
    for (int i = 0; i < 8; i++) {
        int m = m0 + i;
        float* crow = C + (size_t)m * N;
        #pragma unroll
        for (int j = 0; j < 8; j++) {
            int n = n0 + j;
            float v = acc[i][j] + bias[n];
            if (flags & 1) v = fmaxf(v, 0.f);
            if (flags & 2) v += pe[(size_t)(m & (S_ - 1)) * DM + n];
            crow[n] = v;
        }
    }
}

// =====================================================================
// Attention: one block per (b, h, q-chunk of 64).  smem-resident K/V/Q/S.
// =====================================================================
static const int KV_STRIDE = 69;   // pad to avoid bank conflicts
static const int ATTN_SMEM = (256 * KV_STRIDE * 2 + 64 * KV_STRIDE + 64 * 256) * 4;

__global__ __launch_bounds__(256) void attn_kernel(
    const float* __restrict__ qkv, float* __restrict__ o)
{
    extern __shared__ float sm[];
    float* Ks = sm;                          // [256][69]
    float* Vs = Ks + 256 * KV_STRIDE;        // [256][69]
    float* Qs = Vs + 256 * KV_STRIDE;        // [64][69]
    float* Ss = Qs + 64 * KV_STRIDE;         // [64][256]

    const int bh = blockIdx.x;
    const int b = bh >> 3, h = bh & 7;
    const int q0 = blockIdx.y * 64;
    const int tid = threadIdx.x;

    const float* base = qkv + (size_t)b * S_ * (3 * DM) + h * DH;

    for (int i = tid; i < 256 * 64; i += 256) {
        int r = i >> 6, c = i & 63;
        Ks[r * KV_STRIDE + c] = base[(size_t)r * (3 * DM) + DM + c];
        Vs[r * KV_STRIDE + c] = base[(size_t)r * (3 * DM) + 2 * DM + c];
    }
    for (int i = tid; i < 64 * 64; i += 256) {
        int r = i >> 6, c = i & 63;
        Qs[r * KV_STRIDE + c] = base[(size_t)(q0 + r) * (3 * DM) + c];
    }
    __syncthreads();

    // scores: iteration qi, thread -> key t
    for (int qi = 0; qi < 64; qi++) {
        const float* qr = &Qs[qi * KV_STRIDE];
        const float* kr = &Ks[tid * KV_STRIDE];
        float a = 0.f;
        #pragma unroll
        for (int c = 0; c < 64; c++) a = fmaf(qr[c], kr[c], a);
        Ss[qi * 256 + tid] = a * 0.125f;        // 1/sqrt(64)
    }
    __syncthreads();

    // softmax: one warp per row
    const int wid = tid >> 5, lane = tid & 31;
    for (int r = wid; r < 64; r += 8) {
        float* row = &Ss[r * 256];
        float mx = -1e30f;
        for (int t = lane; t < 256; t += 32) mx = fmaxf(mx, row[t]);
        #pragma unroll
        for (int off = 16; off; off >>= 1) mx = fmaxf(mx, __shfl_xor_sync(0xffffffffu, mx, off));
        float s = 0.f;
        for (int t = lane; t < 256; t += 32) { float e = expf(row[t] - mx); row[t] = e; s += e; }
        #pragma unroll
        for (int off = 16; off; off >>= 1) s += __shfl_xor_sync(0xffffffffu, s, off);
        float inv = 1.f / s;
        for (int t = lane; t < 256; t += 32) row[t] *= inv;
    }
    __syncthreads();

    // O = S @ V
    for (int i = tid; i < 64 * 64; i += 256) {
        int qi = i >> 6, c = i & 63;
        const float* srow = &Ss[qi * 256];
        float a = 0.f;
        #pragma unroll 8
        for (int t = 0; t < 256; t++) a = fmaf(srow[t], Vs[t * KV_STRIDE + c], a);
        o[((size_t)b * S_ + q0 + qi) * DM + h * DH + c] = a;
    }
}

// =====================================================================
// Residual + LayerNorm: out = LN(x + r) * g + b    (one block per row)
// =====================================================================
__global__ __launch_bounds__(128) void ln_kernel(
    const float* __restrict__ x, const float* __restrict__ r,
    const float* __restrict__ gam, const float* __restrict__ bet,
    float* __restrict__ out)
{
    const int row = blockIdx.x, tid = threadIdx.x;
    const float* xr = x + (size_t)row * DM;
    const float* rr = r + (size_t)row * DM;
    float v[4];
    float s = 0.f, s2 = 0.f;
    #pragma unroll
    for (int u = 0; u < 4; u++) {
        int i = tid + u * 128;
        v[u] = xr[i] + rr[i];
        s += v[u]; s2 += v[u] * v[u];
    }
    // block reduce (4 warps)
    __shared__ float rs[4], rs2[4];
    #pragma unroll
    for (int off = 16; off; off >>= 1) {
        s  += __shfl_xor_sync(0xffffffffu, s,  off);
        s2 += __shfl_xor_sync(0xffffffffu, s2, off);
    }
    if ((tid & 31) == 0) { rs[tid >> 5] = s; rs2[tid >> 5] = s2; }
    __syncthreads();
    s = rs[0] + rs[1] + rs[2] + rs[3];
    s2 = rs2[0] + rs2[1] + rs2[2] + rs2[3];
    float mean = s * (1.f / DM);
    float var  = s2 * (1.f / DM) - mean * mean;
    float k = rsqrtf(var + 1e-5f);
    float* orow = out + (size_t)row * DM;
    #pragma unroll
    for (int u = 0; u < 4; u++) {
        int i = tid + u * 128;
        orow[i] = (v[u] - mean) * k * gam[i] + bet[i];
    }
}

// =====================================================================
// host launcher
// =====================================================================
static void run_gemm(const float* A, const float* W, const float* bias, float* C,
                     int M, int N, int K, int flags, const float* pe) {
    dim3 grid(N / 128, M / 128);
    gemm_nt<<<grid, 256>>>(A, W, bias, C, M, N, K, flags, pe);
}

extern "C" void kernel_launch(void* const* d_in, const int* in_sizes, int n_in,
                              void* d_out, int out_size)
{
    const float* lm    = (const float*)d_in[0];
    const int*   ei    = (const int*)  d_in[1];
    const int    E     = in_sizes[1] / 2;
    const float* g1w   = (const float*)d_in[2];
    const float* g1as  = (const float*)d_in[3];
    const float* g1ad  = (const float*)d_in[4];
    const float* g1b   = (const float*)d_in[5];
    const float* g2w   = (const float*)d_in[6];
    const float* g2as  = (const float*)d_in[7];
    const float* g2ad  = (const float*)d_in[8];
    const float* g2b   = (const float*)d_in[9];
    const float* fcw   = (const float*)d_in[10];
    const float* fcb   = (const float*)d_in[11];
    const float* pe    = (const float*)d_in[12];
    const float* ipw   = (const float*)d_in[13];
    const float* ipb   = (const float*)d_in[14];
    const float* opw   = (const float*)d_in[15];
    const float* opb   = (const float*)d_in[16];
    const float* ln1g  = (const float*)d_in[17];
    const float* ln1b  = (const float*)d_in[18];
    const float* fw1   = (const float*)d_in[19];
    const float* fb1   = (const float*)d_in[20];
    const float* fw2   = (const float*)d_in[21];
    const float* fb2   = (const float*)d_in[22];
    const float* ln2g  = (const float*)d_in[23];
    const float* ln2b  = (const float*)d_in[24];

    float *gh, *gx, *gqkv, *gattn, *gproj, *gff;
    cudaGetSymbolAddress((void**)&gh,   g_h);
    cudaGetSymbolAddress((void**)&gx,   g_x);
    cudaGetSymbolAddress((void**)&gqkv, g_qkv);
    cudaGetSymbolAddress((void**)&gattn,g_attn);
    cudaGetSymbolAddress((void**)&gproj,g_proj);
    cudaGetSymbolAddress((void**)&gff,  g_ff);

    cudaFuncSetAttribute(attn_kernel, cudaFuncAttributeMaxDynamicSharedMemorySize, ATTN_SMEM);

    // 1. GAT frontend
    gat_kernel<<<G_, 128>>>(lm, ei, E, g1w, g1as, g1ad, g1b,
                            g2w, g2as, g2ad, g2b, gh);

    // 2. FC + positional encoding
    run_gemm(gh, fcw, fcb, gx, G_, DM, L_ * 64, /*flags=*/2, pe);

    // 3. transformer encoder layers
    for (int l = 0; l < NL; l++) {
        run_gemm(gx, ipw + (size_t)l * 3 * DM * DM, ipb + (size_t)l * 3 * DM,
                 gqkv, G_, 3 * DM, DM, 0, nullptr);
        attn_kernel<<<dim3(B_ * NH, S_ / 64), 256, ATTN_SMEM>>>(gqkv, gattn);
        run_gemm(gattn, opw + (size_t)l * DM * DM, opb + (size_t)l * DM,
                 gproj, G_, DM, DM, 0, nullptr);
        ln_kernel<<<G_, 128>>>(gx, gproj, ln1g + (size_t)l * DM, ln1b + (size_t)l * DM, gx);

        run_gemm(gx, fw1 + (size_t)l * DFF * DM, fb1 + (size_t)l * DFF,
                 gff, G_, DFF, DM, /*relu*/1, nullptr);
        run_gemm(gff, fw2 + (size_t)l * DM * DFF, fb2 + (size_t)l * DM,
                 gproj, G_, DM, DFF, 0, nullptr);
        float* outp = (l == NL - 1) ? (float*)d_out : gx;
        ln_kernel<<<G_, 128>>>(gx, gproj, ln2g + (size_t)l * DM, ln2b + (size_t)l * DM, outp);
    }
    (void)n_in; (void)out_size;
}

// round 3
// speedup vs baseline: 1.9672x; 1.9672x over previous
#include <cuda_runtime.h>
#include <cuda_bf16.h>
#include <math.h>
#include <stdint.h>

// ---------------- problem constants ----------------
static const int B_  = 8;
static const int S_  = 256;
static const int G_  = 2048;      // B*S graphs / tokens
static const int L_  = 68;        // landmarks
static const int DM  = 512;       // d_model
static const int NH  = 8;
static const int DH  = 64;
static const int DFF = 2048;
static const int NL  = 6;
static const int MAXE = 512;

// ---------------- scratch (static device memory; no allocation) -------------
__device__ float g_h   [G_ * L_ * 64];   // GAT output  [G,4352]
__device__ float g_x   [G_ * DM];
__device__ float g_qkv [G_ * 3 * DM];
__device__ float g_attn[G_ * DM];
__device__ float g_proj[G_ * DM];
__device__ float g_ff  [G_ * DFF];

// =====================================================================
// GAT: both layers fused, one block per graph
// =====================================================================
__global__ __launch_bounds__(128) void gat_kernel(
    const float* __restrict__ lm, const int* __restrict__ ei, int E,
    const float* __restrict__ w1, const float* __restrict__ as1,
    const float* __restrict__ ad1, const float* __restrict__ b1,
    const float* __restrict__ w2, const float* __restrict__ as2,
    const float* __restrict__ ad2, const float* __restrict__ b2,
    float* __restrict__ out)
{
    __shared__ float h1[L_ * 16];
    __shared__ float x2[L_ * 16];
    __shared__ float h2[L_ * 64];
    __shared__ float sa[L_], sd[L_];
    __shared__ float ee[MAXE];
    __shared__ int   ssrc[MAXE], sdst[MAXE];

    const int g   = blockIdx.x;
    const int tid = threadIdx.x;
    const float* x = lm + (size_t)g * L_ * 2;

    for (int j = tid; j < E; j += blockDim.x) { ssrc[j] = ei[j]; sdst[j] = ei[E + j]; }

    for (int i = tid; i < L_ * 16; i += blockDim.x) {
        int l = i >> 4, f = i & 15;
        h1[i] = w1[f * 2 + 0] * x[l * 2 + 0] + w1[f * 2 + 1] * x[l * 2 + 1];
    }
    __syncthreads();
    if (tid < L_) {
        float a = 0.f, d = 0.f;
        #pragma unroll
        for (int f = 0; f < 16; f++) { a += h1[tid * 16 + f] * as1[f]; d += h1[tid * 16 + f] * ad1[f]; }
        sa[tid] = a; sd[tid] = d;
    }
    __syncthreads();
    for (int j = tid; j < E; j += blockDim.x) {
        float v = sa[ssrc[j]] + sd[sdst[j]];
        ee[j] = v > 0.f ? v : 0.2f * v;
    }
    __syncthreads();
    if (tid < L_) {
        float m = -1e30f;
        for (int j = 0; j < E; j++) if (sdst[j] == tid) m = fmaxf(m, ee[j]);
        float s = 0.f;
        float acc[16];
        #pragma unroll
        for (int f = 0; f < 16; f++) acc[f] = 0.f;
        for (int j = 0; j < E; j++) if (sdst[j] == tid) {
            float w = expf(ee[j] - m); s += w;
            const float* hs = &h1[ssrc[j] * 16];
            #pragma unroll
            for (int f = 0; f < 16; f++) acc[f] += w * hs[f];
        }
        float inv = 1.f / s;
        #pragma unroll
        for (int f = 0; f < 16; f++) {
            float v = acc[f] * inv + b1[f];
            x2[tid * 16 + f] = v > 0.f ? v : 0.f;
        }
    }
    __syncthreads();

    for (int i = tid; i < L_ * 64; i += blockDim.x) {
        int l = i >> 6, f = i & 63;
        float a = 0.f;
        const float* xr = &x2[l * 16];
        const float* wr = &w2[f * 16];
        #pragma unroll
        for (int c = 0; c < 16; c++) a += xr[c] * wr[c];
        h2[i] = a;
    }
    __syncthreads();
    if (tid < L_) {
        float a = 0.f, d = 0.f;
        const float* hr = &h2[tid * 64];
        #pragma unroll
        for (int f = 0; f < 64; f++) { a += hr[f] * as2[f]; d += hr[f] * ad2[f]; }
        sa[tid] = a; sd[tid] = d;
    }
    __syncthreads();
    for (int j = tid; j < E; j += blockDim.x) {
        float v = sa[ssrc[j]] + sd[sdst[j]];
        ee[j] = v > 0.f ? v : 0.2f * v;
    }
    __syncthreads();
    if (tid < L_) {
        float m = -1e30f;
        for (int j = 0; j < E; j++) if (sdst[j] == tid) m = fmaxf(m, ee[j]);
        float s = 0.f;
        float acc[64];
        #pragma unroll
        for (int f = 0; f < 64; f++) acc[f] = 0.f;
        for (int j = 0; j < E; j++) if (sdst[j] == tid) {
            float w = expf(ee[j] - m); s += w;
            const float* hs = &h2[ssrc[j] * 64];
            #pragma unroll
            for (int f = 0; f < 64; f++) acc[f] += w * hs[f];
        }
        float inv = 1.f / s;
        float* orow = out + (size_t)g * (L_ * 64) + tid * 64;
        #pragma unroll
        for (int f = 0; f < 64; f++) {
            float v = acc[f] * inv + b2[f];
            orow[f] = v > 0.f ? v : 0.f;
        }
    }
}

// =====================================================================
// bf16 split-precision tensor-core GEMM:  C[M,N] = A[M,K] @ W[N,K]^T + bias
// 128x128 block tile, 8 warps (2x4), warp tile 64x32, k-step 32.
// Each fp32 operand split into hi+lo bf16; C += ah*bh + ah*bl + al*bh.
// flags: 1 = relu, 2 = add positional encoding pe[(m%256)*512 + n]
// =====================================================================
static const int TSTR = 40;   // smem row stride (bf16 elems) -> 80B, conflict-free ldmatrix

__device__ __forceinline__ void ldsm4(uint32_t& r0, uint32_t& r1, uint32_t& r2, uint32_t& r3,
                                      const __nv_bfloat16* p) {
    uint32_t addr = (uint32_t)__cvta_generic_to_shared(p);
    asm volatile("ldmatrix.sync.aligned.m8n8.x4.shared.b16 {%0,%1,%2,%3}, [%4];\n"
                 : "=r"(r0), "=r"(r1), "=r"(r2), "=r"(r3) : "r"(addr));
}

__device__ __forceinline__ void mma16816(float* c, const uint32_t* a, uint32_t b0, uint32_t b1) {
    asm volatile("mma.sync.aligned.m16n8k16.row.col.f32.bf16.bf16.f32 "
                 "{%0,%1,%2,%3}, {%4,%5,%6,%7}, {%8,%9}, {%0,%1,%2,%3};\n"
                 : "+f"(c[0]), "+f"(c[1]), "+f"(c[2]), "+f"(c[3])
                 : "r"(a[0]), "r"(a[1]), "r"(a[2]), "r"(a[3]), "r"(b0), "r"(b1));
}

__device__ __forceinline__ uint32_t pack_bf2(__nv_bfloat16 a, __nv_bfloat16 b) {
    __nv_bfloat162 t; t.x = a; t.y = b;
    return *(uint32_t*)&t;
}

__global__ __launch_bounds__(256) void gemm_bf16s(
    const float* __restrict__ A, const float* __restrict__ W,
    const float* __restrict__ bias, float* __restrict__ C,
    int M, int N, int K, int flags, const float* __restrict__ pe)
{
    __shared__ __nv_bfloat16 Ah[128 * TSTR], Al[128 * TSTR];
    __shared__ __nv_bfloat16 Bh[128 * TSTR], Bl[128 * TSTR];

    const int tid  = threadIdx.x;
    const int lane = tid & 31, warp = tid >> 5;
    const int wm = warp & 1, wn = warp >> 1;          // 2 x 4 warp grid
    const int bm = blockIdx.y, bn = blockIdx.x;

    const float* Ag = A + (size_t)(bm * 128) * K;
    const float* Wg = W + (size_t)(bn * 128) * K;

    float c[4][4][4];
    #pragma unroll
    for (int i = 0; i < 4; i++)
        #pragma unroll
        for (int j = 0; j < 4; j++)
            #pragma unroll
            for (int q = 0; q < 4; q++) c[i][j][q] = 0.f;

    float4 ra[4], rb[4];

    // preload tile 0
    #pragma unroll
    for (int i = 0; i < 4; i++) {
        int idx = tid + i * 256;
        int row = idx >> 3, c4 = idx & 7;
        ra[i] = *(const float4*)(Ag + (size_t)row * K + c4 * 4);
        rb[i] = *(const float4*)(Wg + (size_t)row * K + c4 * 4);
    }
    // store tile 0
    #pragma unroll
    for (int i = 0; i < 4; i++) {
        int idx = tid + i * 256;
        int row = idx >> 3, c4 = idx & 7;
        float va[4] = {ra[i].x, ra[i].y, ra[i].z, ra[i].w};
        float vb[4] = {rb[i].x, rb[i].y, rb[i].z, rb[i].w};
        __nv_bfloat16 ah[4], al[4], bh[4], bl[4];
        #pragma unroll
        for (int j = 0; j < 4; j++) {
            ah[j] = __float2bfloat16(va[j]);
            al[j] = __float2bfloat16(va[j] - __bfloat162float(ah[j]));
            bh[j] = __float2bfloat16(vb[j]);
            bl[j] = __float2bfloat16(vb[j] - __bfloat162float(bh[j]));
        }
        uint2 pa_h = {pack_bf2(ah[0], ah[1]), pack_bf2(ah[2], ah[3])};
        uint2 pa_l = {pack_bf2(al[0], al[1]), pack_bf2(al[2], al[3])};
        uint2 pb_h = {pack_bf2(bh[0], bh[1]), pack_bf2(bh[2], bh[3])};
        uint2 pb_l = {pack_bf2(bl[0], bl[1]), pack_bf2(bl[2], bl[3])};
        *(uint2*)&Ah[row * TSTR + c4 * 4] = pa_h;
        *(uint2*)&Al[row * TSTR + c4 * 4] = pa_l;
        *(uint2*)&Bh[row * TSTR + c4 * 4] = pb_h;
        *(uint2*)&Bl[row * TSTR + c4 * 4] = pb_l;
    }
    __syncthreads();

    for (int k0 = 0; k0 < K; k0 += 32) {
        const bool last = (k0 + 32 >= K);
        if (!last) {
            #pragma unroll
            for (int i = 0; i < 4; i++) {
                int idx = tid + i * 256;
                int row = idx >> 3, c4 = idx & 7;
                ra[i] = *(const float4*)(Ag + (size_t)row * K + (k0 + 32) + c4 * 4);
                rb[i] = *(const float4*)(Wg + (size_t)row * K + (k0 + 32) + c4 * 4);
            }
        }

        // compute current smem tile: two k16 halves
        #pragma unroll
        for (int kh = 0; kh < 2; kh++) {
            const int r  = lane & 15;
            const int cc = kh * 16 + ((lane >> 4) << 3);
            uint32_t ah[4][4], al[4][4], bhr[2][4], blr[2][4];
            #pragma unroll
            for (int mt = 0; mt < 4; mt++) {
                int row = wm * 64 + mt * 16 + r;
                ldsm4(ah[mt][0], ah[mt][1], ah[mt][2], ah[mt][3], &Ah[row * TSTR + cc]);
                ldsm4(al[mt][0], al[mt][1], al[mt][2], al[mt][3], &Al[row * TSTR + cc]);
            }
            #pragma unroll
            for (int g = 0; g < 2; g++) {
                int row = wn * 32 + g * 16 + r;
                ldsm4(bhr[g][0], bhr[g][1], bhr[g][2], bhr[g][3], &Bh[row * TSTR + cc]);
                ldsm4(blr[g][0], blr[g][1], blr[g][2], blr[g][3], &Bl[row * TSTR + cc]);
            }
            #pragma unroll
            for (int mt = 0; mt < 4; mt++) {
                #pragma unroll
                for (int nt = 0; nt < 4; nt++) {
                    const int g = nt >> 1, s = nt & 1;
                    mma16816(c[mt][nt], ah[mt], bhr[g][s], bhr[g][s + 2]);
                    mma16816(c[mt][nt], ah[mt], blr[g][s], blr[g][s + 2]);
                    mma16816(c[mt][nt], al[mt], bhr[g][s], bhr[g][s + 2]);
                }
            }
        }
        __syncthreads();
        if (!last) {
            #pragma unroll
            for (int i = 0; i < 4; i++) {
                int idx = tid + i * 256;
                int row = idx >> 3, c4 = idx & 7;
                float va[4] = {ra[i].x, ra[i].y, ra[i].z, ra[i].w};
                float vb[4] = {rb[i].x, rb[i].y, rb[i].z, rb[i].w};
                __nv_bfloat16 hah[4], hal[4], hbh[4], hbl[4];
                #pragma unroll
                for (int j = 0; j < 4; j++) {
                    hah[j] = __float2bfloat16(va[j]);
                    hal[j] = __float2bfloat16(va[j] - __bfloat162float(hah[j]));
                    hbh[j] = __float2bfloat16(vb[j]);
                    hbl[j] = __float2bfloat16(vb[j] - __bfloat162float(hbh[j]));
                }
                *(uint2*)&Ah[row * TSTR + c4 * 4] = {pack_bf2(hah[0], hah[1]), pack_bf2(hah[2], hah[3])};
                *(uint2*)&Al[row * TSTR + c4 * 4] = {pack_bf2(hal[0], hal[1]), pack_bf2(hal[2], hal[3])};
                *(uint2*)&Bh[row * TSTR + c4 * 4] = {pack_bf2(hbh[0], hbh[1]), pack_bf2(hbh[2], hbh[3])};
                *(uint2*)&Bl[row * TSTR + c4 * 4] = {pack_bf2(hbl[0], hbl[1]), pack_bf2(hbl[2], hbl[3])};
            }
            __syncthreads();
        }
    }

    // epilogue
    #pragma unroll
    for (int mt = 0; mt < 4; mt++) {
        const int mbase = bm * 128 + wm * 64 + mt * 16 + (lane >> 2);
        #pragma unroll
        for (int half = 0; half < 2; half++) {
            const int m = mbase + half * 8;
            float* crow = C + (size_t)m * N;
            const float* perow = (flags & 2) ? (pe + (size_t)(m & (S_ - 1)) * DM) : nullptr;
            #pragma unroll
            for (int nt = 0; nt < 4; nt++) {
                const int n = bn * 128 + wn * 32 + nt * 8 + (lane & 3) * 2;
                float v0 = c[mt][nt][half * 2 + 0] + bias[n];
                float v1 = c[mt][nt][half * 2 + 1] + bias[n + 1];
                if (flags & 1) { v0 = fmaxf(v0, 0.f); v1 = fmaxf(v1, 0.f); }
                if (flags & 2) { v0 += perow[n]; v1 += perow[n + 1]; }
                float2 o; o.x = v0; o.y = v1;
                *(float2*)(crow + n) = o;
            }
        }
    }
}

// =====================================================================
// Attention: one block per (b, h, q-chunk of 64).  smem-resident K/V/Q/S.
// =====================================================================
static const int KV_STRIDE = 69;
static const int ATTN_SMEM = (256 * KV_STRIDE * 2 + 64 * KV_STRIDE + 64 * 256) * 4;

__global__ __launch_bounds__(256) void attn_kernel(
    const float* __restrict__ qkv, float* __restrict__ o)
{
    extern __shared__ float sm[];
    float* Ks = sm;
    float* Vs = Ks + 256 * KV_STRIDE;
    float* Qs = Vs + 256 * KV_STRIDE;
    float* Ss = Qs + 64 * KV_STRIDE;

    const int bh = blockIdx.x;
    const int b = bh >> 3, h = bh & 7;
    const int q0 = blockIdx.y * 64;
    const int tid = threadIdx.x;

    const float* base = qkv + (size_t)b * S_ * (3 * DM) + h * DH;

    for (int i = tid; i < 256 * 64; i += 256) {
        int r = i >> 6, c = i & 63;
        Ks[r * KV_STRIDE + c] = base[(size_t)r * (3 * DM) + DM + c];
        Vs[r * KV_STRIDE + c] = base[(size_t)r * (3 * DM) + 2 * DM + c];
    }
    for (int i = tid; i < 64 * 64; i += 256) {
        int r = i >> 6, c = i & 63;
        Qs[r * KV_STRIDE + c] = base[(size_t)(q0 + r) * (3 * DM) + c];
    }
    __syncthreads();

    for (int qi = 0; qi < 64; qi++) {
        const float* qr = &Qs[qi * KV_STRIDE];
        const float* kr = &Ks[tid * KV_STRIDE];
        float a = 0.f;
        #pragma unroll
        for (int c = 0; c < 64; c++) a = fmaf(qr[c], kr[c], a);
        Ss[qi * 256 + tid] = a * 0.125f;
    }
    __syncthreads();

    const int wid = tid >> 5, lane = tid & 31;
    for (int r = wid; r < 64; r += 8) {
        float* row = &Ss[r * 256];
        float mx = -1e30f;
        for (int t = lane; t < 256; t += 32) mx = fmaxf(mx, row[t]);
        #pragma unroll
        for (int off = 16; off; off >>= 1) mx = fmaxf(mx, __shfl_xor_sync(0xffffffffu, mx, off));
        float s = 0.f;
        for (int t = lane; t < 256; t += 32) { float e = expf(row[t] - mx); row[t] = e; s += e; }
        #pragma unroll
        for (int off = 16; off; off >>= 1) s += __shfl_xor_sync(0xffffffffu, s, off);
        float inv = 1.f / s;
        for (int t = lane; t < 256; t += 32) row[t] *= inv;
    }
    __syncthreads();

    for (int i = tid; i < 64 * 64; i += 256) {
        int qi = i >> 6, c = i & 63;
        const float* srow = &Ss[qi * 256];
        float a = 0.f;
        #pragma unroll 8
        for (int t = 0; t < 256; t++) a = fmaf(srow[t], Vs[t * KV_STRIDE + c], a);
        o[((size_t)b * S_ + q0 + qi) * DM + h * DH + c] = a;
    }
}

// =====================================================================
// Residual + LayerNorm
// =====================================================================
__global__ __launch_bounds__(128) void ln_kernel(
    const float* __restrict__ x, const float* __restrict__ r,
    const float* __restrict__ gam, const float* __restrict__ bet,
    float* __restrict__ out)
{
    const int row = blockIdx.x, tid = threadIdx.x;
    const float* xr = x + (size_t)row * DM;
    const float* rr = r + (size_t)row * DM;
    float v[4];
    float s = 0.f, s2 = 0.f;
    #pragma unroll
    for (int u = 0; u < 4; u++) {
        int i = tid + u * 128;
        v[u] = xr[i] + rr[i];
        s += v[u]; s2 += v[u] * v[u];
    }
    __shared__ float rs[4], rs2[4];
    #pragma unroll
    for (int off = 16; off; off >>= 1) {
        s  += __shfl_xor_sync(0xffffffffu, s,  off);
        s2 += __shfl_xor_sync(0xffffffffu, s2, off);
    }
    if ((tid & 31) == 0) { rs[tid >> 5] = s; rs2[tid >> 5] = s2; }
    __syncthreads();
    s  = rs[0] + rs[1] + rs[2] + rs[3];
    s2 = rs2[0] + rs2[1] + rs2[2] + rs2[3];
    float mean = s * (1.f / DM);
    float var  = s2 * (1.f / DM) - mean * mean;
    float k = rsqrtf(var + 1e-5f);
    float* orow = out + (size_t)row * DM;
    #pragma unroll
    for (int u = 0; u < 4; u++) {
        int i = tid + u * 128;
        orow[i] = (v[u] - mean) * k * gam[i] + bet[i];
    }
}

// =====================================================================
// host launcher
// =====================================================================
static void run_gemm(const float* A, const float* W, const float* bias, float* C,
                     int M, int N, int K, int flags, const float* pe) {
    dim3 grid(N / 128, M / 128);
    gemm_bf16s<<<grid, 256>>>(A, W, bias, C, M, N, K, flags, pe);
}

extern "C" void kernel_launch(void* const* d_in, const int* in_sizes, int n_in,
                              void* d_out, int out_size)
{
    const float* lm    = (const float*)d_in[0];
    const int*   ei    = (const int*)  d_in[1];
    const int    E     = in_sizes[1] / 2;
    const float* g1w   = (const float*)d_in[2];
    const float* g1as  = (const float*)d_in[3];
    const float* g1ad  = (const float*)d_in[4];
    const float* g1b   = (const float*)d_in[5];
    const float* g2w   = (const float*)d_in[6];
    const float* g2as  = (const float*)d_in[7];
    const float* g2ad  = (const float*)d_in[8];
    const float* g2b   = (const float*)d_in[9];
    const float* fcw   = (const float*)d_in[10];
    const float* fcb   = (const float*)d_in[11];
    const float* pe    = (const float*)d_in[12];
    const float* ipw   = (const float*)d_in[13];
    const float* ipb   = (const float*)d_in[14];
    const float* opw   = (const float*)d_in[15];
    const float* opb   = (const float*)d_in[16];
    const float* ln1g  = (const float*)d_in[17];
    const float* ln1b  = (const float*)d_in[18];
    const float* fw1   = (const float*)d_in[19];
    const float* fb1   = (const float*)d_in[20];
    const float* fw2   = (const float*)d_in[21];
    const float* fb2   = (const float*)d_in[22];
    const float* ln2g  = (const float*)d_in[23];
    const float* ln2b  = (const float*)d_in[24];

    float *gh, *gx, *gqkv, *gattn, *gproj, *gff;
    cudaGetSymbolAddress((void**)&gh,   g_h);
    cudaGetSymbolAddress((void**)&gx,   g_x);
    cudaGetSymbolAddress((void**)&gqkv, g_qkv);
    cudaGetSymbolAddress((void**)&gattn,g_attn);
    cudaGetSymbolAddress((void**)&gproj,g_proj);
    cudaGetSymbolAddress((void**)&gff,  g_ff);

    cudaFuncSetAttribute(attn_kernel, cudaFuncAttributeMaxDynamicSharedMemorySize, ATTN_SMEM);

    // 1. GAT frontend
    gat_kernel<<<G_, 128>>>(lm, ei, E, g1w, g1as, g1ad, g1b,
                            g2w, g2as, g2ad, g2b, gh);

    // 2. FC + positional encoding
    run_gemm(gh, fcw, fcb, gx, G_, DM, L_ * 64, /*flags=*/2, pe);

    // 3. transformer encoder layers
    for (int l = 0; l < NL; l++) {
        run_gemm(gx, ipw + (size_t)l * 3 * DM * DM, ipb + (size_t)l * 3 * DM,
                 gqkv, G_, 3 * DM, DM, 0, nullptr);
        attn_kernel<<<dim3(B_ * NH, S_ / 64), 256, ATTN_SMEM>>>(gqkv, gattn);
        run_gemm(gattn, opw + (size_t)l * DM * DM, opb + (size_t)l * DM,
                 gproj, G_, DM, DM, 0, nullptr);
        ln_kernel<<<G_, 128>>>(gx, gproj, ln1g + (size_t)l * DM, ln1b + (size_t)l * DM, gx);

        run_gemm(gx, fw1 + (size_t)l * DFF * DM, fb1 + (size_t)l * DFF,
                 gff, G_, DFF, DM, /*relu*/1, nullptr);
        run_gemm(gff, fw2 + (size_t)l * DM * DFF, fb2 + (size_t)l * DM,
                 gproj, G_, DM, DFF, 0, nullptr);
        float* outp = (l == NL - 1) ? (float*)d_out : gx;
        ln_kernel<<<G_, 128>>>(gx, gproj, ln2g + (size_t)l * DM, ln2b + (size_t)l * DM, outp);
    }
    (void)n_in; (void)out_size;
}

// round 5
// speedup vs baseline: 1.9834x; 1.0082x over previous
#include <cuda_runtime.h>
#include <cuda_bf16.h>
#include <math.h>
#include <stdint.h>

// ---------------- problem constants ----------------
static const int B_  = 8;
static const int S_  = 256;
static const int G_  = 2048;
static const int L_  = 68;
static const int DM  = 512;
static const int NH  = 8;
static const int DH  = 64;
static const int DFF = 2048;
static const int NL  = 6;
static const int MAXE = 512;

// weight offsets in the packed split-weight buffers
static const size_t OFF_FC = 0;                    // 512*4352
static const size_t OFF_IP = 2228224;              // 6*1536*512
static const size_t OFF_OP = 6946816;              // 6*512*512
static const size_t OFF_F1 = 8519680;              // 6*2048*512
static const size_t OFF_F2 = 14811136;             // 6*512*2048
static const size_t W_TOT  = 21102592;

// ---------------- scratch (static device memory) ----------------
__device__ __nv_bfloat16 w_h[W_TOT], w_l[W_TOT];
__device__ __nv_bfloat16 gh_h[G_ * L_ * 64], gh_l[G_ * L_ * 64];
__device__ __nv_bfloat16 gx_h[G_ * DM],      gx_l[G_ * DM];
__device__ __nv_bfloat16 at_h[G_ * DM],      at_l[G_ * DM];
__device__ __nv_bfloat16 ff_h[G_ * DFF],     ff_l[G_ * DFF];
__device__ float g_x   [G_ * DM];
__device__ float g_qkv [G_ * 3 * DM];
__device__ float g_proj[G_ * DM];

// ---------------- helpers ----------------
__device__ __forceinline__ void split_write(float v, __nv_bfloat16* hi, __nv_bfloat16* lo, size_t i) {
    __nv_bfloat16 h = __float2bfloat16(v);
    hi[i] = h;
    lo[i] = __float2bfloat16(v - __bfloat162float(h));
}

// =====================================================================
// weight split kernel (grid-stride)
// =====================================================================
__global__ __launch_bounds__(256) void split_kernel(
    const float* __restrict__ src, __nv_bfloat16* __restrict__ hi,
    __nv_bfloat16* __restrict__ lo, int n)
{
    int i = blockIdx.x * blockDim.x + threadIdx.x;
    int stride = gridDim.x * blockDim.x;
    for (; i < n; i += stride) {
        float v = src[i];
        __nv_bfloat16 h = __float2bfloat16(v);
        hi[i] = h;
        lo[i] = __float2bfloat16(v - __bfloat162float(h));
    }
}

// =====================================================================
// GAT: both layers fused, one block per graph; writes split bf16
// =====================================================================
__global__ __launch_bounds__(128) void gat_kernel(
    const float* __restrict__ lm, const int* __restrict__ ei, int E,
    const float* __restrict__ w1, const float* __restrict__ as1,
    const float* __restrict__ ad1, const float* __restrict__ b1,
    const float* __restrict__ w2, const float* __restrict__ as2,
    const float* __restrict__ ad2, const float* __restrict__ b2,
    __nv_bfloat16* __restrict__ oh, __nv_bfloat16* __restrict__ ol)
{
    __shared__ float h1[L_ * 16];
    __shared__ float x2[L_ * 16];
    __shared__ float h2[L_ * 64];
    __shared__ float sa[L_], sd[L_];
    __shared__ float ee[MAXE];
    __shared__ int   ssrc[MAXE], sdst[MAXE];

    const int g   = blockIdx.x;
    const int tid = threadIdx.x;
    const float* x = lm + (size_t)g * L_ * 2;

    for (int j = tid; j < E; j += blockDim.x) { ssrc[j] = ei[j]; sdst[j] = ei[E + j]; }

    for (int i = tid; i < L_ * 16; i += blockDim.x) {
        int l = i >> 4, f = i & 15;
        h1[i] = w1[f * 2 + 0] * x[l * 2 + 0] + w1[f * 2 + 1] * x[l * 2 + 1];
    }
    __syncthreads();
    if (tid < L_) {
        float a = 0.f, d = 0.f;
        #pragma unroll
        for (int f = 0; f < 16; f++) { a += h1[tid * 16 + f] * as1[f]; d += h1[tid * 16 + f] * ad1[f]; }
        sa[tid] = a; sd[tid] = d;
    }
    __syncthreads();
    for (int j = tid; j < E; j += blockDim.x) {
        float v = sa[ssrc[j]] + sd[sdst[j]];
        ee[j] = v > 0.f ? v : 0.2f * v;
    }
    __syncthreads();
    if (tid < L_) {
        float m = -1e30f;
        for (int j = 0; j < E; j++) if (sdst[j] == tid) m = fmaxf(m, ee[j]);
        float s = 0.f;
        float acc[16];
        #pragma unroll
        for (int f = 0; f < 16; f++) acc[f] = 0.f;
        for (int j = 0; j < E; j++) if (sdst[j] == tid) {
            float w = expf(ee[j] - m); s += w;
            const float* hs = &h1[ssrc[j] * 16];
            #pragma unroll
            for (int f = 0; f < 16; f++) acc[f] += w * hs[f];
        }
        float inv = 1.f / s;
        #pragma unroll
        for (int f = 0; f < 16; f++) {
            float v = acc[f] * inv + b1[f];
            x2[tid * 16 + f] = v > 0.f ? v : 0.f;
        }
    }
    __syncthreads();

    for (int i = tid; i < L_ * 64; i += blockDim.x) {
        int l = i >> 6, f = i & 63;
        float a = 0.f;
        const float* xr = &x2[l * 16];
        const float* wr = &w2[f * 16];
        #pragma unroll
        for (int c = 0; c < 16; c++) a += xr[c] * wr[c];
        h2[i] = a;
    }
    __syncthreads();
    if (tid < L_) {
        float a = 0.f, d = 0.f;
        const float* hr = &h2[tid * 64];
        #pragma unroll
        for (int f = 0; f < 64; f++) { a += hr[f] * as2[f]; d += hr[f] * ad2[f]; }
        sa[tid] = a; sd[tid] = d;
    }
    __syncthreads();
    for (int j = tid; j < E; j += blockDim.x) {
        float v = sa[ssrc[j]] + sd[sdst[j]];
        ee[j] = v > 0.f ? v : 0.2f * v;
    }
    __syncthreads();
    if (tid < L_) {
        float m = -1e30f;
        for (int j = 0; j < E; j++) if (sdst[j] == tid) m = fmaxf(m, ee[j]);
        float s = 0.f;
        float acc[64];
        #pragma unroll
        for (int f = 0; f < 64; f++) acc[f] = 0.f;
        for (int j = 0; j < E; j++) if (sdst[j] == tid) {
            float w = expf(ee[j] - m); s += w;
            const float* hs = &h2[ssrc[j] * 64];
            #pragma unroll
            for (int f = 0; f < 64; f++) acc[f] += w * hs[f];
        }
        float inv = 1.f / s;
        size_t base = (size_t)g * (L_ * 64) + tid * 64;
        #pragma unroll
        for (int f = 0; f < 64; f++) {
            float v = acc[f] * inv + b2[f];
            v = v > 0.f ? v : 0.f;
            split_write(v, oh, ol, base + f);
        }
    }
}

// =====================================================================
// split-bf16 tensor-core GEMM with pre-split operands + cp.async pipeline
// C[M,N] = (Ah+Al)[M,K] @ (Bh+Bl)[N,K]^T + bias  (3-MMA split product)
// flags: 1 relu, 2 +pe, 4 write fp32 C, 8 write split Ch/Cl
// =====================================================================
static const int TSTR = 40;     // smem row stride in bf16 elems (80B, conflict-free)
static const int GEMM_SMEM = 2 * 4 * 128 * TSTR * 2;  // 81920 B

__device__ __forceinline__ void ldsm4(uint32_t& r0, uint32_t& r1, uint32_t& r2, uint32_t& r3,
                                      const __nv_bfloat16* p) {
    uint32_t addr = (uint32_t)__cvta_generic_to_shared(p);
    asm volatile("ldmatrix.sync.aligned.m8n8.x4.shared.b16 {%0,%1,%2,%3}, [%4];\n"
                 : "=r"(r0), "=r"(r1), "=r"(r2), "=r"(r3) : "r"(addr));
}

__device__ __forceinline__ void mma16816(float* c, const uint32_t* a, uint32_t b0, uint32_t b1) {
    asm volatile("mma.sync.aligned.m16n8k16.row.col.f32.bf16.bf16.f32 "
                 "{%0,%1,%2,%3}, {%4,%5,%6,%7}, {%8,%9}, {%0,%1,%2,%3};\n"
                 : "+f"(c[0]), "+f"(c[1]), "+f"(c[2]), "+f"(c[3])
                 : "r"(a[0]), "r"(a[1]), "r"(a[2]), "r"(a[3]), "r"(b0), "r"(b1));
}

__device__ __forceinline__ void cp16(__nv_bfloat16* dst, const __nv_bfloat16* src) {
    uint32_t d = (uint32_t)__cvta_generic_to_shared(dst);
    asm volatile("cp.async.ca.shared.global [%0], [%1], 16;\n" :: "r"(d), "l"(src));
}

__global__ __launch_bounds__(256) void gemm_split(
    const __nv_bfloat16* __restrict__ Ah, const __nv_bfloat16* __restrict__ Al,
    const __nv_bfloat16* __restrict__ Bh, const __nv_bfloat16* __restrict__ Bl,
    const float* __restrict__ bias, float* __restrict__ C,
    __nv_bfloat16* __restrict__ Ch, __nv_bfloat16* __restrict__ Cl,
    int M, int N, int K, int flags, const float* __restrict__ pe)
{
    extern __shared__ __nv_bfloat16 smb[];   // [2 stages][4 planes][128*TSTR]

    const int tid  = threadIdx.x;
    const int lane = tid & 31, warp = tid >> 5;
    const int wm = warp & 1, wn = warp >> 1;
    const int bm = blockIdx.y, bn = blockIdx.x;

    const __nv_bfloat16* srcs[4];
    srcs[0] = Ah + (size_t)(bm * 128) * K;
    srcs[1] = Al + (size_t)(bm * 128) * K;
    srcs[2] = Bh + (size_t)(bn * 128) * K;
    srcs[3] = Bl + (size_t)(bn * 128) * K;

    const int row0 = tid >> 2;         // load row for i=0
    const int q0v  = (tid & 3) * 8;    // k offset within tile

    // issue one 128x32 tile per plane into stage st
    auto issue = [&](int st, int k0) {
        __nv_bfloat16* stbase = smb + (size_t)st * 4 * 128 * TSTR;
        #pragma unroll
        for (int p = 0; p < 4; p++) {
            __nv_bfloat16* pl = stbase + p * 128 * TSTR;
            #pragma unroll
            for (int i = 0; i < 2; i++) {
                int row = row0 + i * 64;
                cp16(pl + row * TSTR + q0v, srcs[p] + (size_t)row * K + k0 + q0v);
            }
        }
        asm volatile("cp.async.commit_group;\n");
    };

    float c[4][4][4];
    #pragma unroll
    for (int i = 0; i < 4; i++)
        #pragma unroll
        for (int j = 0; j < 4; j++)
            #pragma unroll
            for (int q = 0; q < 4; q++) c[i][j][q] = 0.f;

    issue(0, 0);
    asm volatile("cp.async.wait_group 0;\n");
    __syncthreads();

    const int KT = K / 32;
    int cur = 0;
    for (int kt = 0; kt < KT; kt++) {
        if (kt + 1 < KT) issue(cur ^ 1, (kt + 1) * 32);

        const __nv_bfloat16* pAh = smb + (size_t)cur * 4 * 128 * TSTR;
        const __nv_bfloat16* pAl = pAh + 128 * TSTR;
        const __nv_bfloat16* pBh = pAl + 128 * TSTR;
        const __nv_bfloat16* pBl = pBh + 128 * TSTR;

        #pragma unroll
        for (int kh = 0; kh < 2; kh++) {
            const int r  = lane & 15;
            const int cc = kh * 16 + ((lane >> 4) << 3);
            uint32_t ah[4][4], al[4][4], bhr[2][4], blr[2][4];
            #pragma unroll
            for (int mt = 0; mt < 4; mt++) {
                int row = wm * 64 + mt * 16 + r;
                ldsm4(ah[mt][0], ah[mt][1], ah[mt][2], ah[mt][3], pAh + row * TSTR + cc);
                ldsm4(al[mt][0], al[mt][1], al[mt][2], al[mt][3], pAl + row * TSTR + cc);
            }
            #pragma unroll
            for (int g = 0; g < 2; g++) {
                int row = wn * 32 + g * 16 + r;
                ldsm4(bhr[g][0], bhr[g][1], bhr[g][2], bhr[g][3], pBh + row * TSTR + cc);
                ldsm4(blr[g][0], blr[g][1], blr[g][2], blr[g][3], pBl + row * TSTR + cc);
            }
            #pragma unroll
            for (int mt = 0; mt < 4; mt++) {
                #pragma unroll
                for (int nt = 0; nt < 4; nt++) {
                    const int g = nt >> 1, s = nt & 1;
                    mma16816(c[mt][nt], ah[mt], bhr[g][s], bhr[g][s + 2]);
                    mma16816(c[mt][nt], ah[mt], blr[g][s], blr[g][s + 2]);
                    mma16816(c[mt][nt], al[mt], bhr[g][s], bhr[g][s + 2]);
                }
            }
        }

        if (kt + 1 < KT) {
            asm volatile("cp.async.wait_group 0;\n");
        }
        __syncthreads();
        cur ^= 1;
    }

    // epilogue
    #pragma unroll
    for (int mt = 0; mt < 4; mt++) {
        const int mbase = bm * 128 + wm * 64 + mt * 16 + (lane >> 2);
        #pragma unroll
        for (int half = 0; half < 2; half++) {
            const int m = mbase + half * 8;
            const size_t rowoff = (size_t)m * N;
            const float* perow = (flags & 2) ? (pe + (size_t)(m & (S_ - 1)) * DM) : nullptr;
            #pragma unroll
            for (int nt = 0; nt < 4; nt++) {
                const int n = bn * 128 + wn * 32 + nt * 8 + (lane & 3) * 2;
                float v0 = c[mt][nt][half * 2 + 0] + bias[n];
                float v1 = c[mt][nt][half * 2 + 1] + bias[n + 1];
                if (flags & 1) { v0 = fmaxf(v0, 0.f); v1 = fmaxf(v1, 0.f); }
                if (flags & 2) { v0 += perow[n]; v1 += perow[n + 1]; }
                if (flags & 4) {
                    float2 o; o.x = v0; o.y = v1;
                    *(float2*)(C + rowoff + n) = o;
                }
                if (flags & 8) {
                    __nv_bfloat16 h0 = __float2bfloat16(v0);
                    __nv_bfloat16 h1 = __float2bfloat16(v1);
                    __nv_bfloat162 hh; hh.x = h0; hh.y = h1;
                    __nv_bfloat162 ll;
                    ll.x = __float2bfloat16(v0 - __bfloat162float(h0));
                    ll.y = __float2bfloat16(v1 - __bfloat162float(h1));
                    *(__nv_bfloat162*)(Ch + rowoff + n) = hh;
                    *(__nv_bfloat162*)(Cl + rowoff + n) = ll;
                }
            }
        }
    }
}

// =====================================================================
// Attention: one block per (b, h, q-chunk of 64); writes split bf16
// =====================================================================
static const int KV_STRIDE = 69;
static const int ATTN_SMEM = (256 * KV_STRIDE * 2 + 64 * KV_STRIDE + 64 * 256) * 4;

__global__ __launch_bounds__(256) void attn_kernel(
    const float* __restrict__ qkv,
    __nv_bfloat16* __restrict__ oh, __nv_bfloat16* __restrict__ ol)
{
    extern __shared__ float sm[];
    float* Ks = sm;
    float* Vs = Ks + 256 * KV_STRIDE;
    float* Qs = Vs + 256 * KV_STRIDE;
    float* Ss = Qs + 64 * KV_STRIDE;

    const int bh = blockIdx.x;
    const int b = bh >> 3, hd = bh & 7;
    const int q0 = blockIdx.y * 64;
    const int tid = threadIdx.x;

    const float* base = qkv + (size_t)b * S_ * (3 * DM) + hd * DH;

    for (int i = tid; i < 256 * 64; i += 256) {
        int r = i >> 6, c = i & 63;
        Ks[r * KV_STRIDE + c] = base[(size_t)r * (3 * DM) + DM + c];
        Vs[r * KV_STRIDE + c] = base[(size_t)r * (3 * DM) + 2 * DM + c];
    }
    for (int i = tid; i < 64 * 64; i += 256) {
        int r = i >> 6, c = i & 63;
        Qs[r * KV_STRIDE + c] = base[(size_t)(q0 + r) * (3 * DM) + c];
    }
    __syncthreads();

    for (int qi = 0; qi < 64; qi++) {
        const float* qr = &Qs[qi * KV_STRIDE];
        const float* kr = &Ks[tid * KV_STRIDE];
        float a = 0.f;
        #pragma unroll
        for (int c = 0; c < 64; c++) a = fmaf(qr[c], kr[c], a);
        Ss[qi * 256 + tid] = a * 0.125f;
    }
    __syncthreads();

    const int wid = tid >> 5, lane = tid & 31;
    for (int r = wid; r < 64; r += 8) {
        float* row = &Ss[r * 256];
        float mx = -1e30f;
        for (int t = lane; t < 256; t += 32) mx = fmaxf(mx, row[t]);
        #pragma unroll
        for (int off = 16; off; off >>= 1) mx = fmaxf(mx, __shfl_xor_sync(0xffffffffu, mx, off));
        float s = 0.f;
        for (int t = lane; t < 256; t += 32) { float e = expf(row[t] - mx); row[t] = e; s += e; }
        #pragma unroll
        for (int off = 16; off; off >>= 1) s += __shfl_xor_sync(0xffffffffu, s, off);
        float inv = 1.f / s;
        for (int t = lane; t < 256; t += 32) row[t] *= inv;
    }
    __syncthreads();

    for (int i = tid; i < 64 * 64; i += 256) {
        int qi = i >> 6, c = i & 63;
        const float* srow = &Ss[qi * 256];
        float a = 0.f;
        #pragma unroll 8
        for (int t = 0; t < 256; t++) a = fmaf(srow[t], Vs[t * KV_STRIDE + c], a);
        size_t idx = ((size_t)b * S_ + q0 + qi) * DM + hd * DH + c;
        split_write(a, oh, ol, idx);
    }
}

// =====================================================================
// Residual + LayerNorm; writes fp32 out + split bf16
// =====================================================================
__global__ __launch_bounds__(128) void ln_kernel(
    const float* __restrict__ x, const float* __restrict__ r,
    const float* __restrict__ gam, const float* __restrict__ bet,
    float* __restrict__ out,
    __nv_bfloat16* __restrict__ oh, __nv_bfloat16* __restrict__ ol)
{
    const int row = blockIdx.x, tid = threadIdx.x;
    const float* xr = x + (size_t)row * DM;
    const float* rr = r + (size_t)row * DM;
    float v[4];
    float s = 0.f, s2 = 0.f;
    #pragma unroll
    for (int u = 0; u < 4; u++) {
        int i = tid + u * 128;
        v[u] = xr[i] + rr[i];
        s += v[u]; s2 += v[u] * v[u];
    }
    __shared__ float rs[4], rs2[4];
    #pragma unroll
    for (int off = 16; off; off >>= 1) {
        s  += __shfl_xor_sync(0xffffffffu, s,  off);
        s2 += __shfl_xor_sync(0xffffffffu, s2, off);
    }
    if ((tid & 31) == 0) { rs[tid >> 5] = s; rs2[tid >> 5] = s2; }
    __syncthreads();
    s  = rs[0] + rs[1] + rs[2] + rs[3];
    s2 = rs2[0] + rs2[1] + rs2[2] + rs2[3];
    float mean = s * (1.f / DM);
    float var  = s2 * (1.f / DM) - mean * mean;
    float k = rsqrtf(var + 1e-5f);
    float* orow = out + (size_t)row * DM;
    #pragma unroll
    for (int u = 0; u < 4; u++) {
        int i = tid + u * 128;
        float o = (v[u] - mean) * k * gam[i] + bet[i];
        orow[i] = o;
        split_write(o, oh, ol, (size_t)row * DM + i);
    }
}

// =====================================================================
// host launcher
// =====================================================================
static void run_gemm(const __nv_bfloat16* Ah, const __nv_bfloat16* Al,
                     const __nv_bfloat16* Bh, const __nv_bfloat16* Bl,
                     const float* bias, float* C,
                     __nv_bfloat16* Ch, __nv_bfloat16* Cl,
                     int M, int N, int K, int flags, const float* pe) {
    dim3 grid(N / 128, M / 128);
    gemm_split<<<grid, 256, GEMM_SMEM>>>(Ah, Al, Bh, Bl, bias, C, Ch, Cl, M, N, K, flags, pe);
}

extern "C" void kernel_launch(void* const* d_in, const int* in_sizes, int n_in,
                              void* d_out, int out_size)
{
    const float* lm    = (const float*)d_in[0];
    const int*   ei    = (const int*)  d_in[1];
    const int    E     = in_sizes[1] / 2;
    const float* g1w   = (const float*)d_in[2];
    const float* g1as  = (const float*)d_in[3];
    const float* g1ad  = (const float*)d_in[4];
    const float* g1b   = (const float*)d_in[5];
    const float* g2w   = (const float*)d_in[6];
    const float* g2as  = (const float*)d_in[7];
    const float* g2ad  = (const float*)d_in[8];
    const float* g2b   = (const float*)d_in[9];
    const float* fcw   = (const float*)d_in[10];
    const float* fcb   = (const float*)d_in[11];
    const float* pe    = (const float*)d_in[12];
    const float* ipw   = (const float*)d_in[13];
    const float* ipb   = (const float*)d_in[14];
    const float* opw   = (const float*)d_in[15];
    const float* opb   = (const float*)d_in[16];
    const float* ln1g  = (const float*)d_in[17];
    const float* ln1b  = (const float*)d_in[18];
    const float* fw1   = (const float*)d_in[19];
    const float* fb1   = (const float*)d_in[20];
    const float* fw2   = (const float*)d_in[21];
    const float* fb2   = (const float*)d_in[22];
    const float* ln2g  = (const float*)d_in[23];
    const float* ln2b  = (const float*)d_in[24];

    __nv_bfloat16 *wh, *wl, *ghh, *ghl, *gxh, *gxl, *ath, *atl, *ffh, *ffl;
    float *gx, *gqkv, *gproj;
    cudaGetSymbolAddress((void**)&wh,   w_h);
    cudaGetSymbolAddress((void**)&wl,   w_l);
    cudaGetSymbolAddress((void**)&ghh,  gh_h);
    cudaGetSymbolAddress((void**)&ghl,  gh_l);
    cudaGetSymbolAddress((void**)&gxh,  gx_h);
    cudaGetSymbolAddress((void**)&gxl,  gx_l);
    cudaGetSymbolAddress((void**)&ath,  at_h);
    cudaGetSymbolAddress((void**)&atl,  at_l);
    cudaGetSymbolAddress((void**)&ffh,  ff_h);
    cudaGetSymbolAddress((void**)&ffl,  ff_l);
    cudaGetSymbolAddress((void**)&gx,   g_x);
    cudaGetSymbolAddress((void**)&gqkv, g_qkv);
    cudaGetSymbolAddress((void**)&gproj,g_proj);

    cudaFuncSetAttribute(attn_kernel, cudaFuncAttributeMaxDynamicSharedMemorySize, ATTN_SMEM);
    cudaFuncSetAttribute(gemm_split,  cudaFuncAttributeMaxDynamicSharedMemorySize, GEMM_SMEM);

    // 0. weight pre-split (once per launch, captured in graph)
    split_kernel<<<2048, 256>>>(fcw, wh + OFF_FC, wl + OFF_FC, 512 * 4352);
    split_kernel<<<2048, 256>>>(ipw, wh + OFF_IP, wl + OFF_IP, NL * 3 * DM * DM);
    split_kernel<<<2048, 256>>>(opw, wh + OFF_OP, wl + OFF_OP, NL * DM * DM);
    split_kernel<<<2048, 256>>>(fw1, wh + OFF_F1, wl + OFF_F1, NL * DFF * DM);
    split_kernel<<<2048, 256>>>(fw2, wh + OFF_F2, wl + OFF_F2, NL * DM * DFF);

    // 1. GAT frontend -> split bf16
    gat_kernel<<<G_, 128>>>(lm, ei, E, g1w, g1as, g1ad, g1b,
                            g2w, g2as, g2ad, g2b, ghh, ghl);

    // 2. FC + positional encoding -> fp32 gx + split
    run_gemm(ghh, ghl, wh + OFF_FC, wl + OFF_FC, fcb, gx, gxh, gxl,
             G_, DM, L_ * 64, /*pe|f32|split*/ 2 | 4 | 8, pe);

    // 3. transformer encoder layers
    for (int l = 0; l < NL; l++) {
        run_gemm(gxh, gxl, wh + OFF_IP + (size_t)l * 3 * DM * DM, wl + OFF_IP + (size_t)l * 3 * DM * DM,
                 ipb + (size_t)l * 3 * DM, gqkv, nullptr, nullptr,
                 G_, 3 * DM, DM, /*f32*/ 4, nullptr);
        attn_kernel<<<dim3(B_ * NH, S_ / 64), 256, ATTN_SMEM>>>(gqkv, ath, atl);
        run_gemm(ath, atl, wh + OFF_OP + (size_t)l * DM * DM, wl + OFF_OP + (size_t)l * DM * DM,
                 opb + (size_t)l * DM, gproj, nullptr, nullptr,
                 G_, DM, DM, 4, nullptr);
        ln_kernel<<<G_, 128>>>(gx, gproj, ln1g + (size_t)l * DM, ln1b + (size_t)l * DM,
                               gx, gxh, gxl);

        run_gemm(gxh, gxl, wh + OFF_F1 + (size_t)l * DFF * DM, wl + OFF_F1 + (size_t)l * DFF * DM,
                 fb1 + (size_t)l * DFF, nullptr, ffh, ffl,
                 G_, DFF, DM, /*relu|split*/ 1 | 8, nullptr);
        run_gemm(ffh, ffl, wh + OFF_F2 + (size_t)l * DM * DFF, wl + OFF_F2 + (size_t)l * DM * DFF,
                 fb2 + (size_t)l * DM, gproj, nullptr, nullptr,
                 G_, DM, DFF, 4, nullptr);
        float* outp = (l == NL - 1) ? (float*)d_out : gx;
        ln_kernel<<<G_, 128>>>(gx, gproj, ln2g + (size_t)l * DM, ln2b + (size_t)l * DM,
                               outp, gxh, gxl);
    }
    (void)n_in; (void)out_size;
}

// round 8
// speedup vs baseline: 2.3303x; 1.1749x over previous
#include <cuda_runtime.h>
#include <cuda_bf16.h>
#include <math.h>
#include <stdint.h>

// ---------------- problem constants ----------------
static const int B_  = 8;
static const int S_  = 256;
static const int G_  = 2048;
static const int L_  = 68;
static const int DM  = 512;
static const int NH  = 8;
static const int DH  = 64;
static const int DFF = 2048;
static const int NL  = 6;
static const int MAXE = 512;

// weight offsets in the packed split-weight buffers
static const size_t OFF_FC = 0;                    // 512*4352
static const size_t OFF_IP = 2228224;              // 6*1536*512
static const size_t OFF_OP = 6946816;              // 6*512*512
static const size_t OFF_F1 = 8519680;              // 6*2048*512
static const size_t OFF_F2 = 14811136;             // 6*512*2048
static const size_t W_TOT  = 21102592;

// ---------------- scratch (static device memory) ----------------
__device__ __nv_bfloat16 w_h[W_TOT], w_l[W_TOT];
__device__ __nv_bfloat16 gh_h[G_ * L_ * 64], gh_l[G_ * L_ * 64];
__device__ __nv_bfloat16 gx_h[G_ * DM],      gx_l[G_ * DM];
__device__ __nv_bfloat16 at_h[G_ * DM],      at_l[G_ * DM];
__device__ __nv_bfloat16 ff_h[G_ * DFF],     ff_l[G_ * DFF];
__device__ __nv_bfloat16 qk_h[G_ * 3 * DM],  qk_l[G_ * 3 * DM];
__device__ float g_x   [G_ * DM];
__device__ float g_proj[G_ * DM];

// ---------------- helpers ----------------
__device__ __forceinline__ void split_write(float v, __nv_bfloat16* hi, __nv_bfloat16* lo, size_t i) {
    __nv_bfloat16 h = __float2bfloat16(v);
    hi[i] = h;
    lo[i] = __float2bfloat16(v - __bfloat162float(h));
}

// =====================================================================
// weight split kernel (grid-stride)
// =====================================================================
__global__ __launch_bounds__(256) void split_kernel(
    const float* __restrict__ src, __nv_bfloat16* __restrict__ hi,
    __nv_bfloat16* __restrict__ lo, int n)
{
    int i = blockIdx.x * blockDim.x + threadIdx.x;
    int stride = gridDim.x * blockDim.x;
    for (; i < n; i += stride) {
        float v = src[i];
        __nv_bfloat16 h = __float2bfloat16(v);
        hi[i] = h;
        lo[i] = __float2bfloat16(v - __bfloat162float(h));
    }
}

// =====================================================================
// GAT: both layers fused, one block per graph; writes split bf16
// =====================================================================
__global__ __launch_bounds__(128) void gat_kernel(
    const float* __restrict__ lm, const int* __restrict__ ei, int E,
    const float* __restrict__ w1, const float* __restrict__ as1,
    const float* __restrict__ ad1, const float* __restrict__ b1,
    const float* __restrict__ w2, const float* __restrict__ as2,
    const float* __restrict__ ad2, const float* __restrict__ b2,
    __nv_bfloat16* __restrict__ oh, __nv_bfloat16* __restrict__ ol)
{
    __shared__ float h1[L_ * 16];
    __shared__ float x2[L_ * 16];
    __shared__ float h2[L_ * 64];
    __shared__ float sa[L_], sd[L_];
    __shared__ float ee[MAXE];
    __shared__ int   ssrc[MAXE], sdst[MAXE];

    const int g   = blockIdx.x;
    const int tid = threadIdx.x;
    const float* x = lm + (size_t)g * L_ * 2;

    for (int j = tid; j < E; j += blockDim.x) { ssrc[j] = ei[j]; sdst[j] = ei[E + j]; }

    for (int i = tid; i < L_ * 16; i += blockDim.x) {
        int l = i >> 4, f = i & 15;
        h1[i] = w1[f * 2 + 0] * x[l * 2 + 0] + w1[f * 2 + 1] * x[l * 2 + 1];
    }
    __syncthreads();
    if (tid < L_) {
        float a = 0.f, d = 0.f;
        #pragma unroll
        for (int f = 0; f < 16; f++) { a += h1[tid * 16 + f] * as1[f]; d += h1[tid * 16 + f] * ad1[f]; }
        sa[tid] = a; sd[tid] = d;
    }
    __syncthreads();
    for (int j = tid; j < E; j += blockDim.x) {
        float v = sa[ssrc[j]] + sd[sdst[j]];
        ee[j] = v > 0.f ? v : 0.2f * v;
    }
    __syncthreads();
    if (tid < L_) {
        float m = -1e30f;
        for (int j = 0; j < E; j++) if (sdst[j] == tid) m = fmaxf(m, ee[j]);
        float s = 0.f;
        float acc[16];
        #pragma unroll
        for (int f = 0; f < 16; f++) acc[f] = 0.f;
        for (int j = 0; j < E; j++) if (sdst[j] == tid) {
            float w = expf(ee[j] - m); s += w;
            const float* hs = &h1[ssrc[j] * 16];
            #pragma unroll
            for (int f = 0; f < 16; f++) acc[f] += w * hs[f];
        }
        float inv = 1.f / s;
        #pragma unroll
        for (int f = 0; f < 16; f++) {
            float v = acc[f] * inv + b1[f];
            x2[tid * 16 + f] = v > 0.f ? v : 0.f;
        }
    }
    __syncthreads();

    for (int i = tid; i < L_ * 64; i += blockDim.x) {
        int l = i >> 6, f = i & 63;
        float a = 0.f;
        const float* xr = &x2[l * 16];
        const float* wr = &w2[f * 16];
        #pragma unroll
        for (int c = 0; c < 16; c++) a += xr[c] * wr[c];
        h2[i] = a;
    }
    __syncthreads();
    if (tid < L_) {
        float a = 0.f, d = 0.f;
        const float* hr = &h2[tid * 64];
        #pragma unroll
        for (int f = 0; f < 64; f++) { a += hr[f] * as2[f]; d += hr[f] * ad2[f]; }
        sa[tid] = a; sd[tid] = d;
    }
    __syncthreads();
    for (int j = tid; j < E; j += blockDim.x) {
        float v = sa[ssrc[j]] + sd[sdst[j]];
        ee[j] = v > 0.f ? v : 0.2f * v;
    }
    __syncthreads();
    if (tid < L_) {
        float m = -1e30f;
        for (int j = 0; j < E; j++) if (sdst[j] == tid) m = fmaxf(m, ee[j]);
        float s = 0.f;
        float acc[64];
        #pragma unroll
        for (int f = 0; f < 64; f++) acc[f] = 0.f;
        for (int j = 0; j < E; j++) if (sdst[j] == tid) {
            float w = expf(ee[j] - m); s += w;
            const float* hs = &h2[ssrc[j] * 64];
            #pragma unroll
            for (int f = 0; f < 64; f++) acc[f] += w * hs[f];
        }
        float inv = 1.f / s;
        size_t base = (size_t)g * (L_ * 64) + tid * 64;
        #pragma unroll
        for (int f = 0; f < 64; f++) {
            float v = acc[f] * inv + b2[f];
            v = v > 0.f ? v : 0.f;
            split_write(v, oh, ol, base + f);
        }
    }
}

// =====================================================================
// mma helpers
// =====================================================================
__device__ __forceinline__ void ldsm4(uint32_t& r0, uint32_t& r1, uint32_t& r2, uint32_t& r3,
                                      const __nv_bfloat16* p) {
    uint32_t addr = (uint32_t)__cvta_generic_to_shared(p);
    asm volatile("ldmatrix.sync.aligned.m8n8.x4.shared.b16 {%0,%1,%2,%3}, [%4];\n"
                 : "=r"(r0), "=r"(r1), "=r"(r2), "=r"(r3) : "r"(addr));
}

__device__ __forceinline__ void ldsm4t(uint32_t& r0, uint32_t& r1, uint32_t& r2, uint32_t& r3,
                                       const __nv_bfloat16* p) {
    uint32_t addr = (uint32_t)__cvta_generic_to_shared(p);
    asm volatile("ldmatrix.sync.aligned.m8n8.x4.trans.shared.b16 {%0,%1,%2,%3}, [%4];\n"
                 : "=r"(r0), "=r"(r1), "=r"(r2), "=r"(r3) : "r"(addr));
}

__device__ __forceinline__ void mma16816(float* c, const uint32_t* a, uint32_t b0, uint32_t b1) {
    asm volatile("mma.sync.aligned.m16n8k16.row.col.f32.bf16.bf16.f32 "
                 "{%0,%1,%2,%3}, {%4,%5,%6,%7}, {%8,%9}, {%0,%1,%2,%3};\n"
                 : "+f"(c[0]), "+f"(c[1]), "+f"(c[2]), "+f"(c[3])
                 : "r"(a[0]), "r"(a[1]), "r"(a[2]), "r"(a[3]), "r"(b0), "r"(b1));
}

__device__ __forceinline__ void cp16(uint32_t dst, const void* src) {
    asm volatile("cp.async.ca.shared.global [%0], [%1], 16;" :: "r"(dst), "l"(src));
}

// =====================================================================
// split-bf16 tensor-core GEMM (R5, known good)
// flags: 1 relu, 2 +pe, 4 write fp32 C, 8 write split Ch/Cl
// =====================================================================
static const int TSTR = 40;
static const int GEMM_SMEM = 2 * 4 * 128 * TSTR * 2;  // 81920 B

__global__ __launch_bounds__(256) void gemm_split(
    const __nv_bfloat16* __restrict__ Ah, const __nv_bfloat16* __restrict__ Al,
    const __nv_bfloat16* __restrict__ Bh, const __nv_bfloat16* __restrict__ Bl,
    const float* __restrict__ bias, float* __restrict__ C,
    __nv_bfloat16* __restrict__ Ch, __nv_bfloat16* __restrict__ Cl,
    int M, int N, int K, int flags, const float* __restrict__ pe)
{
    extern __shared__ __nv_bfloat16 smb[];

    const int tid  = threadIdx.x;
    const int lane = tid & 31, warp = tid >> 5;
    const int wm = warp & 1, wn = warp >> 1;
    const int bm = blockIdx.y, bn = blockIdx.x;

    const __nv_bfloat16* srcs[4];
    srcs[0] = Ah + (size_t)(bm * 128) * K;
    srcs[1] = Al + (size_t)(bm * 128) * K;
    srcs[2] = Bh + (size_t)(bn * 128) * K;
    srcs[3] = Bl + (size_t)(bn * 128) * K;

    const int row0 = tid >> 2;
    const int q0v  = (tid & 3) * 8;

    auto issue = [&](int st, int k0) {
        __nv_bfloat16* stbase = smb + (size_t)st * 4 * 128 * TSTR;
        #pragma unroll
        for (int p = 0; p < 4; p++) {
            __nv_bfloat16* pl = stbase + p * 128 * TSTR;
            #pragma unroll
            for (int i = 0; i < 2; i++) {
                int row = row0 + i * 64;
                cp16((uint32_t)__cvta_generic_to_shared(pl + row * TSTR + q0v),
                     srcs[p] + (size_t)row * K + k0 + q0v);
            }
        }
        asm volatile("cp.async.commit_group;\n");
    };

    float c[4][4][4];
    #pragma unroll
    for (int i = 0; i < 4; i++)
        #pragma unroll
        for (int j = 0; j < 4; j++)
            #pragma unroll
            for (int q = 0; q < 4; q++) c[i][j][q] = 0.f;

    issue(0, 0);
    asm volatile("cp.async.wait_group 0;\n");
    __syncthreads();

    const int KT = K / 32;
    int cur = 0;
    for (int kt = 0; kt < KT; kt++) {
        if (kt + 1 < KT) issue(cur ^ 1, (kt + 1) * 32);

        const __nv_bfloat16* pAh = smb + (size_t)cur * 4 * 128 * TSTR;
        const __nv_bfloat16* pAl = pAh + 128 * TSTR;
        const __nv_bfloat16* pBh = pAl + 128 * TSTR;
        const __nv_bfloat16* pBl = pBh + 128 * TSTR;

        #pragma unroll
        for (int kh = 0; kh < 2; kh++) {
            const int r  = lane & 15;
            const int cc = kh * 16 + ((lane >> 4) << 3);
            uint32_t ah[4][4], al[4][4], bhr[2][4], blr[2][4];
            #pragma unroll
            for (int mt = 0; mt < 4; mt++) {
                int row = wm * 64 + mt * 16 + r;
                ldsm4(ah[mt][0], ah[mt][1], ah[mt][2], ah[mt][3], pAh + row * TSTR + cc);
                ldsm4(al[mt][0], al[mt][1], al[mt][2], al[mt][3], pAl + row * TSTR + cc);
            }
            #pragma unroll
            for (int g = 0; g < 2; g++) {
                int row = wn * 32 + g * 16 + r;
                ldsm4(bhr[g][0], bhr[g][1], bhr[g][2], bhr[g][3], pBh + row * TSTR + cc);
                ldsm4(blr[g][0], blr[g][1], blr[g][2], blr[g][3], pBl + row * TSTR + cc);
            }
            #pragma unroll
            for (int mt = 0; mt < 4; mt++) {
                #pragma unroll
                for (int nt = 0; nt < 4; nt++) {
                    const int g = nt >> 1, s = nt & 1;
                    mma16816(c[mt][nt], ah[mt], bhr[g][s], bhr[g][s + 2]);
                    mma16816(c[mt][nt], ah[mt], blr[g][s], blr[g][s + 2]);
                    mma16816(c[mt][nt], al[mt], bhr[g][s], bhr[g][s + 2]);
                }
            }
        }

        if (kt + 1 < KT) {
            asm volatile("cp.async.wait_group 0;\n");
        }
        __syncthreads();
        cur ^= 1;
    }

    #pragma unroll
    for (int mt = 0; mt < 4; mt++) {
        const int mbase = bm * 128 + wm * 64 + mt * 16 + (lane >> 2);
        #pragma unroll
        for (int half = 0; half < 2; half++) {
            const int m = mbase + half * 8;
            const size_t rowoff = (size_t)m * N;
            const float* perow = (flags & 2) ? (pe + (size_t)(m & (S_ - 1)) * DM) : nullptr;
            #pragma unroll
            for (int nt = 0; nt < 4; nt++) {
                const int n = bn * 128 + wn * 32 + nt * 8 + (lane & 3) * 2;
                float v0 = c[mt][nt][half * 2 + 0] + bias[n];
                float v1 = c[mt][nt][half * 2 + 1] + bias[n + 1];
                if (flags & 1) { v0 = fmaxf(v0, 0.f); v1 = fmaxf(v1, 0.f); }
                if (flags & 2) { v0 += perow[n]; v1 += perow[n + 1]; }
                if (flags & 4) {
                    float2 o; o.x = v0; o.y = v1;
                    *(float2*)(C + rowoff + n) = o;
                }
                if (flags & 8) {
                    __nv_bfloat16 h0 = __float2bfloat16(v0);
                    __nv_bfloat16 h1 = __float2bfloat16(v1);
                    __nv_bfloat162 hh; hh.x = h0; hh.y = h1;
                    __nv_bfloat162 ll;
                    ll.x = __float2bfloat16(v0 - __bfloat162float(h0));
                    ll.y = __float2bfloat16(v1 - __bfloat162float(h1));
                    *(__nv_bfloat162*)(Ch + rowoff + n) = hh;
                    *(__nv_bfloat162*)(Cl + rowoff + n) = ll;
                }
            }
        }
    }
}

// =====================================================================
// Tensor-core attention: block per (b, h, q-chunk 32), 8 warps.
// QK^T (split 3-term mma) -> fp32 smem softmax -> split S -> S@V (mma).
// =====================================================================
static const int KSTR = 72;    // K/V/Q smem stride (bf16)
static const int SSTR = 264;   // S smem stride
// byte offsets
static const int OF_KH = 0;
static const int OF_KL = OF_KH + 256 * KSTR * 2;     // 36864
static const int OF_VH = OF_KL + 256 * KSTR * 2;
static const int OF_VL = OF_VH + 256 * KSTR * 2;
static const int OF_QH = OF_VL + 256 * KSTR * 2;     // 147456
static const int OF_QL = OF_QH + 32 * KSTR * 2;      // +4608
static const int OF_SH = OF_QL + 32 * KSTR * 2;
static const int OF_SL = OF_SH + 32 * SSTR * 2;      // +16896
static const int OF_SF = OF_SL + 32 * SSTR * 2;
static const int ATTN_SMEM = OF_SF + 32 * SSTR * 4;  // 224256

__global__ __launch_bounds__(256) void attn_mma(
    const __nv_bfloat16* __restrict__ qh, const __nv_bfloat16* __restrict__ ql,
    __nv_bfloat16* __restrict__ oh, __nv_bfloat16* __restrict__ ol)
{
    extern __shared__ __align__(16) char smc[];
    __nv_bfloat16* Kh = (__nv_bfloat16*)(smc + OF_KH);
    __nv_bfloat16* Kl = (__nv_bfloat16*)(smc + OF_KL);
    __nv_bfloat16* Vh = (__nv_bfloat16*)(smc + OF_VH);
    __nv_bfloat16* Vl = (__nv_bfloat16*)(smc + OF_VL);
    __nv_bfloat16* Qh = (__nv_bfloat16*)(smc + OF_QH);
    __nv_bfloat16* Ql = (__nv_bfloat16*)(smc + OF_QL);
    __nv_bfloat16* Sh = (__nv_bfloat16*)(smc + OF_SH);
    __nv_bfloat16* Sl = (__nv_bfloat16*)(smc + OF_SL);
    float*         Sf = (float*)(smc + OF_SF);

    const int bh  = blockIdx.x;
    const int b   = bh >> 3, hd = bh & 7;
    const int q0  = blockIdx.y * 32;
    const int tid = threadIdx.x;
    const int lane = tid & 31, warp = tid >> 5;

    // -------- load K/V/Q hi+lo planes (uint4 = 8 bf16) --------
    const size_t rowK = (size_t)b * S_ * (3 * DM) + hd * DH;
    {
        for (int i = tid; i < 256 * 8; i += 256) {
            int r = i >> 3, cc = (i & 7) * 8;
            size_t g = rowK + (size_t)r * (3 * DM);
            *(uint4*)&Kh[r * KSTR + cc] = *(const uint4*)(qh + g + DM + cc);
            *(uint4*)&Kl[r * KSTR + cc] = *(const uint4*)(ql + g + DM + cc);
            *(uint4*)&Vh[r * KSTR + cc] = *(const uint4*)(qh + g + 2 * DM + cc);
            *(uint4*)&Vl[r * KSTR + cc] = *(const uint4*)(ql + g + 2 * DM + cc);
        }
        for (int i = tid; i < 32 * 8; i += 256) {
            int r = i >> 3, cc = (i & 7) * 8;
            size_t g = rowK + (size_t)(q0 + r) * (3 * DM);
            *(uint4*)&Qh[r * KSTR + cc] = *(const uint4*)(qh + g + cc);
            *(uint4*)&Ql[r * KSTR + cc] = *(const uint4*)(ql + g + cc);
        }
    }
    __syncthreads();

    // -------- QK^T: warp wm (2) x wn (4); q 16 rows, keys 64 --------
    const int wm = warp & 1, wn = warp >> 1;
    {
        float c[8][4];
        #pragma unroll
        for (int t = 0; t < 8; t++)
            #pragma unroll
            for (int q = 0; q < 4; q++) c[t][q] = 0.f;

        const int r  = lane & 15;
        const int c8 = (lane >> 4) << 3;
        #pragma unroll
        for (int k0 = 0; k0 < 64; k0 += 16) {
            uint32_t aqh[4], aql[4];
            ldsm4(aqh[0], aqh[1], aqh[2], aqh[3], Qh + (wm * 16 + r) * KSTR + k0 + c8);
            ldsm4(aql[0], aql[1], aql[2], aql[3], Ql + (wm * 16 + r) * KSTR + k0 + c8);
            #pragma unroll
            for (int j = 0; j < 4; j++) {
                uint32_t bkh[4], bkl[4];
                const int key = wn * 64 + j * 16 + r;
                ldsm4(bkh[0], bkh[1], bkh[2], bkh[3], Kh + key * KSTR + k0 + c8);
                ldsm4(bkl[0], bkl[1], bkl[2], bkl[3], Kl + key * KSTR + k0 + c8);
                #pragma unroll
                for (int s = 0; s < 2; s++) {
                    mma16816(c[2 * j + s], aqh, bkh[s], bkh[s + 2]);
                    mma16816(c[2 * j + s], aqh, bkl[s], bkl[s + 2]);
                    mma16816(c[2 * j + s], aql, bkh[s], bkh[s + 2]);
                }
            }
        }
        const int row0 = wm * 16 + (lane >> 2);
        #pragma unroll
        for (int t = 0; t < 8; t++) {
            const int col = wn * 64 + t * 8 + (lane & 3) * 2;
            Sf[row0 * SSTR + col]           = c[t][0] * 0.125f;
            Sf[row0 * SSTR + col + 1]       = c[t][1] * 0.125f;
            Sf[(row0 + 8) * SSTR + col]     = c[t][2] * 0.125f;
            Sf[(row0 + 8) * SSTR + col + 1] = c[t][3] * 0.125f;
        }
    }
    __syncthreads();

    // -------- softmax over 256 keys per row; write split bf16 --------
    for (int rr = warp; rr < 32; rr += 8) {
        float* row = &Sf[rr * SSTR];
        float mx = -1e30f;
        #pragma unroll
        for (int t = lane; t < 256; t += 32) mx = fmaxf(mx, row[t]);
        #pragma unroll
        for (int off = 16; off; off >>= 1) mx = fmaxf(mx, __shfl_xor_sync(0xffffffffu, mx, off));
        float s = 0.f;
        float ev[8];
        #pragma unroll
        for (int u = 0; u < 8; u++) {
            ev[u] = expf(row[lane + u * 32] - mx);
            s += ev[u];
        }
        #pragma unroll
        for (int off = 16; off; off >>= 1) s += __shfl_xor_sync(0xffffffffu, s, off);
        float inv = 1.f / s;
        #pragma unroll
        for (int u = 0; u < 8; u++) {
            float v = ev[u] * inv;
            __nv_bfloat16 h = __float2bfloat16(v);
            Sh[rr * SSTR + lane + u * 32] = h;
            Sl[rr * SSTR + lane + u * 32] = __float2bfloat16(v - __bfloat162float(h));
        }
    }
    __syncthreads();

    // -------- S @ V: warp wm (2 q-halves) x wn (4 d-16 tiles) --------
    {
        float o[2][4];
        #pragma unroll
        for (int t = 0; t < 2; t++)
            #pragma unroll
            for (int q = 0; q < 4; q++) o[t][q] = 0.f;

        const int r  = lane & 15;
        const int c8 = (lane >> 4) << 3;
        #pragma unroll 4
        for (int k0 = 0; k0 < 256; k0 += 16) {
            uint32_t ash[4], asl[4];
            ldsm4(ash[0], ash[1], ash[2], ash[3], Sh + (wm * 16 + r) * SSTR + k0 + c8);
            ldsm4(asl[0], asl[1], asl[2], asl[3], Sl + (wm * 16 + r) * SSTR + k0 + c8);
            uint32_t bvh[4], bvl[4];
            ldsm4t(bvh[0], bvh[1], bvh[2], bvh[3], Vh + (k0 + r) * KSTR + wn * 16 + c8);
            ldsm4t(bvl[0], bvl[1], bvl[2], bvl[3], Vl + (k0 + r) * KSTR + wn * 16 + c8);
            #pragma unroll
            for (int t = 0; t < 2; t++) {
                mma16816(o[t], ash, bvh[2 * t], bvh[2 * t + 1]);
                mma16816(o[t], ash, bvl[2 * t], bvl[2 * t + 1]);
                mma16816(o[t], asl, bvh[2 * t], bvh[2 * t + 1]);
            }
        }
        const int row0 = q0 + wm * 16 + (lane >> 2);
        #pragma unroll
        for (int t = 0; t < 2; t++) {
            const int d = hd * DH + wn * 16 + t * 8 + (lane & 3) * 2;
            size_t i0 = ((size_t)b * S_ + row0) * DM + d;
            size_t i1 = ((size_t)b * S_ + row0 + 8) * DM + d;
            split_write(o[t][0], oh, ol, i0);
            split_write(o[t][1], oh, ol, i0 + 1);
            split_write(o[t][2], oh, ol, i1);
            split_write(o[t][3], oh, ol, i1 + 1);
        }
    }
}

// =====================================================================
// Residual + LayerNorm; writes fp32 out + split bf16
// =====================================================================
__global__ __launch_bounds__(128) void ln_kernel(
    const float* __restrict__ x, const float* __restrict__ r,
    const float* __restrict__ gam, const float* __restrict__ bet,
    float* __restrict__ out,
    __nv_bfloat16* __restrict__ oh, __nv_bfloat16* __restrict__ ol)
{
    const int row = blockIdx.x, tid = threadIdx.x;
    const float* xr = x + (size_t)row * DM;
    const float* rr = r + (size_t)row * DM;
    float v[4];
    float s = 0.f, s2 = 0.f;
    #pragma unroll
    for (int u = 0; u < 4; u++) {
        int i = tid + u * 128;
        v[u] = xr[i] + rr[i];
        s += v[u]; s2 += v[u] * v[u];
    }
    __shared__ float rs[4], rs2[4];
    #pragma unroll
    for (int off = 16; off; off >>= 1) {
        s  += __shfl_xor_sync(0xffffffffu, s,  off);
        s2 += __shfl_xor_sync(0xffffffffu, s2, off);
    }
    if ((tid & 31) == 0) { rs[tid >> 5] = s; rs2[tid >> 5] = s2; }
    __syncthreads();
    s  = rs[0] + rs[1] + rs[2] + rs[3];
    s2 = rs2[0] + rs2[1] + rs2[2] + rs2[3];
    float mean = s * (1.f / DM);
    float var  = s2 * (1.f / DM) - mean * mean;
    float k = rsqrtf(var + 1e-5f);
    float* orow = out + (size_t)row * DM;
    #pragma unroll
    for (int u = 0; u < 4; u++) {
        int i = tid + u * 128;
        float o = (v[u] - mean) * k * gam[i] + bet[i];
        orow[i] = o;
        split_write(o, oh, ol, (size_t)row * DM + i);
    }
}

// =====================================================================
// host launcher
// =====================================================================
static void run_gemm(const __nv_bfloat16* Ah, const __nv_bfloat16* Al,
                     const __nv_bfloat16* Bh, const __nv_bfloat16* Bl,
                     const float* bias, float* C,
                     __nv_bfloat16* Ch, __nv_bfloat16* Cl,
                     int M, int N, int K, int flags, const float* pe) {
    dim3 grid(N / 128, M / 128);
    gemm_split<<<grid, 256, GEMM_SMEM>>>(Ah, Al, Bh, Bl, bias, C, Ch, Cl, M, N, K, flags, pe);
}

extern "C" void kernel_launch(void* const* d_in, const int* in_sizes, int n_in,
                              void* d_out, int out_size)
{
    const float* lm    = (const float*)d_in[0];
    const int*   ei    = (const int*)  d_in[1];
    const int    E     = in_sizes[1] / 2;
    const float* g1w   = (const float*)d_in[2];
    const float* g1as  = (const float*)d_in[3];
    const float* g1ad  = (const float*)d_in[4];
    const float* g1b   = (const float*)d_in[5];
    const float* g2w   = (const float*)d_in[6];
    const float* g2as  = (const float*)d_in[7];
    const float* g2ad  = (const float*)d_in[8];
    const float* g2b   = (const float*)d_in[9];
    const float* fcw   = (const float*)d_in[10];
    const float* fcb   = (const float*)d_in[11];
    const float* pe    = (const float*)d_in[12];
    const float* ipw   = (const float*)d_in[13];
    const float* ipb   = (const float*)d_in[14];
    const float* opw   = (const float*)d_in[15];
    const float* opb   = (const float*)d_in[16];
    const float* ln1g  = (const float*)d_in[17];
    const float* ln1b  = (const float*)d_in[18];
    const float* fw1   = (const float*)d_in[19];
    const float* fb1   = (const float*)d_in[20];
    const float* fw2   = (const float*)d_in[21];
    const float* fb2   = (const float*)d_in[22];
    const float* ln2g  = (const float*)d_in[23];
    const float* ln2b  = (const float*)d_in[24];

    __nv_bfloat16 *wh, *wl, *ghh, *ghl, *gxh, *gxl, *ath, *atl, *ffh, *ffl, *qkh, *qkl;
    float *gx, *gproj;
    cudaGetSymbolAddress((void**)&wh,   w_h);
    cudaGetSymbolAddress((void**)&wl,   w_l);
    cudaGetSymbolAddress((void**)&ghh,  gh_h);
    cudaGetSymbolAddress((void**)&ghl,  gh_l);
    cudaGetSymbolAddress((void**)&gxh,  gx_h);
    cudaGetSymbolAddress((void**)&gxl,  gx_l);
    cudaGetSymbolAddress((void**)&ath,  at_h);
    cudaGetSymbolAddress((void**)&atl,  at_l);
    cudaGetSymbolAddress((void**)&ffh,  ff_h);
    cudaGetSymbolAddress((void**)&ffl,  ff_l);
    cudaGetSymbolAddress((void**)&qkh,  qk_h);
    cudaGetSymbolAddress((void**)&qkl,  qk_l);
    cudaGetSymbolAddress((void**)&gx,   g_x);
    cudaGetSymbolAddress((void**)&gproj,g_proj);

    cudaFuncSetAttribute(attn_mma,   cudaFuncAttributeMaxDynamicSharedMemorySize, ATTN_SMEM);
    cudaFuncSetAttribute(gemm_split, cudaFuncAttributeMaxDynamicSharedMemorySize, GEMM_SMEM);

    // 0. weight pre-split
    split_kernel<<<2048, 256>>>(fcw, wh + OFF_FC, wl + OFF_FC, 512 * 4352);
    split_kernel<<<2048, 256>>>(ipw, wh + OFF_IP, wl + OFF_IP, NL * 3 * DM * DM);
    split_kernel<<<2048, 256>>>(opw, wh + OFF_OP, wl + OFF_OP, NL * DM * DM);
    split_kernel<<<2048, 256>>>(fw1, wh + OFF_F1, wl + OFF_F1, NL * DFF * DM);
    split_kernel<<<2048, 256>>>(fw2, wh + OFF_F2, wl + OFF_F2, NL * DM * DFF);

    // 1. GAT frontend -> split bf16
    gat_kernel<<<G_, 128>>>(lm, ei, E, g1w, g1as, g1ad, g1b,
                            g2w, g2as, g2ad, g2b, ghh, ghl);

    // 2. FC + positional encoding -> fp32 gx + split
    run_gemm(ghh, ghl, wh + OFF_FC, wl + OFF_FC, fcb, gx, gxh, gxl,
             G_, DM, L_ * 64, 2 | 4 | 8, pe);

    // 3. transformer encoder layers
    for (int l = 0; l < NL; l++) {
        run_gemm(gxh, gxl, wh + OFF_IP + (size_t)l * 3 * DM * DM, wl + OFF_IP + (size_t)l * 3 * DM * DM,
                 ipb + (size_t)l * 3 * DM, nullptr, qkh, qkl,
                 G_, 3 * DM, DM, /*split*/ 8, nullptr);
        attn_mma<<<dim3(B_ * NH, S_ / 32), 256, ATTN_SMEM>>>(qkh, qkl, ath, atl);
        run_gemm(ath, atl, wh + OFF_OP + (size_t)l * DM * DM, wl + OFF_OP + (size_t)l * DM * DM,
                 opb + (size_t)l * DM, gproj, nullptr, nullptr,
                 G_, DM, DM, 4, nullptr);
        ln_kernel<<<G_, 128>>>(gx, gproj, ln1g + (size_t)l * DM, ln1b + (size_t)l * DM,
                               gx, gxh, gxl);

        run_gemm(gxh, gxl, wh + OFF_F1 + (size_t)l * DFF * DM, wl + OFF_F1 + (size_t)l * DFF * DM,
                 fb1 + (size_t)l * DFF, nullptr, ffh, ffl,
                 G_, DFF, DM, 1 | 8, nullptr);
        run_gemm(ffh, ffl, wh + OFF_F2 + (size_t)l * DM * DFF, wl + OFF_F2 + (size_t)l * DM * DFF,
                 fb2 + (size_t)l * DM, gproj, nullptr, nullptr,
                 G_, DM, DFF, 4, nullptr);
        float* outp = (l == NL - 1) ? (float*)d_out : gx;
        ln_kernel<<<G_, 128>>>(gx, gproj, ln2g + (size_t)l * DM, ln2b + (size_t)l * DM,
                               outp, gxh, gxl);
    }
    (void)n_in; (void)out_size;
}

// round 9
// speedup vs baseline: 2.8077x; 1.2049x over previous
#include <cuda_runtime.h>
#include <cuda_bf16.h>
#include <math.h>
#include <stdint.h>

// ---------------- problem constants ----------------
static const int B_  = 8;
static const int S_  = 256;
static const int G_  = 2048;
static const int L_  = 68;
static const int DM  = 512;
static const int NH  = 8;
static const int DH  = 64;
static const int DFF = 2048;
static const int NL  = 6;
static const int MAXE = 512;

// weight offsets in the packed split-weight buffers
static const size_t OFF_FC = 0;                    // 512*4352
static const size_t OFF_IP = 2228224;              // 6*1536*512
static const size_t OFF_OP = 6946816;              // 6*512*512
static const size_t OFF_F1 = 8519680;              // 6*2048*512
static const size_t OFF_F2 = 14811136;             // 6*512*2048
static const size_t W_TOT  = 21102592;

// ---------------- scratch (static device memory) ----------------
__device__ __nv_bfloat16 w_h[W_TOT], w_l[W_TOT];
__device__ __nv_bfloat16 gh_h[G_ * L_ * 64], gh_l[G_ * L_ * 64];
__device__ __nv_bfloat16 gx_h[G_ * DM],      gx_l[G_ * DM];
__device__ __nv_bfloat16 at_h[G_ * DM],      at_l[G_ * DM];
__device__ __nv_bfloat16 ff_h[G_ * DFF],     ff_l[G_ * DFF];
__device__ __nv_bfloat16 qk_h[G_ * 3 * DM],  qk_l[G_ * 3 * DM];
__device__ float g_x   [G_ * DM];
__device__ float g_proj[G_ * DM];

// ---------------- helpers ----------------
__device__ __forceinline__ void split_write(float v, __nv_bfloat16* hi, __nv_bfloat16* lo, size_t i) {
    __nv_bfloat16 h = __float2bfloat16(v);
    hi[i] = h;
    lo[i] = __float2bfloat16(v - __bfloat162float(h));
}

// =====================================================================
// weight split kernel (grid-stride)
// =====================================================================
__global__ __launch_bounds__(256) void split_kernel(
    const float* __restrict__ src, __nv_bfloat16* __restrict__ hi,
    __nv_bfloat16* __restrict__ lo, int n)
{
    int i = blockIdx.x * blockDim.x + threadIdx.x;
    int stride = gridDim.x * blockDim.x;
    for (; i < n; i += stride) {
        float v = src[i];
        __nv_bfloat16 h = __float2bfloat16(v);
        hi[i] = h;
        lo[i] = __float2bfloat16(v - __bfloat162float(h));
    }
}

// =====================================================================
// GAT: both layers fused, one block per graph; writes split bf16
// =====================================================================
__global__ __launch_bounds__(128) void gat_kernel(
    const float* __restrict__ lm, const int* __restrict__ ei, int E,
    const float* __restrict__ w1, const float* __restrict__ as1,
    const float* __restrict__ ad1, const float* __restrict__ b1,
    const float* __restrict__ w2, const float* __restrict__ as2,
    const float* __restrict__ ad2, const float* __restrict__ b2,
    __nv_bfloat16* __restrict__ oh, __nv_bfloat16* __restrict__ ol)
{
    __shared__ float h1[L_ * 16];
    __shared__ float x2[L_ * 16];
    __shared__ float h2[L_ * 64];
    __shared__ float sa[L_], sd[L_];
    __shared__ float ee[MAXE];
    __shared__ int   ssrc[MAXE], sdst[MAXE];

    const int g   = blockIdx.x;
    const int tid = threadIdx.x;
    const float* x = lm + (size_t)g * L_ * 2;

    for (int j = tid; j < E; j += blockDim.x) { ssrc[j] = ei[j]; sdst[j] = ei[E + j]; }

    for (int i = tid; i < L_ * 16; i += blockDim.x) {
        int l = i >> 4, f = i & 15;
        h1[i] = w1[f * 2 + 0] * x[l * 2 + 0] + w1[f * 2 + 1] * x[l * 2 + 1];
    }
    __syncthreads();
    if (tid < L_) {
        float a = 0.f, d = 0.f;
        #pragma unroll
        for (int f = 0; f < 16; f++) { a += h1[tid * 16 + f] * as1[f]; d += h1[tid * 16 + f] * ad1[f]; }
        sa[tid] = a; sd[tid] = d;
    }
    __syncthreads();
    for (int j = tid; j < E; j += blockDim.x) {
        float v = sa[ssrc[j]] + sd[sdst[j]];
        ee[j] = v > 0.f ? v : 0.2f * v;
    }
    __syncthreads();
    if (tid < L_) {
        float m = -1e30f;
        for (int j = 0; j < E; j++) if (sdst[j] == tid) m = fmaxf(m, ee[j]);
        float s = 0.f;
        float acc[16];
        #pragma unroll
        for (int f = 0; f < 16; f++) acc[f] = 0.f;
        for (int j = 0; j < E; j++) if (sdst[j] == tid) {
            float w = expf(ee[j] - m); s += w;
            const float* hs = &h1[ssrc[j] * 16];
            #pragma unroll
            for (int f = 0; f < 16; f++) acc[f] += w * hs[f];
        }
        float inv = 1.f / s;
        #pragma unroll
        for (int f = 0; f < 16; f++) {
            float v = acc[f] * inv + b1[f];
            x2[tid * 16 + f] = v > 0.f ? v : 0.f;
        }
    }
    __syncthreads();

    for (int i = tid; i < L_ * 64; i += blockDim.x) {
        int l = i >> 6, f = i & 63;
        float a = 0.f;
        const float* xr = &x2[l * 16];
        const float* wr = &w2[f * 16];
        #pragma unroll
        for (int c = 0; c < 16; c++) a += xr[c] * wr[c];
        h2[i] = a;
    }
    __syncthreads();
    if (tid < L_) {
        float a = 0.f, d = 0.f;
        const float* hr = &h2[tid * 64];
        #pragma unroll
        for (int f = 0; f < 64; f++) { a += hr[f] * as2[f]; d += hr[f] * ad2[f]; }
        sa[tid] = a; sd[tid] = d;
    }
    __syncthreads();
    for (int j = tid; j < E; j += blockDim.x) {
        float v = sa[ssrc[j]] + sd[sdst[j]];
        ee[j] = v > 0.f ? v : 0.2f * v;
    }
    __syncthreads();
    if (tid < L_) {
        float m = -1e30f;
        for (int j = 0; j < E; j++) if (sdst[j] == tid) m = fmaxf(m, ee[j]);
        float s = 0.f;
        float acc[64];
        #pragma unroll
        for (int f = 0; f < 64; f++) acc[f] = 0.f;
        for (int j = 0; j < E; j++) if (sdst[j] == tid) {
            float w = expf(ee[j] - m); s += w;
            const float* hs = &h2[ssrc[j] * 64];
            #pragma unroll
            for (int f = 0; f < 64; f++) acc[f] += w * hs[f];
        }
        float inv = 1.f / s;
        size_t base = (size_t)g * (L_ * 64) + tid * 64;
        #pragma unroll
        for (int f = 0; f < 64; f++) {
            float v = acc[f] * inv + b2[f];
            v = v > 0.f ? v : 0.f;
            split_write(v, oh, ol, base + f);
        }
    }
}

// =====================================================================
// mma helpers
// =====================================================================
__device__ __forceinline__ void ldsm4(uint32_t& r0, uint32_t& r1, uint32_t& r2, uint32_t& r3,
                                      const __nv_bfloat16* p) {
    uint32_t addr = (uint32_t)__cvta_generic_to_shared(p);
    asm volatile("ldmatrix.sync.aligned.m8n8.x4.shared.b16 {%0,%1,%2,%3}, [%4];\n"
                 : "=r"(r0), "=r"(r1), "=r"(r2), "=r"(r3) : "r"(addr));
}

__device__ __forceinline__ void ldsm4t(uint32_t& r0, uint32_t& r1, uint32_t& r2, uint32_t& r3,
                                       const __nv_bfloat16* p) {
    uint32_t addr = (uint32_t)__cvta_generic_to_shared(p);
    asm volatile("ldmatrix.sync.aligned.m8n8.x4.trans.shared.b16 {%0,%1,%2,%3}, [%4];\n"
                 : "=r"(r0), "=r"(r1), "=r"(r2), "=r"(r3) : "r"(addr));
}

__device__ __forceinline__ void mma16816(float* c, const uint32_t* a, uint32_t b0, uint32_t b1) {
    asm volatile("mma.sync.aligned.m16n8k16.row.col.f32.bf16.bf16.f32 "
                 "{%0,%1,%2,%3}, {%4,%5,%6,%7}, {%8,%9}, {%0,%1,%2,%3};\n"
                 : "+f"(c[0]), "+f"(c[1]), "+f"(c[2]), "+f"(c[3])
                 : "r"(a[0]), "r"(a[1]), "r"(a[2]), "r"(a[3]), "r"(b0), "r"(b1));
}

__device__ __forceinline__ void cp16(uint32_t dst, const void* src) {
    asm volatile("cp.async.ca.shared.global [%0], [%1], 16;" :: "r"(dst), "l"(src));
}

// =====================================================================
// split-bf16 tensor-core GEMM, 64x128 block tile (wave-quantization fix)
// grid = (N/128, M/64); 8 warps (2x4), warp tile 32x32.
// flags: 1 relu, 2 +pe, 4 write fp32 C, 8 write split Ch/Cl
// =====================================================================
static const int TSTR = 40;
// per stage: Ah(64) + Al(64) + Bh(128) + Bl(128) = 384 rows
static const int GEMM_SMEM = 2 * 384 * TSTR * 2;  // 61440 B

__global__ __launch_bounds__(256) void gemm_split(
    const __nv_bfloat16* __restrict__ Ah, const __nv_bfloat16* __restrict__ Al,
    const __nv_bfloat16* __restrict__ Bh, const __nv_bfloat16* __restrict__ Bl,
    const float* __restrict__ bias, float* __restrict__ C,
    __nv_bfloat16* __restrict__ Ch, __nv_bfloat16* __restrict__ Cl,
    int M, int N, int K, int flags, const float* __restrict__ pe)
{
    extern __shared__ __nv_bfloat16 smb[];

    const int tid  = threadIdx.x;
    const int lane = tid & 31, warp = tid >> 5;
    const int wm = warp & 1, wn = warp >> 1;     // warp tile 32x32
    const int bm = blockIdx.y, bn = blockIdx.x;

    const __nv_bfloat16* srcA[2];
    const __nv_bfloat16* srcB[2];
    srcA[0] = Ah + (size_t)(bm * 64) * K;
    srcA[1] = Al + (size_t)(bm * 64) * K;
    srcB[0] = Bh + (size_t)(bn * 128) * K;
    srcB[1] = Bl + (size_t)(bn * 128) * K;

    const int lrow = tid >> 2;          // 0..63
    const int lcol = (tid & 3) * 8;     // k offset within 32-chunk

    auto issue = [&](int st, int k0) {
        __nv_bfloat16* stbase = smb + (size_t)st * 384 * TSTR;
        // A planes: 64 rows, 1 chunk per thread
        #pragma unroll
        for (int p = 0; p < 2; p++) {
            __nv_bfloat16* pl = stbase + p * 64 * TSTR;
            cp16((uint32_t)__cvta_generic_to_shared(pl + lrow * TSTR + lcol),
                 srcA[p] + (size_t)lrow * K + k0 + lcol);
        }
        // B planes: 128 rows, 2 chunks per thread
        #pragma unroll
        for (int p = 0; p < 2; p++) {
            __nv_bfloat16* pl = stbase + (128 + p * 128) * TSTR;
            #pragma unroll
            for (int i = 0; i < 2; i++) {
                int row = lrow + i * 64;
                cp16((uint32_t)__cvta_generic_to_shared(pl + row * TSTR + lcol),
                     srcB[p] + (size_t)row * K + k0 + lcol);
            }
        }
        asm volatile("cp.async.commit_group;\n");
    };

    float c[2][4][4];
    #pragma unroll
    for (int i = 0; i < 2; i++)
        #pragma unroll
        for (int j = 0; j < 4; j++)
            #pragma unroll
            for (int q = 0; q < 4; q++) c[i][j][q] = 0.f;

    issue(0, 0);
    asm volatile("cp.async.wait_group 0;\n");
    __syncthreads();

    const int KT = K / 32;
    int cur = 0;
    for (int kt = 0; kt < KT; kt++) {
        if (kt + 1 < KT) issue(cur ^ 1, (kt + 1) * 32);

        const __nv_bfloat16* stb = smb + (size_t)cur * 384 * TSTR;
        const __nv_bfloat16* pAh = stb;
        const __nv_bfloat16* pAl = stb + 64 * TSTR;
        const __nv_bfloat16* pBh = stb + 128 * TSTR;
        const __nv_bfloat16* pBl = stb + 256 * TSTR;

        #pragma unroll
        for (int kh = 0; kh < 2; kh++) {
            const int r  = lane & 15;
            const int cc = kh * 16 + ((lane >> 4) << 3);
            uint32_t ah[2][4], al[2][4], bhr[2][4], blr[2][4];
            #pragma unroll
            for (int mt = 0; mt < 2; mt++) {
                int row = wm * 32 + mt * 16 + r;
                ldsm4(ah[mt][0], ah[mt][1], ah[mt][2], ah[mt][3], pAh + row * TSTR + cc);
                ldsm4(al[mt][0], al[mt][1], al[mt][2], al[mt][3], pAl + row * TSTR + cc);
            }
            #pragma unroll
            for (int g = 0; g < 2; g++) {
                int row = wn * 32 + g * 16 + r;
                ldsm4(bhr[g][0], bhr[g][1], bhr[g][2], bhr[g][3], pBh + row * TSTR + cc);
                ldsm4(blr[g][0], blr[g][1], blr[g][2], blr[g][3], pBl + row * TSTR + cc);
            }
            #pragma unroll
            for (int mt = 0; mt < 2; mt++) {
                #pragma unroll
                for (int nt = 0; nt < 4; nt++) {
                    const int g = nt >> 1, s = nt & 1;
                    mma16816(c[mt][nt], ah[mt], bhr[g][s], bhr[g][s + 2]);
                    mma16816(c[mt][nt], ah[mt], blr[g][s], blr[g][s + 2]);
                    mma16816(c[mt][nt], al[mt], bhr[g][s], bhr[g][s + 2]);
                }
            }
        }

        if (kt + 1 < KT) {
            asm volatile("cp.async.wait_group 0;\n");
        }
        __syncthreads();
        cur ^= 1;
    }

    #pragma unroll
    for (int mt = 0; mt < 2; mt++) {
        const int mbase = bm * 64 + wm * 32 + mt * 16 + (lane >> 2);
        #pragma unroll
        for (int half = 0; half < 2; half++) {
            const int m = mbase + half * 8;
            const size_t rowoff = (size_t)m * N;
            const float* perow = (flags & 2) ? (pe + (size_t)(m & (S_ - 1)) * DM) : nullptr;
            #pragma unroll
            for (int nt = 0; nt < 4; nt++) {
                const int n = bn * 128 + wn * 32 + nt * 8 + (lane & 3) * 2;
                float v0 = c[mt][nt][half * 2 + 0] + bias[n];
                float v1 = c[mt][nt][half * 2 + 1] + bias[n + 1];
                if (flags & 1) { v0 = fmaxf(v0, 0.f); v1 = fmaxf(v1, 0.f); }
                if (flags & 2) { v0 += perow[n]; v1 += perow[n + 1]; }
                if (flags & 4) {
                    float2 o; o.x = v0; o.y = v1;
                    *(float2*)(C + rowoff + n) = o;
                }
                if (flags & 8) {
                    __nv_bfloat16 h0 = __float2bfloat16(v0);
                    __nv_bfloat16 h1 = __float2bfloat16(v1);
                    __nv_bfloat162 hh; hh.x = h0; hh.y = h1;
                    __nv_bfloat162 ll;
                    ll.x = __float2bfloat16(v0 - __bfloat162float(h0));
                    ll.y = __float2bfloat16(v1 - __bfloat162float(h1));
                    *(__nv_bfloat162*)(Ch + rowoff + n) = hh;
                    *(__nv_bfloat162*)(Cl + rowoff + n) = ll;
                }
            }
        }
    }
}

// =====================================================================
// Tensor-core attention: block per (b, h, q-chunk 32), 8 warps.
// =====================================================================
static const int KSTR = 72;
static const int SSTR = 264;
static const int OF_KH = 0;
static const int OF_KL = OF_KH + 256 * KSTR * 2;
static const int OF_VH = OF_KL + 256 * KSTR * 2;
static const int OF_VL = OF_VH + 256 * KSTR * 2;
static const int OF_QH = OF_VL + 256 * KSTR * 2;
static const int OF_QL = OF_QH + 32 * KSTR * 2;
static const int OF_SH = OF_QL + 32 * KSTR * 2;
static const int OF_SL = OF_SH + 32 * SSTR * 2;
static const int OF_SF = OF_SL + 32 * SSTR * 2;
static const int ATTN_SMEM = OF_SF + 32 * SSTR * 4;  // 224256

__global__ __launch_bounds__(256) void attn_mma(
    const __nv_bfloat16* __restrict__ qh, const __nv_bfloat16* __restrict__ ql,
    __nv_bfloat16* __restrict__ oh, __nv_bfloat16* __restrict__ ol)
{
    extern __shared__ __align__(16) char smc[];
    __nv_bfloat16* Kh = (__nv_bfloat16*)(smc + OF_KH);
    __nv_bfloat16* Kl = (__nv_bfloat16*)(smc + OF_KL);
    __nv_bfloat16* Vh = (__nv_bfloat16*)(smc + OF_VH);
    __nv_bfloat16* Vl = (__nv_bfloat16*)(smc + OF_VL);
    __nv_bfloat16* Qh = (__nv_bfloat16*)(smc + OF_QH);
    __nv_bfloat16* Ql = (__nv_bfloat16*)(smc + OF_QL);
    __nv_bfloat16* Sh = (__nv_bfloat16*)(smc + OF_SH);
    __nv_bfloat16* Sl = (__nv_bfloat16*)(smc + OF_SL);
    float*         Sf = (float*)(smc + OF_SF);

    const int bh  = blockIdx.x;
    const int b   = bh >> 3, hd = bh & 7;
    const int q0  = blockIdx.y * 32;
    const int tid = threadIdx.x;
    const int lane = tid & 31, warp = tid >> 5;

    const size_t rowK = (size_t)b * S_ * (3 * DM) + hd * DH;
    {
        for (int i = tid; i < 256 * 8; i += 256) {
            int r = i >> 3, cc = (i & 7) * 8;
            size_t g = rowK + (size_t)r * (3 * DM);
            *(uint4*)&Kh[r * KSTR + cc] = *(const uint4*)(qh + g + DM + cc);
            *(uint4*)&Kl[r * KSTR + cc] = *(const uint4*)(ql + g + DM + cc);
            *(uint4*)&Vh[r * KSTR + cc] = *(const uint4*)(qh + g + 2 * DM + cc);
            *(uint4*)&Vl[r * KSTR + cc] = *(const uint4*)(ql + g + 2 * DM + cc);
        }
        for (int i = tid; i < 32 * 8; i += 256) {
            int r = i >> 3, cc = (i & 7) * 8;
            size_t g = rowK + (size_t)(q0 + r) * (3 * DM);
            *(uint4*)&Qh[r * KSTR + cc] = *(const uint4*)(qh + g + cc);
            *(uint4*)&Ql[r * KSTR + cc] = *(const uint4*)(ql + g + cc);
        }
    }
    __syncthreads();

    const int wm = warp & 1, wn = warp >> 1;
    {
        float c[8][4];
        #pragma unroll
        for (int t = 0; t < 8; t++)
            #pragma unroll
            for (int q = 0; q < 4; q++) c[t][q] = 0.f;

        const int r  = lane & 15;
        const int c8 = (lane >> 4) << 3;
        #pragma unroll
        for (int k0 = 0; k0 < 64; k0 += 16) {
            uint32_t aqh[4], aql[4];
            ldsm4(aqh[0], aqh[1], aqh[2], aqh[3], Qh + (wm * 16 + r) * KSTR + k0 + c8);
            ldsm4(aql[0], aql[1], aql[2], aql[3], Ql + (wm * 16 + r) * KSTR + k0 + c8);
            #pragma unroll
            for (int j = 0; j < 4; j++) {
                uint32_t bkh[4], bkl[4];
                const int key = wn * 64 + j * 16 + r;
                ldsm4(bkh[0], bkh[1], bkh[2], bkh[3], Kh + key * KSTR + k0 + c8);
                ldsm4(bkl[0], bkl[1], bkl[2], bkl[3], Kl + key * KSTR + k0 + c8);
                #pragma unroll
                for (int s = 0; s < 2; s++) {
                    mma16816(c[2 * j + s], aqh, bkh[s], bkh[s + 2]);
                    mma16816(c[2 * j + s], aqh, bkl[s], bkl[s + 2]);
                    mma16816(c[2 * j + s], aql, bkh[s], bkh[s + 2]);
                }
            }
        }
        const int row0 = wm * 16 + (lane >> 2);
        #pragma unroll
        for (int t = 0; t < 8; t++) {
            const int col = wn * 64 + t * 8 + (lane & 3) * 2;
            Sf[row0 * SSTR + col]           = c[t][0] * 0.125f;
            Sf[row0 * SSTR + col + 1]       = c[t][1] * 0.125f;
            Sf[(row0 + 8) * SSTR + col]     = c[t][2] * 0.125f;
            Sf[(row0 + 8) * SSTR + col + 1] = c[t][3] * 0.125f;
        }
    }
    __syncthreads();

    for (int rr = warp; rr < 32; rr += 8) {
        float* row = &Sf[rr * SSTR];
        float mx = -1e30f;
        #pragma unroll
        for (int t = lane; t < 256; t += 32) mx = fmaxf(mx, row[t]);
        #pragma unroll
        for (int off = 16; off; off >>= 1) mx = fmaxf(mx, __shfl_xor_sync(0xffffffffu, mx, off));
        float s = 0.f;
        float ev[8];
        #pragma unroll
        for (int u = 0; u < 8; u++) {
            ev[u] = expf(row[lane + u * 32] - mx);
            s += ev[u];
        }
        #pragma unroll
        for (int off = 16; off; off >>= 1) s += __shfl_xor_sync(0xffffffffu, s, off);
        float inv = 1.f / s;
        #pragma unroll
        for (int u = 0; u < 8; u++) {
            float v = ev[u] * inv;
            __nv_bfloat16 h = __float2bfloat16(v);
            Sh[rr * SSTR + lane + u * 32] = h;
            Sl[rr * SSTR + lane + u * 32] = __float2bfloat16(v - __bfloat162float(h));
        }
    }
    __syncthreads();

    {
        float o[2][4];
        #pragma unroll
        for (int t = 0; t < 2; t++)
            #pragma unroll
            for (int q = 0; q < 4; q++) o[t][q] = 0.f;

        const int r  = lane & 15;
        const int c8 = (lane >> 4) << 3;
        #pragma unroll 4
        for (int k0 = 0; k0 < 256; k0 += 16) {
            uint32_t ash[4], asl[4];
            ldsm4(ash[0], ash[1], ash[2], ash[3], Sh + (wm * 16 + r) * SSTR + k0 + c8);
            ldsm4(asl[0], asl[1], asl[2], asl[3], Sl + (wm * 16 + r) * SSTR + k0 + c8);
            uint32_t bvh[4], bvl[4];
            ldsm4t(bvh[0], bvh[1], bvh[2], bvh[3], Vh + (k0 + r) * KSTR + wn * 16 + c8);
            ldsm4t(bvl[0], bvl[1], bvl[2], bvl[3], Vl + (k0 + r) * KSTR + wn * 16 + c8);
            #pragma unroll
            for (int t = 0; t < 2; t++) {
                mma16816(o[t], ash, bvh[2 * t], bvh[2 * t + 1]);
                mma16816(o[t], ash, bvl[2 * t], bvl[2 * t + 1]);
                mma16816(o[t], asl, bvh[2 * t], bvh[2 * t + 1]);
            }
        }
        const int row0 = q0 + wm * 16 + (lane >> 2);
        #pragma unroll
        for (int t = 0; t < 2; t++) {
            const int d = hd * DH + wn * 16 + t * 8 + (lane & 3) * 2;
            size_t i0 = ((size_t)b * S_ + row0) * DM + d;
            size_t i1 = ((size_t)b * S_ + row0 + 8) * DM + d;
            split_write(o[t][0], oh, ol, i0);
            split_write(o[t][1], oh, ol, i0 + 1);
            split_write(o[t][2], oh, ol, i1);
            split_write(o[t][3], oh, ol, i1 + 1);
        }
    }
}

// =====================================================================
// Residual + LayerNorm; writes fp32 out + split bf16
// =====================================================================
__global__ __launch_bounds__(128) void ln_kernel(
    const float* __restrict__ x, const float* __restrict__ r,
    const float* __restrict__ gam, const float* __restrict__ bet,
    float* __restrict__ out,
    __nv_bfloat16* __restrict__ oh, __nv_bfloat16* __restrict__ ol)
{
    const int row = blockIdx.x, tid = threadIdx.x;
    const float* xr = x + (size_t)row * DM;
    const float* rr = r + (size_t)row * DM;
    float v[4];
    float s = 0.f, s2 = 0.f;
    #pragma unroll
    for (int u = 0; u < 4; u++) {
        int i = tid + u * 128;
        v[u] = xr[i] + rr[i];
        s += v[u]; s2 += v[u] * v[u];
    }
    __shared__ float rs[4], rs2[4];
    #pragma unroll
    for (int off = 16; off; off >>= 1) {
        s  += __shfl_xor_sync(0xffffffffu, s,  off);
        s2 += __shfl_xor_sync(0xffffffffu, s2, off);
    }
    if ((tid & 31) == 0) { rs[tid >> 5] = s; rs2[tid >> 5] = s2; }
    __syncthreads();
    s  = rs[0] + rs[1] + rs[2] + rs[3];
    s2 = rs2[0] + rs2[1] + rs2[2] + rs2[3];
    float mean = s * (1.f / DM);
    float var  = s2 * (1.f / DM) - mean * mean;
    float k = rsqrtf(var + 1e-5f);
    float* orow = out + (size_t)row * DM;
    #pragma unroll
    for (int u = 0; u < 4; u++) {
        int i = tid + u * 128;
        float o = (v[u] - mean) * k * gam[i] + bet[i];
        orow[i] = o;
        split_write(o, oh, ol, (size_t)row * DM + i);
    }
}

// =====================================================================
// host launcher
// =====================================================================
static void run_gemm(const __nv_bfloat16* Ah, const __nv_bfloat16* Al,
                     const __nv_bfloat16* Bh, const __nv_bfloat16* Bl,
                     const float* bias, float* C,
                     __nv_bfloat16* Ch, __nv_bfloat16* Cl,
                     int M, int N, int K, int flags, const float* pe) {
    dim3 grid(N / 128, M / 64);
    gemm_split<<<grid, 256, GEMM_SMEM>>>(Ah, Al, Bh, Bl, bias, C, Ch, Cl, M, N, K, flags, pe);
}

extern "C" void kernel_launch(void* const* d_in, const int* in_sizes, int n_in,
                              void* d_out, int out_size)
{
    const float* lm    = (const float*)d_in[0];
    const int*   ei    = (const int*)  d_in[1];
    const int    E     = in_sizes[1] / 2;
    const float* g1w   = (const float*)d_in[2];
    const float* g1as  = (const float*)d_in[3];
    const float* g1ad  = (const float*)d_in[4];
    const float* g1b   = (const float*)d_in[5];
    const float* g2w   = (const float*)d_in[6];
    const float* g2as  = (const float*)d_in[7];
    const float* g2ad  = (const float*)d_in[8];
    const float* g2b   = (const float*)d_in[9];
    const float* fcw   = (const float*)d_in[10];
    const float* fcb   = (const float*)d_in[11];
    const float* pe    = (const float*)d_in[12];
    const float* ipw   = (const float*)d_in[13];
    const float* ipb   = (const float*)d_in[14];
    const float* opw   = (const float*)d_in[15];
    const float* opb   = (const float*)d_in[16];
    const float* ln1g  = (const float*)d_in[17];
    const float* ln1b  = (const float*)d_in[18];
    const float* fw1   = (const float*)d_in[19];
    const float* fb1   = (const float*)d_in[20];
    const float* fw2   = (const float*)d_in[21];
    const float* fb2   = (const float*)d_in[22];
    const float* ln2g  = (const float*)d_in[23];
    const float* ln2b  = (const float*)d_in[24];

    __nv_bfloat16 *wh, *wl, *ghh, *ghl, *gxh, *gxl, *ath, *atl, *ffh, *ffl, *qkh, *qkl;
    float *gx, *gproj;
    cudaGetSymbolAddress((void**)&wh,   w_h);
    cudaGetSymbolAddress((void**)&wl,   w_l);
    cudaGetSymbolAddress((void**)&ghh,  gh_h);
    cudaGetSymbolAddress((void**)&ghl,  gh_l);
    cudaGetSymbolAddress((void**)&gxh,  gx_h);
    cudaGetSymbolAddress((void**)&gxl,  gx_l);
    cudaGetSymbolAddress((void**)&ath,  at_h);
    cudaGetSymbolAddress((void**)&atl,  at_l);
    cudaGetSymbolAddress((void**)&ffh,  ff_h);
    cudaGetSymbolAddress((void**)&ffl,  ff_l);
    cudaGetSymbolAddress((void**)&qkh,  qk_h);
    cudaGetSymbolAddress((void**)&qkl,  qk_l);
    cudaGetSymbolAddress((void**)&gx,   g_x);
    cudaGetSymbolAddress((void**)&gproj,g_proj);

    cudaFuncSetAttribute(attn_mma,   cudaFuncAttributeMaxDynamicSharedMemorySize, ATTN_SMEM);
    cudaFuncSetAttribute(gemm_split, cudaFuncAttributeMaxDynamicSharedMemorySize, GEMM_SMEM);

    // 0. weight pre-split
    split_kernel<<<2048, 256>>>(fcw, wh + OFF_FC, wl + OFF_FC, 512 * 4352);
    split_kernel<<<2048, 256>>>(ipw, wh + OFF_IP, wl + OFF_IP, NL * 3 * DM * DM);
    split_kernel<<<2048, 256>>>(opw, wh + OFF_OP, wl + OFF_OP, NL * DM * DM);
    split_kernel<<<2048, 256>>>(fw1, wh + OFF_F1, wl + OFF_F1, NL * DFF * DM);
    split_kernel<<<2048, 256>>>(fw2, wh + OFF_F2, wl + OFF_F2, NL * DM * DFF);

    // 1. GAT frontend -> split bf16
    gat_kernel<<<G_, 128>>>(lm, ei, E, g1w, g1as, g1ad, g1b,
                            g2w, g2as, g2ad, g2b, ghh, ghl);

    // 2. FC + positional encoding -> fp32 gx + split
    run_gemm(ghh, ghl, wh + OFF_FC, wl + OFF_FC, fcb, gx, gxh, gxl,
             G_, DM, L_ * 64, 2 | 4 | 8, pe);

    // 3. transformer encoder layers
    for (int l = 0; l < NL; l++) {
        run_gemm(gxh, gxl, wh + OFF_IP + (size_t)l * 3 * DM * DM, wl + OFF_IP + (size_t)l * 3 * DM * DM,
                 ipb + (size_t)l * 3 * DM, nullptr, qkh, qkl,
                 G_, 3 * DM, DM, /*split*/ 8, nullptr);
        attn_mma<<<dim3(B_ * NH, S_ / 32), 256, ATTN_SMEM>>>(qkh, qkl, ath, atl);
        run_gemm(ath, atl, wh + OFF_OP + (size_t)l * DM * DM, wl + OFF_OP + (size_t)l * DM * DM,
                 opb + (size_t)l * DM, gproj, nullptr, nullptr,
                 G_, DM, DM, 4, nullptr);
        ln_kernel<<<G_, 128>>>(gx, gproj, ln1g + (size_t)l * DM, ln1b + (size_t)l * DM,
                               gx, gxh, gxl);

        run_gemm(gxh, gxl, wh + OFF_F1 + (size_t)l * DFF * DM, wl + OFF_F1 + (size_t)l * DFF * DM,
                 fb1 + (size_t)l * DFF, nullptr, ffh, ffl,
                 G_, DFF, DM, 1 | 8, nullptr);
        run_gemm(ffh, ffl, wh + OFF_F2 + (size_t)l * DM * DFF, wl + OFF_F2 + (size_t)l * DM * DFF,
                 fb2 + (size_t)l * DM, gproj, nullptr, nullptr,
                 G_, DM, DFF, 4, nullptr);
        float* outp = (l == NL - 1) ? (float*)d_out : gx;
        ln_kernel<<<G_, 128>>>(gx, gproj, ln2g + (size_t)l * DM, ln2b + (size_t)l * DM,
                               outp, gxh, gxl);
    }
    (void)n_in; (void)out_size;
}

// round 10
// speedup vs baseline: 4.2122x; 1.5002x over previous
#include <cuda_runtime.h>
#include <cuda_fp16.h>
#include <math.h>
#include <stdint.h>

// ---------------- problem constants ----------------
static const int B_  = 8;
static const int S_  = 256;
static const int G_  = 2048;
static const int L_  = 68;
static const int DM  = 512;
static const int NH  = 8;
static const int DH  = 64;
static const int DFF = 2048;
static const int NL  = 6;
static const int MAXE = 512;

// weight offsets in the packed fp16 weight buffer
static const size_t OFF_FC = 0;                    // 512*4352
static const size_t OFF_IP = 2228224;              // 6*1536*512
static const size_t OFF_OP = 6946816;              // 6*512*512
static const size_t OFF_F1 = 8519680;              // 6*2048*512
static const size_t OFF_F2 = 14811136;             // 6*512*2048
static const size_t W_TOT  = 21102592;

// ---------------- scratch (static device memory) ----------------
__device__ __half w_f [W_TOT];
__device__ __half gh_f[G_ * L_ * 64];
__device__ __half gx_f[G_ * DM];
__device__ __half at_f[G_ * DM];
__device__ __half ff_f[G_ * DFF];
__device__ __half qk_f[G_ * 3 * DM];
__device__ float g_x   [G_ * DM];
__device__ float g_proj[G_ * DM];

// =====================================================================
// fp32 -> fp16 convert (grid-stride)
// =====================================================================
__global__ __launch_bounds__(256) void cvt_kernel(
    const float* __restrict__ src, __half* __restrict__ dst, int n)
{
    int i = blockIdx.x * blockDim.x + threadIdx.x;
    int stride = gridDim.x * blockDim.x;
    for (; i < n; i += stride) dst[i] = __float2half(src[i]);
}

// =====================================================================
// GAT: both layers fused, one block per graph; writes fp16
// =====================================================================
__global__ __launch_bounds__(128) void gat_kernel(
    const float* __restrict__ lm, const int* __restrict__ ei, int E,
    const float* __restrict__ w1, const float* __restrict__ as1,
    const float* __restrict__ ad1, const float* __restrict__ b1,
    const float* __restrict__ w2, const float* __restrict__ as2,
    const float* __restrict__ ad2, const float* __restrict__ b2,
    __half* __restrict__ out)
{
    __shared__ float h1[L_ * 16];
    __shared__ float x2[L_ * 16];
    __shared__ float h2[L_ * 64];
    __shared__ float sa[L_], sd[L_];
    __shared__ float ee[MAXE];
    __shared__ int   ssrc[MAXE], sdst[MAXE];

    const int g   = blockIdx.x;
    const int tid = threadIdx.x;
    const float* x = lm + (size_t)g * L_ * 2;

    for (int j = tid; j < E; j += blockDim.x) { ssrc[j] = ei[j]; sdst[j] = ei[E + j]; }

    for (int i = tid; i < L_ * 16; i += blockDim.x) {
        int l = i >> 4, f = i & 15;
        h1[i] = w1[f * 2 + 0] * x[l * 2 + 0] + w1[f * 2 + 1] * x[l * 2 + 1];
    }
    __syncthreads();
    if (tid < L_) {
        float a = 0.f, d = 0.f;
        #pragma unroll
        for (int f = 0; f < 16; f++) { a += h1[tid * 16 + f] * as1[f]; d += h1[tid * 16 + f] * ad1[f]; }
        sa[tid] = a; sd[tid] = d;
    }
    __syncthreads();
    for (int j = tid; j < E; j += blockDim.x) {
        float v = sa[ssrc[j]] + sd[sdst[j]];
        ee[j] = v > 0.f ? v : 0.2f * v;
    }
    __syncthreads();
    if (tid < L_) {
        float m = -1e30f;
        for (int j = 0; j < E; j++) if (sdst[j] == tid) m = fmaxf(m, ee[j]);
        float s = 0.f;
        float acc[16];
        #pragma unroll
        for (int f = 0; f < 16; f++) acc[f] = 0.f;
        for (int j = 0; j < E; j++) if (sdst[j] == tid) {
            float w = expf(ee[j] - m); s += w;
            const float* hs = &h1[ssrc[j] * 16];
            #pragma unroll
            for (int f = 0; f < 16; f++) acc[f] += w * hs[f];
        }
        float inv = 1.f / s;
        #pragma unroll
        for (int f = 0; f < 16; f++) {
            float v = acc[f] * inv + b1[f];
            x2[tid * 16 + f] = v > 0.f ? v : 0.f;
        }
    }
    __syncthreads();

    for (int i = tid; i < L_ * 64; i += blockDim.x) {
        int l = i >> 6, f = i & 63;
        float a = 0.f;
        const float* xr = &x2[l * 16];
        const float* wr = &w2[f * 16];
        #pragma unroll
        for (int c = 0; c < 16; c++) a += xr[c] * wr[c];
        h2[i] = a;
    }
    __syncthreads();
    if (tid < L_) {
        float a = 0.f, d = 0.f;
        const float* hr = &h2[tid * 64];
        #pragma unroll
        for (int f = 0; f < 64; f++) { a += hr[f] * as2[f]; d += hr[f] * ad2[f]; }
        sa[tid] = a; sd[tid] = d;
    }
    __syncthreads();
    for (int j = tid; j < E; j += blockDim.x) {
        float v = sa[ssrc[j]] + sd[sdst[j]];
        ee[j] = v > 0.f ? v : 0.2f * v;
    }
    __syncthreads();
    if (tid < L_) {
        float m = -1e30f;
        for (int j = 0; j < E; j++) if (sdst[j] == tid) m = fmaxf(m, ee[j]);
        float s = 0.f;
        float acc[64];
        #pragma unroll
        for (int f = 0; f < 64; f++) acc[f] = 0.f;
        for (int j = 0; j < E; j++) if (sdst[j] == tid) {
            float w = expf(ee[j] - m); s += w;
            const float* hs = &h2[ssrc[j] * 64];
            #pragma unroll
            for (int f = 0; f < 64; f++) acc[f] += w * hs[f];
        }
        float inv = 1.f / s;
        __half* orow = out + (size_t)g * (L_ * 64) + tid * 64;
        #pragma unroll
        for (int f = 0; f < 64; f++) {
            float v = acc[f] * inv + b2[f];
            orow[f] = __float2half(v > 0.f ? v : 0.f);
        }
    }
}

// =====================================================================
// mma helpers (fp16)
// =====================================================================
__device__ __forceinline__ void ldsm4(uint32_t& r0, uint32_t& r1, uint32_t& r2, uint32_t& r3,
                                      const __half* p) {
    uint32_t addr = (uint32_t)__cvta_generic_to_shared(p);
    asm volatile("ldmatrix.sync.aligned.m8n8.x4.shared.b16 {%0,%1,%2,%3}, [%4];\n"
                 : "=r"(r0), "=r"(r1), "=r"(r2), "=r"(r3) : "r"(addr));
}

__device__ __forceinline__ void ldsm4t(uint32_t& r0, uint32_t& r1, uint32_t& r2, uint32_t& r3,
                                       const __half* p) {
    uint32_t addr = (uint32_t)__cvta_generic_to_shared(p);
    asm volatile("ldmatrix.sync.aligned.m8n8.x4.trans.shared.b16 {%0,%1,%2,%3}, [%4];\n"
                 : "=r"(r0), "=r"(r1), "=r"(r2), "=r"(r3) : "r"(addr));
}

__device__ __forceinline__ void mma16816(float* c, const uint32_t* a, uint32_t b0, uint32_t b1) {
    asm volatile("mma.sync.aligned.m16n8k16.row.col.f32.f16.f16.f32 "
                 "{%0,%1,%2,%3}, {%4,%5,%6,%7}, {%8,%9}, {%0,%1,%2,%3};\n"
                 : "+f"(c[0]), "+f"(c[1]), "+f"(c[2]), "+f"(c[3])
                 : "r"(a[0]), "r"(a[1]), "r"(a[2]), "r"(a[3]), "r"(b0), "r"(b1));
}

__device__ __forceinline__ void cp16(uint32_t dst, const void* src) {
    asm volatile("cp.async.ca.shared.global [%0], [%1], 16;" :: "r"(dst), "l"(src));
}

// =====================================================================
// fp16 tensor-core GEMM, 64x128 block tile, single-term
// grid = (N/128, M/64); 8 warps (2x4), warp tile 32x32.
// flags: 1 relu, 2 +pe, 4 write fp32 C, 8 write fp16 Cf
// =====================================================================
static const int TSTR = 40;
// per stage: A(64 rows) + B(128 rows) = 192 rows
static const int GEMM_SMEM = 2 * 192 * TSTR * 2;  // 30720 B

__global__ __launch_bounds__(256) void gemm_half(
    const __half* __restrict__ A, const __half* __restrict__ B,
    const float* __restrict__ bias, float* __restrict__ C,
    __half* __restrict__ Cf,
    int M, int N, int K, int flags, const float* __restrict__ pe)
{
    extern __shared__ __half smb[];

    const int tid  = threadIdx.x;
    const int lane = tid & 31, warp = tid >> 5;
    const int wm = warp & 1, wn = warp >> 1;
    const int bm = blockIdx.y, bn = blockIdx.x;

    const __half* Ag = A + (size_t)(bm * 64) * K;
    const __half* Bg = B + (size_t)(bn * 128) * K;

    const int lrow = tid >> 2;          // 0..63
    const int lcol = (tid & 3) * 8;

    auto issue = [&](int st, int k0) {
        __half* stbase = smb + (size_t)st * 192 * TSTR;
        cp16((uint32_t)__cvta_generic_to_shared(stbase + lrow * TSTR + lcol),
             Ag + (size_t)lrow * K + k0 + lcol);
        __half* bl = stbase + 64 * TSTR;
        #pragma unroll
        for (int i = 0; i < 2; i++) {
            int row = lrow + i * 64;
            cp16((uint32_t)__cvta_generic_to_shared(bl + row * TSTR + lcol),
                 Bg + (size_t)row * K + k0 + lcol);
        }
        asm volatile("cp.async.commit_group;\n");
    };

    float c[2][4][4];
    #pragma unroll
    for (int i = 0; i < 2; i++)
        #pragma unroll
        for (int j = 0; j < 4; j++)
            #pragma unroll
            for (int q = 0; q < 4; q++) c[i][j][q] = 0.f;

    issue(0, 0);
    asm volatile("cp.async.wait_group 0;\n");
    __syncthreads();

    const int KT = K / 32;
    int cur = 0;
    for (int kt = 0; kt < KT; kt++) {
        if (kt + 1 < KT) issue(cur ^ 1, (kt + 1) * 32);

        const __half* pA = smb + (size_t)cur * 192 * TSTR;
        const __half* pB = pA + 64 * TSTR;

        #pragma unroll
        for (int kh = 0; kh < 2; kh++) {
            const int r  = lane & 15;
            const int cc = kh * 16 + ((lane >> 4) << 3);
            uint32_t ah[2][4], bh[2][4];
            #pragma unroll
            for (int mt = 0; mt < 2; mt++) {
                int row = wm * 32 + mt * 16 + r;
                ldsm4(ah[mt][0], ah[mt][1], ah[mt][2], ah[mt][3], pA + row * TSTR + cc);
            }
            #pragma unroll
            for (int g = 0; g < 2; g++) {
                int row = wn * 32 + g * 16 + r;
                ldsm4(bh[g][0], bh[g][1], bh[g][2], bh[g][3], pB + row * TSTR + cc);
            }
            #pragma unroll
            for (int mt = 0; mt < 2; mt++) {
                #pragma unroll
                for (int nt = 0; nt < 4; nt++) {
                    const int g = nt >> 1, s = nt & 1;
                    mma16816(c[mt][nt], ah[mt], bh[g][s], bh[g][s + 2]);
                }
            }
        }

        if (kt + 1 < KT) {
            asm volatile("cp.async.wait_group 0;\n");
        }
        __syncthreads();
        cur ^= 1;
    }

    #pragma unroll
    for (int mt = 0; mt < 2; mt++) {
        const int mbase = bm * 64 + wm * 32 + mt * 16 + (lane >> 2);
        #pragma unroll
        for (int half_ = 0; half_ < 2; half_++) {
            const int m = mbase + half_ * 8;
            const size_t rowoff = (size_t)m * N;
            const float* perow = (flags & 2) ? (pe + (size_t)(m & (S_ - 1)) * DM) : nullptr;
            #pragma unroll
            for (int nt = 0; nt < 4; nt++) {
                const int n = bn * 128 + wn * 32 + nt * 8 + (lane & 3) * 2;
                float v0 = c[mt][nt][half_ * 2 + 0] + bias[n];
                float v1 = c[mt][nt][half_ * 2 + 1] + bias[n + 1];
                if (flags & 1) { v0 = fmaxf(v0, 0.f); v1 = fmaxf(v1, 0.f); }
                if (flags & 2) { v0 += perow[n]; v1 += perow[n + 1]; }
                if (flags & 4) {
                    float2 o; o.x = v0; o.y = v1;
                    *(float2*)(C + rowoff + n) = o;
                }
                if (flags & 8) {
                    __half2 hh; hh.x = __float2half(v0); hh.y = __float2half(v1);
                    *(__half2*)(Cf + rowoff + n) = hh;
                }
            }
        }
    }
}

// =====================================================================
// fp16 tensor-core attention: block per (b, h, q-chunk 32), 8 warps.
// =====================================================================
static const int KSTR = 72;
static const int SSTR = 264;
static const int OF_K  = 0;
static const int OF_V  = OF_K + 256 * KSTR * 2;      // 36864
static const int OF_Q  = OF_V + 256 * KSTR * 2;      // 73728
static const int OF_S2 = OF_Q + 32 * KSTR * 2;       // 78336
static const int OF_SF = OF_S2 + 32 * SSTR * 2;      // 95232
static const int ATTN_SMEM = OF_SF + 32 * SSTR * 4;  // 129024

__global__ __launch_bounds__(256) void attn_mma(
    const __half* __restrict__ qkv, __half* __restrict__ out)
{
    extern __shared__ __align__(16) char smc[];
    __half* Ks = (__half*)(smc + OF_K);
    __half* Vs = (__half*)(smc + OF_V);
    __half* Qs = (__half*)(smc + OF_Q);
    __half* S2 = (__half*)(smc + OF_S2);
    float*  Sf = (float*)(smc + OF_SF);

    const int bh  = blockIdx.x;
    const int b   = bh >> 3, hd = bh & 7;
    const int q0  = blockIdx.y * 32;
    const int tid = threadIdx.x;
    const int lane = tid & 31, warp = tid >> 5;

    const size_t rowK = (size_t)b * S_ * (3 * DM) + hd * DH;
    {
        for (int i = tid; i < 256 * 8; i += 256) {
            int r = i >> 3, cc = (i & 7) * 8;
            size_t g = rowK + (size_t)r * (3 * DM);
            *(uint4*)&Ks[r * KSTR + cc] = *(const uint4*)(qkv + g + DM + cc);
            *(uint4*)&Vs[r * KSTR + cc] = *(const uint4*)(qkv + g + 2 * DM + cc);
        }
        for (int i = tid; i < 32 * 8; i += 256) {
            int r = i >> 3, cc = (i & 7) * 8;
            size_t g = rowK + (size_t)(q0 + r) * (3 * DM);
            *(uint4*)&Qs[r * KSTR + cc] = *(const uint4*)(qkv + g + cc);
        }
    }
    __syncthreads();

    const int wm = warp & 1, wn = warp >> 1;
    {
        float c[8][4];
        #pragma unroll
        for (int t = 0; t < 8; t++)
            #pragma unroll
            for (int q = 0; q < 4; q++) c[t][q] = 0.f;

        const int r  = lane & 15;
        const int c8 = (lane >> 4) << 3;
        #pragma unroll
        for (int k0 = 0; k0 < 64; k0 += 16) {
            uint32_t aq[4];
            ldsm4(aq[0], aq[1], aq[2], aq[3], Qs + (wm * 16 + r) * KSTR + k0 + c8);
            #pragma unroll
            for (int j = 0; j < 4; j++) {
                uint32_t bk[4];
                const int key = wn * 64 + j * 16 + r;
                ldsm4(bk[0], bk[1], bk[2], bk[3], Ks + key * KSTR + k0 + c8);
                #pragma unroll
                for (int s = 0; s < 2; s++)
                    mma16816(c[2 * j + s], aq, bk[s], bk[s + 2]);
            }
        }
        const int row0 = wm * 16 + (lane >> 2);
        #pragma unroll
        for (int t = 0; t < 8; t++) {
            const int col = wn * 64 + t * 8 + (lane & 3) * 2;
            Sf[row0 * SSTR + col]           = c[t][0] * 0.125f;
            Sf[row0 * SSTR + col + 1]       = c[t][1] * 0.125f;
            Sf[(row0 + 8) * SSTR + col]     = c[t][2] * 0.125f;
            Sf[(row0 + 8) * SSTR + col + 1] = c[t][3] * 0.125f;
        }
    }
    __syncthreads();

    for (int rr = warp; rr < 32; rr += 8) {
        float* row = &Sf[rr * SSTR];
        float mx = -1e30f;
        #pragma unroll
        for (int t = lane; t < 256; t += 32) mx = fmaxf(mx, row[t]);
        #pragma unroll
        for (int off = 16; off; off >>= 1) mx = fmaxf(mx, __shfl_xor_sync(0xffffffffu, mx, off));
        float s = 0.f;
        float ev[8];
        #pragma unroll
        for (int u = 0; u < 8; u++) {
            ev[u] = expf(row[lane + u * 32] - mx);
            s += ev[u];
        }
        #pragma unroll
        for (int off = 16; off; off >>= 1) s += __shfl_xor_sync(0xffffffffu, s, off);
        float inv = 1.f / s;
        #pragma unroll
        for (int u = 0; u < 8; u++)
            S2[rr * SSTR + lane + u * 32] = __float2half(ev[u] * inv);
    }
    __syncthreads();

    {
        float o[2][4];
        #pragma unroll
        for (int t = 0; t < 2; t++)
            #pragma unroll
            for (int q = 0; q < 4; q++) o[t][q] = 0.f;

        const int r  = lane & 15;
        const int c8 = (lane >> 4) << 3;
        #pragma unroll 4
        for (int k0 = 0; k0 < 256; k0 += 16) {
            uint32_t as_[4];
            ldsm4(as_[0], as_[1], as_[2], as_[3], S2 + (wm * 16 + r) * SSTR + k0 + c8);
            uint32_t bv[4];
            ldsm4t(bv[0], bv[1], bv[2], bv[3], Vs + (k0 + r) * KSTR + wn * 16 + c8);
            #pragma unroll
            for (int t = 0; t < 2; t++)
                mma16816(o[t], as_, bv[2 * t], bv[2 * t + 1]);
        }
        const int row0 = q0 + wm * 16 + (lane >> 2);
        #pragma unroll
        for (int t = 0; t < 2; t++) {
            const int d = hd * DH + wn * 16 + t * 8 + (lane & 3) * 2;
            size_t i0 = ((size_t)b * S_ + row0) * DM + d;
            size_t i1 = ((size_t)b * S_ + row0 + 8) * DM + d;
            out[i0]     = __float2half(o[t][0]);
            out[i0 + 1] = __float2half(o[t][1]);
            out[i1]     = __float2half(o[t][2]);
            out[i1 + 1] = __float2half(o[t][3]);
        }
    }
}

// =====================================================================
// Residual + LayerNorm; writes fp32 out + fp16
// =====================================================================
__global__ __launch_bounds__(128) void ln_kernel(
    const float* __restrict__ x, const float* __restrict__ r,
    const float* __restrict__ gam, const float* __restrict__ bet,
    float* __restrict__ out, __half* __restrict__ outh)
{
    const int row = blockIdx.x, tid = threadIdx.x;
    const float* xr = x + (size_t)row * DM;
    const float* rr = r + (size_t)row * DM;
    float v[4];
    float s = 0.f, s2 = 0.f;
    #pragma unroll
    for (int u = 0; u < 4; u++) {
        int i = tid + u * 128;
        v[u] = xr[i] + rr[i];
        s += v[u]; s2 += v[u] * v[u];
    }
    __shared__ float rs[4], rs2[4];
    #pragma unroll
    for (int off = 16; off; off >>= 1) {
        s  += __shfl_xor_sync(0xffffffffu, s,  off);
        s2 += __shfl_xor_sync(0xffffffffu, s2, off);
    }
    if ((tid & 31) == 0) { rs[tid >> 5] = s; rs2[tid >> 5] = s2; }
    __syncthreads();
    s  = rs[0] + rs[1] + rs[2] + rs[3];
    s2 = rs2[0] + rs2[1] + rs2[2] + rs2[3];
    float mean = s * (1.f / DM);
    float var  = s2 * (1.f / DM) - mean * mean;
    float k = rsqrtf(var + 1e-5f);
    float* orow = out + (size_t)row * DM;
    __half* hrow = outh + (size_t)row * DM;
    #pragma unroll
    for (int u = 0; u < 4; u++) {
        int i = tid + u * 128;
        float o = (v[u] - mean) * k * gam[i] + bet[i];
        orow[i] = o;
        hrow[i] = __float2half(o);
    }
}

// =====================================================================
// host launcher
// =====================================================================
static void run_gemm(const __half* A, const __half* B, const float* bias,
                     float* C, __half* Cf,
                     int M, int N, int K, int flags, const float* pe) {
    dim3 grid(N / 128, M / 64);
    gemm_half<<<grid, 256, GEMM_SMEM>>>(A, B, bias, C, Cf, M, N, K, flags, pe);
}

extern "C" void kernel_launch(void* const* d_in, const int* in_sizes, int n_in,
                              void* d_out, int out_size)
{
    const float* lm    = (const float*)d_in[0];
    const int*   ei    = (const int*)  d_in[1];
    const int    E     = in_sizes[1] / 2;
    const float* g1w   = (const float*)d_in[2];
    const float* g1as  = (const float*)d_in[3];
    const float* g1ad  = (const float*)d_in[4];
    const float* g1b   = (const float*)d_in[5];
    const float* g2w   = (const float*)d_in[6];
    const float* g2as  = (const float*)d_in[7];
    const float* g2ad  = (const float*)d_in[8];
    const float* g2b   = (const float*)d_in[9];
    const float* fcw   = (const float*)d_in[10];
    const float* fcb   = (const float*)d_in[11];
    const float* pe    = (const float*)d_in[12];
    const float* ipw   = (const float*)d_in[13];
    const float* ipb   = (const float*)d_in[14];
    const float* opw   = (const float*)d_in[15];
    const float* opb   = (const float*)d_in[16];
    const float* ln1g  = (const float*)d_in[17];
    const float* ln1b  = (const float*)d_in[18];
    const float* fw1   = (const float*)d_in[19];
    const float* fb1   = (const float*)d_in[20];
    const float* fw2   = (const float*)d_in[21];
    const float* fb2   = (const float*)d_in[22];
    const float* ln2g  = (const float*)d_in[23];
    const float* ln2b  = (const float*)d_in[24];

    __half *wf, *ghf, *gxf, *atf, *fff, *qkf;
    float *gx, *gproj;
    cudaGetSymbolAddress((void**)&wf,  w_f);
    cudaGetSymbolAddress((void**)&ghf, gh_f);
    cudaGetSymbolAddress((void**)&gxf, gx_f);
    cudaGetSymbolAddress((void**)&atf, at_f);
    cudaGetSymbolAddress((void**)&fff, ff_f);
    cudaGetSymbolAddress((void**)&qkf, qk_f);
    cudaGetSymbolAddress((void**)&gx,  g_x);
    cudaGetSymbolAddress((void**)&gproj, g_proj);

    cudaFuncSetAttribute(attn_mma,  cudaFuncAttributeMaxDynamicSharedMemorySize, ATTN_SMEM);
    cudaFuncSetAttribute(gemm_half, cudaFuncAttributeMaxDynamicSharedMemorySize, GEMM_SMEM);

    // 0. weight convert (fp32 -> fp16), once per launch
    cvt_kernel<<<2048, 256>>>(fcw, wf + OFF_FC, 512 * 4352);
    cvt_kernel<<<2048, 256>>>(ipw, wf + OFF_IP, NL * 3 * DM * DM);
    cvt_kernel<<<2048, 256>>>(opw, wf + OFF_OP, NL * DM * DM);
    cvt_kernel<<<2048, 256>>>(fw1, wf + OFF_F1, NL * DFF * DM);
    cvt_kernel<<<2048, 256>>>(fw2, wf + OFF_F2, NL * DM * DFF);

    // 1. GAT frontend -> fp16
    gat_kernel<<<G_, 128>>>(lm, ei, E, g1w, g1as, g1ad, g1b,
                            g2w, g2as, g2ad, g2b, ghf);

    // 2. FC + positional encoding -> fp32 gx + fp16
    run_gemm(ghf, wf + OFF_FC, fcb, gx, gxf, G_, DM, L_ * 64, 2 | 4 | 8, pe);

    // 3. transformer encoder layers
    for (int l = 0; l < NL; l++) {
        run_gemm(gxf, wf + OFF_IP + (size_t)l * 3 * DM * DM, ipb + (size_t)l * 3 * DM,
                 nullptr, qkf, G_, 3 * DM, DM, /*fp16*/ 8, nullptr);
        attn_mma<<<dim3(B_ * NH, S_ / 32), 256, ATTN_SMEM>>>(qkf, atf);
        run_gemm(atf, wf + OFF_OP + (size_t)l * DM * DM, opb + (size_t)l * DM,
                 gproj, nullptr, G_, DM, DM, 4, nullptr);
        ln_kernel<<<G_, 128>>>(gx, gproj, ln1g + (size_t)l * DM, ln1b + (size_t)l * DM,
                               gx, gxf);

        run_gemm(gxf, wf + OFF_F1 + (size_t)l * DFF * DM, fb1 + (size_t)l * DFF,
                 nullptr, fff, G_, DFF, DM, 1 | 8, nullptr);
        run_gemm(fff, wf + OFF_F2 + (size_t)l * DM * DFF, fb2 + (size_t)l * DM,
                 gproj, nullptr, G_, DM, DFF, 4, nullptr);
        float* outp = (l == NL - 1) ? (float*)d_out : gx;
        ln_kernel<<<G_, 128>>>(gx, gproj, ln2g + (size_t)l * DM, ln2b + (size_t)l * DM,
                               outp, gxf);
    }
    (void)n_in; (void)out_size;
}

// round 11
// speedup vs baseline: 4.8123x; 1.1425x over previous
#include <cuda_runtime.h>
#include <cuda_fp16.h>
#include <math.h>
#include <stdint.h>

// ---------------- problem constants ----------------
static const int B_  = 8;
static const int S_  = 256;
static const int G_  = 2048;
static const int L_  = 68;
static const int DM  = 512;
static const int NH  = 8;
static const int DH  = 64;
static const int DFF = 2048;
static const int NL  = 6;
static const int MAXE = 512;

// weight offsets in the packed fp16 weight buffer
static const size_t OFF_FC = 0;                    // 512*4352
static const size_t OFF_IP = 2228224;              // 6*1536*512
static const size_t OFF_OP = 6946816;              // 6*512*512
static const size_t OFF_F1 = 8519680;              // 6*2048*512
static const size_t OFF_F2 = 14811136;             // 6*512*2048
static const size_t W_TOT  = 21102592;

// ---------------- scratch (static device memory) ----------------
__device__ __half w_f [W_TOT];
__device__ __half gh_f[G_ * L_ * 64];
__device__ __half gx_f[G_ * DM];
__device__ __half at_f[G_ * DM];
__device__ __half ff_f[G_ * DFF];
__device__ __half qk_f[G_ * 3 * DM];
__device__ float g_x   [G_ * DM];
__device__ float g_proj[G_ * DM];

// =====================================================================
// fp32 -> fp16 convert (grid-stride)
// =====================================================================
__global__ __launch_bounds__(256) void cvt_kernel(
    const float* __restrict__ src, __half* __restrict__ dst, int n)
{
    int i = blockIdx.x * blockDim.x + threadIdx.x;
    int stride = gridDim.x * blockDim.x;
    for (; i < n; i += stride) dst[i] = __float2half(src[i]);
}

// =====================================================================
// GAT: both layers fused, one block per graph; writes fp16
// =====================================================================
__global__ __launch_bounds__(128) void gat_kernel(
    const float* __restrict__ lm, const int* __restrict__ ei, int E,
    const float* __restrict__ w1, const float* __restrict__ as1,
    const float* __restrict__ ad1, const float* __restrict__ b1,
    const float* __restrict__ w2, const float* __restrict__ as2,
    const float* __restrict__ ad2, const float* __restrict__ b2,
    __half* __restrict__ out)
{
    __shared__ float h1[L_ * 16];
    __shared__ float x2[L_ * 16];
    __shared__ float h2[L_ * 64];
    __shared__ float sa[L_], sd[L_];
    __shared__ float ee[MAXE];
    __shared__ int   ssrc[MAXE], sdst[MAXE];

    const int g   = blockIdx.x;
    const int tid = threadIdx.x;
    const float* x = lm + (size_t)g * L_ * 2;

    for (int j = tid; j < E; j += blockDim.x) { ssrc[j] = ei[j]; sdst[j] = ei[E + j]; }

    for (int i = tid; i < L_ * 16; i += blockDim.x) {
        int l = i >> 4, f = i & 15;
        h1[i] = w1[f * 2 + 0] * x[l * 2 + 0] + w1[f * 2 + 1] * x[l * 2 + 1];
    }
    __syncthreads();
    if (tid < L_) {
        float a = 0.f, d = 0.f;
        #pragma unroll
        for (int f = 0; f < 16; f++) { a += h1[tid * 16 + f] * as1[f]; d += h1[tid * 16 + f] * ad1[f]; }
        sa[tid] = a; sd[tid] = d;
    }
    __syncthreads();
    for (int j = tid; j < E; j += blockDim.x) {
        float v = sa[ssrc[j]] + sd[sdst[j]];
        ee[j] = v > 0.f ? v : 0.2f * v;
    }
    __syncthreads();
    if (tid < L_) {
        float m = -1e30f;
        for (int j = 0; j < E; j++) if (sdst[j] == tid) m = fmaxf(m, ee[j]);
        float s = 0.f;
        float acc[16];
        #pragma unroll
        for (int f = 0; f < 16; f++) acc[f] = 0.f;
        for (int j = 0; j < E; j++) if (sdst[j] == tid) {
            float w = expf(ee[j] - m); s += w;
            const float* hs = &h1[ssrc[j] * 16];
            #pragma unroll
            for (int f = 0; f < 16; f++) acc[f] += w * hs[f];
        }
        float inv = 1.f / s;
        #pragma unroll
        for (int f = 0; f < 16; f++) {
            float v = acc[f] * inv + b1[f];
            x2[tid * 16 + f] = v > 0.f ? v : 0.f;
        }
    }
    __syncthreads();

    for (int i = tid; i < L_ * 64; i += blockDim.x) {
        int l = i >> 6, f = i & 63;
        float a = 0.f;
        const float* xr = &x2[l * 16];
        const float* wr = &w2[f * 16];
        #pragma unroll
        for (int c = 0; c < 16; c++) a += xr[c] * wr[c];
        h2[i] = a;
    }
    __syncthreads();
    if (tid < L_) {
        float a = 0.f, d = 0.f;
        const float* hr = &h2[tid * 64];
        #pragma unroll
        for (int f = 0; f < 64; f++) { a += hr[f] * as2[f]; d += hr[f] * ad2[f]; }
        sa[tid] = a; sd[tid] = d;
    }
    __syncthreads();
    for (int j = tid; j < E; j += blockDim.x) {
        float v = sa[ssrc[j]] + sd[sdst[j]];
        ee[j] = v > 0.f ? v : 0.2f * v;
    }
    __syncthreads();
    if (tid < L_) {
        float m = -1e30f;
        for (int j = 0; j < E; j++) if (sdst[j] == tid) m = fmaxf(m, ee[j]);
        float s = 0.f;
        float acc[64];
        #pragma unroll
        for (int f = 0; f < 64; f++) acc[f] = 0.f;
        for (int j = 0; j < E; j++) if (sdst[j] == tid) {
            float w = expf(ee[j] - m); s += w;
            const float* hs = &h2[ssrc[j] * 64];
            #pragma unroll
            for (int f = 0; f < 64; f++) acc[f] += w * hs[f];
        }
        float inv = 1.f / s;
        __half* orow = out + (size_t)g * (L_ * 64) + tid * 64;
        #pragma unroll
        for (int f = 0; f < 64; f++) {
            float v = acc[f] * inv + b2[f];
            orow[f] = __float2half(v > 0.f ? v : 0.f);
        }
    }
}

// =====================================================================
// mma helpers (fp16)
// =====================================================================
__device__ __forceinline__ void ldsm4(uint32_t& r0, uint32_t& r1, uint32_t& r2, uint32_t& r3,
                                      const __half* p) {
    uint32_t addr = (uint32_t)__cvta_generic_to_shared(p);
    asm volatile("ldmatrix.sync.aligned.m8n8.x4.shared.b16 {%0,%1,%2,%3}, [%4];\n"
                 : "=r"(r0), "=r"(r1), "=r"(r2), "=r"(r3) : "r"(addr));
}

__device__ __forceinline__ void ldsm4t(uint32_t& r0, uint32_t& r1, uint32_t& r2, uint32_t& r3,
                                       const __half* p) {
    uint32_t addr = (uint32_t)__cvta_generic_to_shared(p);
    asm volatile("ldmatrix.sync.aligned.m8n8.x4.trans.shared.b16 {%0,%1,%2,%3}, [%4];\n"
                 : "=r"(r0), "=r"(r1), "=r"(r2), "=r"(r3) : "r"(addr));
}

__device__ __forceinline__ void mma16816(float* c, const uint32_t* a, uint32_t b0, uint32_t b1) {
    asm volatile("mma.sync.aligned.m16n8k16.row.col.f32.f16.f16.f32 "
                 "{%0,%1,%2,%3}, {%4,%5,%6,%7}, {%8,%9}, {%0,%1,%2,%3};\n"
                 : "+f"(c[0]), "+f"(c[1]), "+f"(c[2]), "+f"(c[3])
                 : "r"(a[0]), "r"(a[1]), "r"(a[2]), "r"(a[3]), "r"(b0), "r"(b1));
}

__device__ __forceinline__ void cp16(uint32_t dst, const void* src) {
    asm volatile("cp.async.ca.shared.global [%0], [%1], 16;" :: "r"(dst), "l"(src));
}

// =====================================================================
// fp16 tensor-core GEMM, 64x128 block tile, K staged by 64.
// grid = (N/128, M/64); 8 warps (2x4), warp tile 32x32.
// flags: 1 relu, 2 +pe, 4 write fp32 C, 8 write fp16 Cf
// =====================================================================
static const int TSTR = 72;   // k64 row stride (+8 pad) -> conflict-free ldsm
static const int GEMM_SMEM = 2 * 192 * TSTR * 2;  // 55296 B

__global__ __launch_bounds__(256) void gemm_half(
    const __half* __restrict__ A, const __half* __restrict__ B,
    const float* __restrict__ bias, float* __restrict__ C,
    __half* __restrict__ Cf,
    int M, int N, int K, int flags, const float* __restrict__ pe)
{
    extern __shared__ __half smb[];

    const int tid  = threadIdx.x;
    const int lane = tid & 31, warp = tid >> 5;
    const int wm = warp & 1, wn = warp >> 1;
    const int bm = blockIdx.y, bn = blockIdx.x;

    const __half* Ag = A + (size_t)(bm * 64) * K;
    const __half* Bg = B + (size_t)(bn * 128) * K;

    // load: 192 rows x 64 halfs = 1536 16B-chunks; 6 per thread
    auto issue = [&](int st, int k0) {
        __half* stbase = smb + (size_t)st * 192 * TSTR;
        #pragma unroll
        for (int i = 0; i < 6; i++) {
            int cix = tid + i * 256;
            int row = cix >> 3;
            int sub = (cix & 7) * 8;
            const __half* g = (row < 64) ? (Ag + (size_t)row * K)
                                         : (Bg + (size_t)(row - 64) * K);
            cp16((uint32_t)__cvta_generic_to_shared(stbase + row * TSTR + sub),
                 g + k0 + sub);
        }
        asm volatile("cp.async.commit_group;\n");
    };

    float c[2][4][4];
    #pragma unroll
    for (int i = 0; i < 2; i++)
        #pragma unroll
        for (int j = 0; j < 4; j++)
            #pragma unroll
            for (int q = 0; q < 4; q++) c[i][j][q] = 0.f;

    issue(0, 0);
    asm volatile("cp.async.wait_group 0;\n");
    __syncthreads();

    const int KT = K >> 6;
    int cur = 0;
    for (int kt = 0; kt < KT; kt++) {
        if (kt + 1 < KT) issue(cur ^ 1, (kt + 1) * 64);

        const __half* pA = smb + (size_t)cur * 192 * TSTR;
        const __half* pB = pA + 64 * TSTR;

        #pragma unroll
        for (int kh = 0; kh < 4; kh++) {
            const int r  = lane & 15;
            const int cc = kh * 16 + ((lane >> 4) << 3);
            uint32_t ah[2][4], bh[2][4];
            #pragma unroll
            for (int mt = 0; mt < 2; mt++) {
                int row = wm * 32 + mt * 16 + r;
                ldsm4(ah[mt][0], ah[mt][1], ah[mt][2], ah[mt][3], pA + row * TSTR + cc);
            }
            #pragma unroll
            for (int g = 0; g < 2; g++) {
                int row = wn * 32 + g * 16 + r;
                ldsm4(bh[g][0], bh[g][1], bh[g][2], bh[g][3], pB + row * TSTR + cc);
            }
            #pragma unroll
            for (int mt = 0; mt < 2; mt++) {
                #pragma unroll
                for (int nt = 0; nt < 4; nt++) {
                    const int g = nt >> 1, s = nt & 1;
                    mma16816(c[mt][nt], ah[mt], bh[g][s], bh[g][s + 2]);
                }
            }
        }

        if (kt + 1 < KT) {
            asm volatile("cp.async.wait_group 0;\n");
        }
        __syncthreads();
        cur ^= 1;
    }

    #pragma unroll
    for (int mt = 0; mt < 2; mt++) {
        const int mbase = bm * 64 + wm * 32 + mt * 16 + (lane >> 2);
        #pragma unroll
        for (int half_ = 0; half_ < 2; half_++) {
            const int m = mbase + half_ * 8;
            const size_t rowoff = (size_t)m * N;
            const float* perow = (flags & 2) ? (pe + (size_t)(m & (S_ - 1)) * DM) : nullptr;
            #pragma unroll
            for (int nt = 0; nt < 4; nt++) {
                const int n = bn * 128 + wn * 32 + nt * 8 + (lane & 3) * 2;
                float v0 = c[mt][nt][half_ * 2 + 0] + bias[n];
                float v1 = c[mt][nt][half_ * 2 + 1] + bias[n + 1];
                if (flags & 1) { v0 = fmaxf(v0, 0.f); v1 = fmaxf(v1, 0.f); }
                if (flags & 2) { v0 += perow[n]; v1 += perow[n + 1]; }
                if (flags & 4) {
                    float2 o; o.x = v0; o.y = v1;
                    *(float2*)(C + rowoff + n) = o;
                }
                if (flags & 8) {
                    __half2 hh; hh.x = __float2half(v0); hh.y = __float2half(v1);
                    *(__half2*)(Cf + rowoff + n) = hh;
                }
            }
        }
    }
}

// =====================================================================
// fp16 tensor-core attention: block per (b, h, q-chunk 32), 8 warps.
// Register-resident softmax (no fp32 score plane); smem 96 KB -> 2/SM.
// =====================================================================
static const int KSTR = 72;
static const int SSTR = 264;
static const int OF_K  = 0;
static const int OF_V  = OF_K + 256 * KSTR * 2;      // 36864
static const int OF_Q  = OF_V + 256 * KSTR * 2;      // 73728
static const int OF_S2 = OF_Q + 32 * KSTR * 2;       // 78336
static const int OF_RM = OF_S2 + 32 * SSTR * 2;      // 95232 (Pmax [32][4])
static const int OF_RS = OF_RM + 32 * 4 * 4;         // 95744 (Psum [32][4])
static const int ATTN_SMEM = OF_RS + 32 * 4 * 4;     // 96256

__global__ __launch_bounds__(256) void attn_mma(
    const __half* __restrict__ qkv, __half* __restrict__ out)
{
    extern __shared__ __align__(16) char smc[];
    __half* Ks = (__half*)(smc + OF_K);
    __half* Vs = (__half*)(smc + OF_V);
    __half* Qs = (__half*)(smc + OF_Q);
    __half* S2 = (__half*)(smc + OF_S2);
    float (*Pmax)[4] = (float (*)[4])(smc + OF_RM);
    float (*Psum)[4] = (float (*)[4])(smc + OF_RS);

    const int bh  = blockIdx.x;
    const int b   = bh >> 3, hd = bh & 7;
    const int q0  = blockIdx.y * 32;
    const int tid = threadIdx.x;
    const int lane = tid & 31, warp = tid >> 5;

    const size_t rowK = (size_t)b * S_ * (3 * DM) + hd * DH;
    {
        for (int i = tid; i < 256 * 8; i += 256) {
            int r = i >> 3, cc = (i & 7) * 8;
            size_t g = rowK + (size_t)r * (3 * DM);
            *(uint4*)&Ks[r * KSTR + cc] = *(const uint4*)(qkv + g + DM + cc);
            *(uint4*)&Vs[r * KSTR + cc] = *(const uint4*)(qkv + g + 2 * DM + cc);
        }
        for (int i = tid; i < 32 * 8; i += 256) {
            int r = i >> 3, cc = (i & 7) * 8;
            size_t g = rowK + (size_t)(q0 + r) * (3 * DM);
            *(uint4*)&Qs[r * KSTR + cc] = *(const uint4*)(qkv + g + cc);
        }
    }
    __syncthreads();

    const int wm = warp & 1, wn = warp >> 1;

    // -------- QK^T into registers --------
    float c[8][4];
    #pragma unroll
    for (int t = 0; t < 8; t++)
        #pragma unroll
        for (int q = 0; q < 4; q++) c[t][q] = 0.f;
    {
        const int r  = lane & 15;
        const int c8 = (lane >> 4) << 3;
        #pragma unroll
        for (int k0 = 0; k0 < 64; k0 += 16) {
            uint32_t aq[4];
            ldsm4(aq[0], aq[1], aq[2], aq[3], Qs + (wm * 16 + r) * KSTR + k0 + c8);
            #pragma unroll
            for (int j = 0; j < 4; j++) {
                uint32_t bk[4];
                const int key = wn * 64 + j * 16 + r;
                ldsm4(bk[0], bk[1], bk[2], bk[3], Ks + key * KSTR + k0 + c8);
                #pragma unroll
                for (int s = 0; s < 2; s++)
                    mma16816(c[2 * j + s], aq, bk[s], bk[s + 2]);
            }
        }
        #pragma unroll
        for (int t = 0; t < 8; t++)
            #pragma unroll
            for (int q = 0; q < 4; q++) c[t][q] *= 0.125f;
    }

    // -------- register softmax: rows r0 (c[t][0..1]) and r0+8 (c[t][2..3]) --------
    const int r0 = wm * 16 + (lane >> 2);
    {
        float mx0 = -1e30f, mx1 = -1e30f;
        #pragma unroll
        for (int t = 0; t < 8; t++) {
            mx0 = fmaxf(mx0, fmaxf(c[t][0], c[t][1]));
            mx1 = fmaxf(mx1, fmaxf(c[t][2], c[t][3]));
        }
        #pragma unroll
        for (int off = 1; off <= 2; off <<= 1) {
            mx0 = fmaxf(mx0, __shfl_xor_sync(0xffffffffu, mx0, off));
            mx1 = fmaxf(mx1, __shfl_xor_sync(0xffffffffu, mx1, off));
        }
        if ((lane & 3) == 0) { Pmax[r0][wn] = mx0; Pmax[r0 + 8][wn] = mx1; }
        __syncthreads();
        float m0 = fmaxf(fmaxf(Pmax[r0][0], Pmax[r0][1]), fmaxf(Pmax[r0][2], Pmax[r0][3]));
        float m1 = fmaxf(fmaxf(Pmax[r0 + 8][0], Pmax[r0 + 8][1]),
                         fmaxf(Pmax[r0 + 8][2], Pmax[r0 + 8][3]));
        float s0 = 0.f, s1 = 0.f;
        #pragma unroll
        for (int t = 0; t < 8; t++) {
            c[t][0] = expf(c[t][0] - m0); c[t][1] = expf(c[t][1] - m0);
            s0 += c[t][0] + c[t][1];
            c[t][2] = expf(c[t][2] - m1); c[t][3] = expf(c[t][3] - m1);
            s1 += c[t][2] + c[t][3];
        }
        #pragma unroll
        for (int off = 1; off <= 2; off <<= 1) {
            s0 += __shfl_xor_sync(0xffffffffu, s0, off);
            s1 += __shfl_xor_sync(0xffffffffu, s1, off);
        }
        if ((lane & 3) == 0) { Psum[r0][wn] = s0; Psum[r0 + 8][wn] = s1; }
        __syncthreads();
        float inv0 = 1.f / (Psum[r0][0] + Psum[r0][1] + Psum[r0][2] + Psum[r0][3]);
        float inv1 = 1.f / (Psum[r0 + 8][0] + Psum[r0 + 8][1] +
                            Psum[r0 + 8][2] + Psum[r0 + 8][3]);
        #pragma unroll
        for (int t = 0; t < 8; t++) {
            const int col = wn * 64 + t * 8 + (lane & 3) * 2;
            __half2 h0; h0.x = __float2half(c[t][0] * inv0); h0.y = __float2half(c[t][1] * inv0);
            __half2 h1; h1.x = __float2half(c[t][2] * inv1); h1.y = __float2half(c[t][3] * inv1);
            *(__half2*)&S2[r0 * SSTR + col]       = h0;
            *(__half2*)&S2[(r0 + 8) * SSTR + col] = h1;
        }
    }
    __syncthreads();

    // -------- S @ V --------
    {
        float o[2][4];
        #pragma unroll
        for (int t = 0; t < 2; t++)
            #pragma unroll
            for (int q = 0; q < 4; q++) o[t][q] = 0.f;

        const int r  = lane & 15;
        const int c8 = (lane >> 4) << 3;
        #pragma unroll 4
        for (int k0 = 0; k0 < 256; k0 += 16) {
            uint32_t as_[4];
            ldsm4(as_[0], as_[1], as_[2], as_[3], S2 + (wm * 16 + r) * SSTR + k0 + c8);
            uint32_t bv[4];
            ldsm4t(bv[0], bv[1], bv[2], bv[3], Vs + (k0 + r) * KSTR + wn * 16 + c8);
            #pragma unroll
            for (int t = 0; t < 2; t++)
                mma16816(o[t], as_, bv[2 * t], bv[2 * t + 1]);
        }
        const int row0 = q0 + wm * 16 + (lane >> 2);
        #pragma unroll
        for (int t = 0; t < 2; t++) {
            const int d = hd * DH + wn * 16 + t * 8 + (lane & 3) * 2;
            size_t i0 = ((size_t)b * S_ + row0) * DM + d;
            size_t i1 = ((size_t)b * S_ + row0 + 8) * DM + d;
            __half2 a; a.x = __float2half(o[t][0]); a.y = __float2half(o[t][1]);
            __half2 bb; bb.x = __float2half(o[t][2]); bb.y = __float2half(o[t][3]);
            *(__half2*)&out[i0] = a;
            *(__half2*)&out[i1] = bb;
        }
    }
}

// =====================================================================
// Residual + LayerNorm; writes fp32 out + fp16
// =====================================================================
__global__ __launch_bounds__(128) void ln_kernel(
    const float* __restrict__ x, const float* __restrict__ r,
    const float* __restrict__ gam, const float* __restrict__ bet,
    float* __restrict__ out, __half* __restrict__ outh)
{
    const int row = blockIdx.x, tid = threadIdx.x;
    const float* xr = x + (size_t)row * DM;
    const float* rr = r + (size_t)row * DM;
    float v[4];
    float s = 0.f, s2 = 0.f;
    #pragma unroll
    for (int u = 0; u < 4; u++) {
        int i = tid + u * 128;
        v[u] = xr[i] + rr[i];
        s += v[u]; s2 += v[u] * v[u];
    }
    __shared__ float rs[4], rs2[4];
    #pragma unroll
    for (int off = 16; off; off >>= 1) {
        s  += __shfl_xor_sync(0xffffffffu, s,  off);
        s2 += __shfl_xor_sync(0xffffffffu, s2, off);
    }
    if ((tid & 31) == 0) { rs[tid >> 5] = s; rs2[tid >> 5] = s2; }
    __syncthreads();
    s  = rs[0] + rs[1] + rs[2] + rs[3];
    s2 = rs2[0] + rs2[1] + rs2[2] + rs2[3];
    float mean = s * (1.f / DM);
    float var  = s2 * (1.f / DM) - mean * mean;
    float k = rsqrtf(var + 1e-5f);
    float* orow = out + (size_t)row * DM;
    __half* hrow = outh + (size_t)row * DM;
    #pragma unroll
    for (int u = 0; u < 4; u++) {
        int i = tid + u * 128;
        float o = (v[u] - mean) * k * gam[i] + bet[i];
        orow[i] = o;
        hrow[i] = __float2half(o);
    }
}

// =====================================================================
// host launcher
// =====================================================================
static void run_gemm(const __half* A, const __half* B, const float* bias,
                     float* C, __half* Cf,
                     int M, int N, int K, int flags, const float* pe) {
    dim3 grid(N / 128, M / 64);
    gemm_half<<<grid, 256, GEMM_SMEM>>>(A, B, bias, C, Cf, M, N, K, flags, pe);
}

extern "C" void kernel_launch(void* const* d_in, const int* in_sizes, int n_in,
                              void* d_out, int out_size)
{
    const float* lm    = (const float*)d_in[0];
    const int*   ei    = (const int*)  d_in[1];
    const int    E     = in_sizes[1] / 2;
    const float* g1w   = (const float*)d_in[2];
    const float* g1as  = (const float*)d_in[3];
    const float* g1ad  = (const float*)d_in[4];
    const float* g1b   = (const float*)d_in[5];
    const float* g2w   = (const float*)d_in[6];
    const float* g2as  = (const float*)d_in[7];
    const float* g2ad  = (const float*)d_in[8];
    const float* g2b   = (const float*)d_in[9];
    const float* fcw   = (const float*)d_in[10];
    const float* fcb   = (const float*)d_in[11];
    const float* pe    = (const float*)d_in[12];
    const float* ipw   = (const float*)d_in[13];
    const float* ipb   = (const float*)d_in[14];
    const float* opw   = (const float*)d_in[15];
    const float* opb   = (const float*)d_in[16];
    const float* ln1g  = (const float*)d_in[17];
    const float* ln1b  = (const float*)d_in[18];
    const float* fw1   = (const float*)d_in[19];
    const float* fb1   = (const float*)d_in[20];
    const float* fw2   = (const float*)d_in[21];
    const float* fb2   = (const float*)d_in[22];
    const float* ln2g  = (const float*)d_in[23];
    const float* ln2b  = (const float*)d_in[24];

    __half *wf, *ghf, *gxf, *atf, *fff, *qkf;
    float *gx, *gproj;
    cudaGetSymbolAddress((void**)&wf,  w_f);
    cudaGetSymbolAddress((void**)&ghf, gh_f);
    cudaGetSymbolAddress((void**)&gxf, gx_f);
    cudaGetSymbolAddress((void**)&atf, at_f);
    cudaGetSymbolAddress((void**)&fff, ff_f);
    cudaGetSymbolAddress((void**)&qkf, qk_f);
    cudaGetSymbolAddress((void**)&gx,  g_x);
    cudaGetSymbolAddress((void**)&gproj, g_proj);

    cudaFuncSetAttribute(attn_mma,  cudaFuncAttributeMaxDynamicSharedMemorySize, ATTN_SMEM);
    cudaFuncSetAttribute(gemm_half, cudaFuncAttributeMaxDynamicSharedMemorySize, GEMM_SMEM);

    // 0. weight convert (fp32 -> fp16), once per launch
    cvt_kernel<<<2048, 256>>>(fcw, wf + OFF_FC, 512 * 4352);
    cvt_kernel<<<2048, 256>>>(ipw, wf + OFF_IP, NL * 3 * DM * DM);
    cvt_kernel<<<2048, 256>>>(opw, wf + OFF_OP, NL * DM * DM);
    cvt_kernel<<<2048, 256>>>(fw1, wf + OFF_F1, NL * DFF * DM);
    cvt_kernel<<<2048, 256>>>(fw2, wf + OFF_F2, NL * DM * DFF);

    // 1. GAT frontend -> fp16
    gat_kernel<<<G_, 128>>>(lm, ei, E, g1w, g1as, g1ad, g1b,
                            g2w, g2as, g2ad, g2b, ghf);

    // 2. FC + positional encoding -> fp32 gx + fp16
    run_gemm(ghf, wf + OFF_FC, fcb, gx, gxf, G_, DM, L_ * 64, 2 | 4 | 8, pe);

    // 3. transformer encoder layers
    for (int l = 0; l < NL; l++) {
        run_gemm(gxf, wf + OFF_IP + (size_t)l * 3 * DM * DM, ipb + (size_t)l * 3 * DM,
                 nullptr, qkf, G_, 3 * DM, DM, /*fp16*/ 8, nullptr);
        attn_mma<<<dim3(B_ * NH, S_ / 32), 256, ATTN_SMEM>>>(qkf, atf);
        run_gemm(atf, wf + OFF_OP + (size_t)l * DM * DM, opb + (size_t)l * DM,
                 gproj, nullptr, G_, DM, DM, 4, nullptr);
        ln_kernel<<<G_, 128>>>(gx, gproj, ln1g + (size_t)l * DM, ln1b + (size_t)l * DM,
                               gx, gxf);

        run_gemm(gxf, wf + OFF_F1 + (size_t)l * DFF * DM, fb1 + (size_t)l * DFF,
                 nullptr, fff, G_, DFF, DM, 1 | 8, nullptr);
        run_gemm(fff, wf + OFF_F2 + (size_t)l * DM * DFF, fb2 + (size_t)l * DM,
                 gproj, nullptr, G_, DM, DFF, 4, nullptr);
        float* outp = (l == NL - 1) ? (float*)d_out : gx;
        ln_kernel<<<G_, 128>>>(gx, gproj, ln2g + (size_t)l * DM, ln2b + (size_t)l * DM,
                               outp, gxf);
    }
    (void)n_in; (void)out_size;
}

// round 14
// speedup vs baseline: 4.8502x; 1.0079x over previous
#include <cuda_runtime.h>
#include <cuda_fp16.h>
#include <math.h>
#include <stdint.h>

// ---------------- problem constants ----------------
static const int B_  = 8;
static const int S_  = 256;
static const int G_  = 2048;
static const int L_  = 68;
static const int DM  = 512;
static const int NH  = 8;
static const int DH  = 64;
static const int DFF = 2048;
static const int NL  = 6;
static const int MAXE = 512;

// weight offsets in the packed fp16 weight buffer (all divisible by 8)
static const size_t OFF_FC = 0;                    // 512*4352   = 2228224
static const size_t OFF_IP = 2228224;              // 6*1536*512 = 4718592
static const size_t OFF_OP = 6946816;              // 6*512*512  = 1572864
static const size_t OFF_F1 = 8519680;              // 6*2048*512 = 6291456
static const size_t OFF_F2 = 14811136;             // 6*512*2048 = 6291456
static const size_t W_TOT  = 21102592;

// ---------------- scratch (static device memory) ----------------
__device__ __half w_f [W_TOT];
__device__ __half gh_f[G_ * L_ * 64];
__device__ __half gx_f[G_ * DM];
__device__ __half at_f[G_ * DM];
__device__ __half ff_f[G_ * DFF];
__device__ __half qk_f[G_ * 3 * DM];
__device__ float g_x   [G_ * DM];
__device__ float g_proj[G_ * DM];

// =====================================================================
// merged fp32 -> fp16 weight convert, vectorized by 8
// =====================================================================
__global__ __launch_bounds__(256) void cvt_all(
    const float* __restrict__ s_fc, const float* __restrict__ s_ip,
    const float* __restrict__ s_op, const float* __restrict__ s_f1,
    const float* __restrict__ s_f2, __half* __restrict__ dst)
{
    const size_t NV = W_TOT / 8;   // groups of 8 elems
    size_t i = (size_t)blockIdx.x * blockDim.x + threadIdx.x;
    size_t stride = (size_t)gridDim.x * blockDim.x;
    for (; i < NV; i += stride) {
        size_t e = i * 8;
        const float* src;
        if      (e < OFF_IP) src = s_fc + e;
        else if (e < OFF_OP) src = s_ip + (e - OFF_IP);
        else if (e < OFF_F1) src = s_op + (e - OFF_OP);
        else if (e < OFF_F2) src = s_f1 + (e - OFF_F1);
        else                 src = s_f2 + (e - OFF_F2);
        float4 a = *(const float4*)(src);
        float4 b = *(const float4*)(src + 4);
        __half2 h[4];
        h[0].x = __float2half(a.x); h[0].y = __float2half(a.y);
        h[1].x = __float2half(a.z); h[1].y = __float2half(a.w);
        h[2].x = __float2half(b.x); h[2].y = __float2half(b.y);
        h[3].x = __float2half(b.z); h[3].y = __float2half(b.w);
        *(uint4*)(dst + e) = *(uint4*)h;
    }
}

// =====================================================================
// GAT: both layers fused, one block per graph; writes fp16
// =====================================================================
__global__ __launch_bounds__(128) void gat_kernel(
    const float* __restrict__ lm, const int* __restrict__ ei, int E,
    const float* __restrict__ w1, const float* __restrict__ as1,
    const float* __restrict__ ad1, const float* __restrict__ b1,
    const float* __restrict__ w2, const float* __restrict__ as2,
    const float* __restrict__ ad2, const float* __restrict__ b2,
    __half* __restrict__ out)
{
    __shared__ float h1[L_ * 16];
    __shared__ float x2[L_ * 16];
    __shared__ float h2[L_ * 64];
    __shared__ float sa[L_], sd[L_];
    __shared__ float ee[MAXE];
    __shared__ int   ssrc[MAXE], sdst[MAXE];

    const int g   = blockIdx.x;
    const int tid = threadIdx.x;
    const float* x = lm + (size_t)g * L_ * 2;

    for (int j = tid; j < E; j += blockDim.x) { ssrc[j] = ei[j]; sdst[j] = ei[E + j]; }

    for (int i = tid; i < L_ * 16; i += blockDim.x) {
        int l = i >> 4, f = i & 15;
        h1[i] = w1[f * 2 + 0] * x[l * 2 + 0] + w1[f * 2 + 1] * x[l * 2 + 1];
    }
    __syncthreads();
    if (tid < L_) {
        float a = 0.f, d = 0.f;
        #pragma unroll
        for (int f = 0; f < 16; f++) { a += h1[tid * 16 + f] * as1[f]; d += h1[tid * 16 + f] * ad1[f]; }
        sa[tid] = a; sd[tid] = d;
    }
    __syncthreads();
    for (int j = tid; j < E; j += blockDim.x) {
        float v = sa[ssrc[j]] + sd[sdst[j]];
        ee[j] = v > 0.f ? v : 0.2f * v;
    }
    __syncthreads();
    if (tid < L_) {
        float m = -1e30f;
        for (int j = 0; j < E; j++) if (sdst[j] == tid) m = fmaxf(m, ee[j]);
        float s = 0.f;
        float acc[16];
        #pragma unroll
        for (int f = 0; f < 16; f++) acc[f] = 0.f;
        for (int j = 0; j < E; j++) if (sdst[j] == tid) {
            float w = expf(ee[j] - m); s += w;
            const float* hs = &h1[ssrc[j] * 16];
            #pragma unroll
            for (int f = 0; f < 16; f++) acc[f] += w * hs[f];
        }
        float inv = 1.f / s;
        #pragma unroll
        for (int f = 0; f < 16; f++) {
            float v = acc[f] * inv + b1[f];
            x2[tid * 16 + f] = v > 0.f ? v : 0.f;
        }
    }
    __syncthreads();

    for (int i = tid; i < L_ * 64; i += blockDim.x) {
        int l = i >> 6, f = i & 63;
        float a = 0.f;
        const float* xr = &x2[l * 16];
        const float* wr = &w2[f * 16];
        #pragma unroll
        for (int c = 0; c < 16; c++) a += xr[c] * wr[c];
        h2[i] = a;
    }
    __syncthreads();
    if (tid < L_) {
        float a = 0.f, d = 0.f;
        const float* hr = &h2[tid * 64];
        #pragma unroll
        for (int f = 0; f < 64; f++) { a += hr[f] * as2[f]; d += hr[f] * ad2[f]; }
        sa[tid] = a; sd[tid] = d;
    }
    __syncthreads();
    for (int j = tid; j < E; j += blockDim.x) {
        float v = sa[ssrc[j]] + sd[sdst[j]];
        ee[j] = v > 0.f ? v : 0.2f * v;
    }
    __syncthreads();
    if (tid < L_) {
        float m = -1e30f;
        for (int j = 0; j < E; j++) if (sdst[j] == tid) m = fmaxf(m, ee[j]);
        float s = 0.f;
        float acc[64];
        #pragma unroll
        for (int f = 0; f < 64; f++) acc[f] = 0.f;
        for (int j = 0; j < E; j++) if (sdst[j] == tid) {
            float w = expf(ee[j] - m); s += w;
            const float* hs = &h2[ssrc[j] * 64];
            #pragma unroll
            for (int f = 0; f < 64; f++) acc[f] += w * hs[f];
        }
        float inv = 1.f / s;
        __half* orow = out + (size_t)g * (L_ * 64) + tid * 64;
        #pragma unroll
        for (int f = 0; f < 64; f++) {
            float v = acc[f] * inv + b2[f];
            orow[f] = __float2half(v > 0.f ? v : 0.f);
        }
    }
}

// =====================================================================
// mma helpers (fp16)
// =====================================================================
__device__ __forceinline__ void ldsm4(uint32_t& r0, uint32_t& r1, uint32_t& r2, uint32_t& r3,
                                      const __half* p) {
    uint32_t addr = (uint32_t)__cvta_generic_to_shared(p);
    asm volatile("ldmatrix.sync.aligned.m8n8.x4.shared.b16 {%0,%1,%2,%3}, [%4];\n"
                 : "=r"(r0), "=r"(r1), "=r"(r2), "=r"(r3) : "r"(addr));
}

__device__ __forceinline__ void ldsm4t(uint32_t& r0, uint32_t& r1, uint32_t& r2, uint32_t& r3,
                                       const __half* p) {
    uint32_t addr = (uint32_t)__cvta_generic_to_shared(p);
    asm volatile("ldmatrix.sync.aligned.m8n8.x4.trans.shared.b16 {%0,%1,%2,%3}, [%4];\n"
                 : "=r"(r0), "=r"(r1), "=r"(r2), "=r"(r3) : "r"(addr));
}

__device__ __forceinline__ void mma16816(float* c, const uint32_t* a, uint32_t b0, uint32_t b1) {
    asm volatile("mma.sync.aligned.m16n8k16.row.col.f32.f16.f16.f32 "
                 "{%0,%1,%2,%3}, {%4,%5,%6,%7}, {%8,%9}, {%0,%1,%2,%3};\n"
                 : "+f"(c[0]), "+f"(c[1]), "+f"(c[2]), "+f"(c[3])
                 : "r"(a[0]), "r"(a[1]), "r"(a[2]), "r"(a[3]), "r"(b0), "r"(b1));
}

__device__ __forceinline__ void cp16(uint32_t dst, const void* src) {
    asm volatile("cp.async.ca.shared.global [%0], [%1], 16;" :: "r"(dst), "l"(src));
}

// =====================================================================
// fp16 tensor-core GEMM, 64x128 block tile, K staged by 64.
// 128 threads (4 warps, 2x2), warp tile 32x64 -> 16 mma : 6 ldsm per k16.
// flags: 1 relu, 2 +pe, 4 write fp32 C, 8 write fp16 Cf
// =====================================================================
static const int TSTR = 72;
static const int GEMM_SMEM = 2 * 192 * TSTR * 2;  // 55296 B

__global__ __launch_bounds__(128) void gemm_half(
    const __half* __restrict__ A, const __half* __restrict__ B,
    const float* __restrict__ bias, float* __restrict__ C,
    __half* __restrict__ Cf,
    int M, int N, int K, int flags, const float* __restrict__ pe)
{
    extern __shared__ __half smb[];

    const int tid  = threadIdx.x;
    const int lane = tid & 31, warp = tid >> 5;
    const int wm = warp & 1, wn = warp >> 1;   // 2x2 warp grid, tile 32x64
    const int bm = blockIdx.y, bn = blockIdx.x;

    const __half* Ag = A + (size_t)(bm * 64) * K;
    const __half* Bg = B + (size_t)(bn * 128) * K;

    // load: 192 rows x 64 halfs = 1536 16B-chunks; 12 per thread
    auto issue = [&](int st, int k0) {
        __half* stbase = smb + (size_t)st * 192 * TSTR;
        #pragma unroll
        for (int i = 0; i < 12; i++) {
            int cix = tid + i * 128;
            int row = cix >> 3;
            int sub = (cix & 7) * 8;
            const __half* g = (row < 64) ? (Ag + (size_t)row * K)
                                         : (Bg + (size_t)(row - 64) * K);
            cp16((uint32_t)__cvta_generic_to_shared(stbase + row * TSTR + sub),
                 g + k0 + sub);
        }
        asm volatile("cp.async.commit_group;\n");
    };

    float c[2][8][4];
    #pragma unroll
    for (int i = 0; i < 2; i++)
        #pragma unroll
        for (int j = 0; j < 8; j++)
            #pragma unroll
            for (int q = 0; q < 4; q++) c[i][j][q] = 0.f;

    issue(0, 0);
    asm volatile("cp.async.wait_group 0;\n");
    __syncthreads();

    const int KT = K >> 6;
    int cur = 0;
    for (int kt = 0; kt < KT; kt++) {
        if (kt + 1 < KT) issue(cur ^ 1, (kt + 1) * 64);

        const __half* pA = smb + (size_t)cur * 192 * TSTR;
        const __half* pB = pA + 64 * TSTR;

        #pragma unroll
        for (int kh = 0; kh < 4; kh++) {
            const int r  = lane & 15;
            const int cc = kh * 16 + ((lane >> 4) << 3);
            uint32_t ah[2][4], bh[4][4];
            #pragma unroll
            for (int mt = 0; mt < 2; mt++) {
                int row = wm * 32 + mt * 16 + r;
                ldsm4(ah[mt][0], ah[mt][1], ah[mt][2], ah[mt][3], pA + row * TSTR + cc);
            }
            #pragma unroll
            for (int j = 0; j < 4; j++) {
                int row = wn * 64 + j * 16 + r;
                ldsm4(bh[j][0], bh[j][1], bh[j][2], bh[j][3], pB + row * TSTR + cc);
            }
            #pragma unroll
            for (int mt = 0; mt < 2; mt++) {
                #pragma unroll
                for (int nt = 0; nt < 8; nt++) {
                    const int j = nt >> 1, s = nt & 1;
                    mma16816(c[mt][nt], ah[mt], bh[j][s], bh[j][s + 2]);
                }
            }
        }

        if (kt + 1 < KT) {
            asm volatile("cp.async.wait_group 0;\n");
        }
        __syncthreads();
        cur ^= 1;
    }

    #pragma unroll
    for (int mt = 0; mt < 2; mt++) {
        const int mbase = bm * 64 + wm * 32 + mt * 16 + (lane >> 2);
        #pragma unroll
        for (int half_ = 0; half_ < 2; half_++) {
            const int m = mbase + half_ * 8;
            const size_t rowoff = (size_t)m * N;
            const float* perow = (flags & 2) ? (pe + (size_t)(m & (S_ - 1)) * DM) : nullptr;
            #pragma unroll
            for (int nt = 0; nt < 8; nt++) {
                const int n = bn * 128 + wn * 64 + nt * 8 + (lane & 3) * 2;
                float v0 = c[mt][nt][half_ * 2 + 0] + bias[n];
                float v1 = c[mt][nt][half_ * 2 + 1] + bias[n + 1];
                if (flags & 1) { v0 = fmaxf(v0, 0.f); v1 = fmaxf(v1, 0.f); }
                if (flags & 2) { v0 += perow[n]; v1 += perow[n + 1]; }
                if (flags & 4) {
                    float2 o; o.x = v0; o.y = v1;
                    *(float2*)(C + rowoff + n) = o;
                }
                if (flags & 8) {
                    __half2 hh; hh.x = __float2half(v0); hh.y = __float2half(v1);
                    *(__half2*)(Cf + rowoff + n) = hh;
                }
            }
        }
    }
}

// =====================================================================
// fp16 tensor-core attention: block per (b, h, q-chunk 32), 8 warps.
// Register-resident softmax; smem 96 KB -> 2 blocks/SM.
// =====================================================================
static const int KSTR = 72;
static const int SSTR = 264;
static const int OF_K  = 0;
static const int OF_V  = OF_K + 256 * KSTR * 2;      // 36864
static const int OF_Q  = OF_V + 256 * KSTR * 2;      // 73728
static const int OF_S2 = OF_Q + 32 * KSTR * 2;       // 78336
static const int OF_RM = OF_S2 + 32 * SSTR * 2;      // 95232
static const int OF_RS = OF_RM + 32 * 4 * 4;         // 95744
static const int ATTN_SMEM = OF_RS + 32 * 4 * 4;     // 96256

__global__ __launch_bounds__(256) void attn_mma(
    const __half* __restrict__ qkv, __half* __restrict__ out)
{
    extern __shared__ __align__(16) char smc[];
    __half* Ks = (__half*)(smc + OF_K);
    __half* Vs = (__half*)(smc + OF_V);
    __half* Qs = (__half*)(smc + OF_Q);
    __half* S2 = (__half*)(smc + OF_S2);
    float (*Pmax)[4] = (float (*)[4])(smc + OF_RM);
    float (*Psum)[4] = (float (*)[4])(smc + OF_RS);

    const int bh  = blockIdx.x;
    const int b   = bh >> 3, hd = bh & 7;
    const int q0  = blockIdx.y * 32;
    const int tid = threadIdx.x;
    const int lane = tid & 31, warp = tid >> 5;

    const size_t rowK = (size_t)b * S_ * (3 * DM) + hd * DH;
    {
        for (int i = tid; i < 256 * 8; i += 256) {
            int r = i >> 3, cc = (i & 7) * 8;
            size_t g = rowK + (size_t)r * (3 * DM);
            *(uint4*)&Ks[r * KSTR + cc] = *(const uint4*)(qkv + g + DM + cc);
            *(uint4*)&Vs[r * KSTR + cc] = *(const uint4*)(qkv + g + 2 * DM + cc);
        }
        for (int i = tid; i < 32 * 8; i += 256) {
            int r = i >> 3, cc = (i & 7) * 8;
            size_t g = rowK + (size_t)(q0 + r) * (3 * DM);
            *(uint4*)&Qs[r * KSTR + cc] = *(const uint4*)(qkv + g + cc);
        }
    }
    __syncthreads();

    const int wm = warp & 1, wn = warp >> 1;

    float c[8][4];
    #pragma unroll
    for (int t = 0; t < 8; t++)
        #pragma unroll
        for (int q = 0; q < 4; q++) c[t][q] = 0.f;
    {
        const int r  = lane & 15;
        const int c8 = (lane >> 4) << 3;
        #pragma unroll
        for (int k0 = 0; k0 < 64; k0 += 16) {
            uint32_t aq[4];
            ldsm4(aq[0], aq[1], aq[2], aq[3], Qs + (wm * 16 + r) * KSTR + k0 + c8);
            #pragma unroll
            for (int j = 0; j < 4; j++) {
                uint32_t bk[4];
                const int key = wn * 64 + j * 16 + r;
                ldsm4(bk[0], bk[1], bk[2], bk[3], Ks + key * KSTR + k0 + c8);
                #pragma unroll
                for (int s = 0; s < 2; s++)
                    mma16816(c[2 * j + s], aq, bk[s], bk[s + 2]);
            }
        }
        #pragma unroll
        for (int t = 0; t < 8; t++)
            #pragma unroll
            for (int q = 0; q < 4; q++) c[t][q] *= 0.125f;
    }

    const int r0 = wm * 16 + (lane >> 2);
    {
        float mx0 = -1e30f, mx1 = -1e30f;
        #pragma unroll
        for (int t = 0; t < 8; t++) {
            mx0 = fmaxf(mx0, fmaxf(c[t][0], c[t][1]));
            mx1 = fmaxf(mx1, fmaxf(c[t][2], c[t][3]));
        }
        #pragma unroll
        for (int off = 1; off <= 2; off <<= 1) {
            mx0 = fmaxf(mx0, __shfl_xor_sync(0xffffffffu, mx0, off));
            mx1 = fmaxf(mx1, __shfl_xor_sync(0xffffffffu, mx1, off));
        }
        if ((lane & 3) == 0) { Pmax[r0][wn] = mx0; Pmax[r0 + 8][wn] = mx1; }
        __syncthreads();
        float m0 = fmaxf(fmaxf(Pmax[r0][0], Pmax[r0][1]), fmaxf(Pmax[r0][2], Pmax[r0][3]));
        float m1 = fmaxf(fmaxf(Pmax[r0 + 8][0], Pmax[r0 + 8][1]),
                         fmaxf(Pmax[r0 + 8][2], Pmax[r0 + 8][3]));
        float s0 = 0.f, s1 = 0.f;
        #pragma unroll
        for (int t = 0; t < 8; t++) {
            c[t][0] = expf(c[t][0] - m0); c[t][1] = expf(c[t][1] - m0);
            s0 += c[t][0] + c[t][1];
            c[t][2] = expf(c[t][2] - m1); c[t][3] = expf(c[t][3] - m1);
            s1 += c[t][2] + c[t][3];
        }
        #pragma unroll
        for (int off = 1; off <= 2; off <<= 1) {
            s0 += __shfl_xor_sync(0xffffffffu, s0, off);
            s1 += __shfl_xor_sync(0xffffffffu, s1, off);
        }
        if ((lane & 3) == 0) { Psum[r0][wn] = s0; Psum[r0 + 8][wn] = s1; }
        __syncthreads();
        float inv0 = 1.f / (Psum[r0][0] + Psum[r0][1] + Psum[r0][2] + Psum[r0][3]);
        float inv1 = 1.f / (Psum[r0 + 8][0] + Psum[r0 + 8][1] +
                            Psum[r0 + 8][2] + Psum[r0 + 8][3]);
        #pragma unroll
        for (int t = 0; t < 8; t++) {
            const int col = wn * 64 + t * 8 + (lane & 3) * 2;
            __half2 h0; h0.x = __float2half(c[t][0] * inv0); h0.y = __float2half(c[t][1] * inv0);
            __half2 h1; h1.x = __float2half(c[t][2] * inv1); h1.y = __float2half(c[t][3] * inv1);
            *(__half2*)&S2[r0 * SSTR + col]       = h0;
            *(__half2*)&S2[(r0 + 8) * SSTR + col] = h1;
        }
    }
    __syncthreads();

    {
        float o[2][4];
        #pragma unroll
        for (int t = 0; t < 2; t++)
            #pragma unroll
            for (int q = 0; q < 4; q++) o[t][q] = 0.f;

        const int r  = lane & 15;
        const int c8 = (lane >> 4) << 3;
        #pragma unroll 4
        for (int k0 = 0; k0 < 256; k0 += 16) {
            uint32_t as_[4];
            ldsm4(as_[0], as_[1], as_[2], as_[3], S2 + (wm * 16 + r) * SSTR + k0 + c8);
            uint32_t bv[4];
            ldsm4t(bv[0], bv[1], bv[2], bv[3], Vs + (k0 + r) * KSTR + wn * 16 + c8);
            #pragma unroll
            for (int t = 0; t < 2; t++)
                mma16816(o[t], as_, bv[2 * t], bv[2 * t + 1]);
        }
        const int row0 = q0 + wm * 16 + (lane >> 2);
        #pragma unroll
        for (int t = 0; t < 2; t++) {
            const int d = hd * DH + wn * 16 + t * 8 + (lane & 3) * 2;
            size_t i0 = ((size_t)b * S_ + row0) * DM + d;
            size_t i1 = ((size_t)b * S_ + row0 + 8) * DM + d;
            __half2 a; a.x = __float2half(o[t][0]); a.y = __float2half(o[t][1]);
            __half2 bb; bb.x = __float2half(o[t][2]); bb.y = __float2half(o[t][3]);
            *(__half2*)&out[i0] = a;
            *(__half2*)&out[i1] = bb;
        }
    }
}

// =====================================================================
// Residual + LayerNorm; writes fp32 out + fp16
// =====================================================================
__global__ __launch_bounds__(128) void ln_kernel(
    const float* __restrict__ x, const float* __restrict__ r,
    const float* __restrict__ gam, const float* __restrict__ bet,
    float* __restrict__ out, __half* __restrict__ outh)
{
    const int row = blockIdx.x, tid = threadIdx.x;
    const float* xr = x + (size_t)row * DM;
    const float* rr = r + (size_t)row * DM;
    float v[4];
    float s = 0.f, s2 = 0.f;
    #pragma unroll
    for (int u = 0; u < 4; u++) {
        int i = tid + u * 128;
        v[u] = xr[i] + rr[i];
        s += v[u]; s2 += v[u] * v[u];
    }
    __shared__ float rs[4], rs2[4];
    #pragma unroll
    for (int off = 16; off; off >>= 1) {
        s  += __shfl_xor_sync(0xffffffffu, s,  off);
        s2 += __shfl_xor_sync(0xffffffffu, s2, off);
    }
    if ((tid & 31) == 0) { rs[tid >> 5] = s; rs2[tid >> 5] = s2; }
    __syncthreads();
    s  = rs[0] + rs[1] + rs[2] + rs[3];
    s2 = rs2[0] + rs2[1] + rs2[2] + rs2[3];
    float mean = s * (1.f / DM);
    float var  = s2 * (1.f / DM) - mean * mean;
    float k = rsqrtf(var + 1e-5f);
    float* orow = out + (size_t)row * DM;
    __half* hrow = outh + (size_t)row * DM;
    #pragma unroll
    for (int u = 0; u < 4; u++) {
        int i = tid + u * 128;
        float o = (v[u] - mean) * k * gam[i] + bet[i];
        orow[i] = o;
        hrow[i] = __float2half(o);
    }
}

// =====================================================================
// host launcher
// =====================================================================
static void run_gemm(const __half* A, const __half* B, const float* bias,
                     float* C, __half* Cf,
                     int M, int N, int K, int flags, const float* pe) {
    dim3 grid(N / 128, M / 64);
    gemm_half<<<grid, 128, GEMM_SMEM>>>(A, B, bias, C, Cf, M, N, K, flags, pe);
}

extern "C" void kernel_launch(void* const* d_in, const int* in_sizes, int n_in,
                              void* d_out, int out_size)
{
    const float* lm    = (const float*)d_in[0];
    const int*   ei    = (const int*)  d_in[1];
    const int    E     = in_sizes[1] / 2;
    const float* g1w   = (const float*)d_in[2];
    const float* g1as  = (const float*)d_in[3];
    const float* g1ad  = (const float*)d_in[4];
    const float* g1b   = (const float*)d_in[5];
    const float* g2w   = (const float*)d_in[6];
    const float* g2as  = (const float*)d_in[7];
    const float* g2ad  = (const float*)d_in[8];
    const float* g2b   = (const float*)d_in[9];
    const float* fcw   = (const float*)d_in[10];
    const float* fcb   = (const float*)d_in[11];
    const float* pe    = (const float*)d_in[12];
    const float* ipw   = (const float*)d_in[13];
    const float* ipb   = (const float*)d_in[14];
    const float* opw   = (const float*)d_in[15];
    const float* opb   = (const float*)d_in[16];
    const float* ln1g  = (const float*)d_in[17];
    const float* ln1b  = (const float*)d_in[18];
    const float* fw1   = (const float*)d_in[19];
    const float* fb1   = (const float*)d_in[20];
    const float* fw2   = (const float*)d_in[21];
    const float* fb2   = (const float*)d_in[22];
    const float* ln2g  = (const float*)d_in[23];
    const float* ln2b  = (const float*)d_in[24];

    __half *wf, *ghf, *gxf, *atf, *fff, *qkf;
    float *gx, *gproj;
    cudaGetSymbolAddress((void**)&wf,  w_f);
    cudaGetSymbolAddress((void**)&ghf, gh_f);
    cudaGetSymbolAddress((void**)&gxf, gx_f);
    cudaGetSymbolAddress((void**)&atf, at_f);
    cudaGetSymbolAddress((void**)&fff, ff_f);
    cudaGetSymbolAddress((void**)&qkf, qk_f);
    cudaGetSymbolAddress((void**)&gx,  g_x);
    cudaGetSymbolAddress((void**)&gproj, g_proj);

    cudaFuncSetAttribute(attn_mma,  cudaFuncAttributeMaxDynamicSharedMemorySize, ATTN_SMEM);
    cudaFuncSetAttribute(gemm_half, cudaFuncAttributeMaxDynamicSharedMemorySize, GEMM_SMEM);

    // 0. weight convert (fp32 -> fp16), one merged kernel
    cvt_all<<<2048, 256>>>(fcw, ipw, opw, fw1, fw2, wf);

    // 1. GAT frontend -> fp16
    gat_kernel<<<G_, 128>>>(lm, ei, E, g1w, g1as, g1ad, g1b,
                            g2w, g2as, g2ad, g2b, ghf);

    // 2. FC + positional encoding -> fp32 gx + fp16
    run_gemm(ghf, wf + OFF_FC, fcb, gx, gxf, G_, DM, L_ * 64, 2 | 4 | 8, pe);

    // 3. transformer encoder layers
    for (int l = 0; l < NL; l++) {
        run_gemm(gxf, wf + OFF_IP + (size_t)l * 3 * DM * DM, ipb + (size_t)l * 3 * DM,
                 nullptr, qkf, G_, 3 * DM, DM, /*fp16*/ 8, nullptr);
        attn_mma<<<dim3(B_ * NH, S_ / 32), 256, ATTN_SMEM>>>(qkf, atf);
        run_gemm(atf, wf + OFF_OP + (size_t)l * DM * DM, opb + (size_t)l * DM,
                 gproj, nullptr, G_, DM, DM, 4, nullptr);
        ln_kernel<<<G_, 128>>>(gx, gproj, ln1g + (size_t)l * DM, ln1b + (size_t)l * DM,
                               gx, gxf);

        run_gemm(gxf, wf + OFF_F1 + (size_t)l * DFF * DM, fb1 + (size_t)l * DFF,
                 nullptr, fff, G_, DFF, DM, 1 | 8, nullptr);
        run_gemm(fff, wf + OFF_F2 + (size_t)l * DM * DFF, fb2 + (size_t)l * DM,
                 gproj, nullptr, G_, DM, DFF, 4, nullptr);
        float* outp = (l == NL - 1) ? (float*)d_out : gx;
        ln_kernel<<<G_, 128>>>(gx, gproj, ln2g + (size_t)l * DM, ln2b + (size_t)l * DM,
                               outp, gxf);
    }
    (void)n_in; (void)out_size;
}